// round 10
// baseline (speedup 1.0000x reference)
#include <cuda_runtime.h>
#include <cuda_bf16.h>
#include <math.h>
#include <stdint.h>

// ---------------------------------------------------------------------------
// Swin block: B=32, H=W=56, D=192, HEADS=6, DH=32, WS=7, SHIFT=3, no pad,
// no attention mask (per reference).
// R10: 64x48 warp tiles (2m x 4n over N=192) in both attn_fused phase 1 and
// bgemm -> 149 B/MMA fragment traffic (was 213); attn CTA now covers a
// head-PAIR (halves B-frag + A-staging redundancy).
// ---------------------------------------------------------------------------

#define NHW   3136
#define NTOK  100352
#define DIM   192

__device__ __nv_bfloat16 g_a1 [(size_t)NTOK * DIM];   // LN1 out (window order)
__device__ __nv_bfloat16 g_ao [(size_t)NTOK * DIM];   // attn out (window order)
__device__ float         g_x2 [(size_t)NTOK * DIM];   // x2 fp32 (plain order)
__device__ __nv_bfloat16 g_x2b[(size_t)NTOK * DIM];   // x2 bf16 (plain order)
__device__ __nv_bfloat16 g_hid[(size_t)NTOK * 384];   // fc1 GELU out
__device__ __nv_bfloat16 g_wqkv[576 * 192];
__device__ __nv_bfloat16 g_wout[192 * 192];
__device__ __nv_bfloat16 g_w1  [384 * 192];           // gamma2-folded
__device__ __nv_bfloat16 g_w2  [192 * 384];
__device__ float2        g_st1 [384];
__device__ float2        g_pbuf[4 * NTOK];
__device__ float2        g_mstat[NTOK];
__device__ __align__(16) __nv_bfloat16 g_zbuf[16];

__device__ __forceinline__ int src_index(int r) {
    int w = r / 49, p = r % 49;
    int b  = w >> 6;
    int wy = (w & 63) >> 3;
    int wx = w & 7;
    int py = p / 7, px = p % 7;
    int h2 = wy * 7 + py;
    int w2 = wx * 7 + px;
    int hs = h2 + 3; if (hs >= 56) hs -= 56;
    int ws = w2 + 3; if (ws >= 56) ws -= 56;
    return b * NHW + hs * 56 + ws;
}

// ---------------------------------------------------------------------------
__device__ __forceinline__ uint32_t smem_u32(const void* p) {
    uint32_t a;
    asm("{ .reg .u64 t; cvta.to.shared.u64 t, %1; cvt.u32.u64 %0, t; }" : "=r"(a) : "l"(p));
    return a;
}
__device__ __forceinline__ void cp_async16(uint32_t dst, const void* src) {
    asm volatile("cp.async.ca.shared.global [%0], [%1], 16;" :: "r"(dst), "l"(src));
}
#define CP_COMMIT()  asm volatile("cp.async.commit_group;" ::: "memory")
#define CP_WAIT(n)   asm volatile("cp.async.wait_group %0;" :: "n"(n) : "memory")

__device__ __forceinline__ void ldsm4(uint32_t* r, uint32_t addr) {
    asm volatile("ldmatrix.sync.aligned.m8n8.x4.shared.b16 {%0,%1,%2,%3}, [%4];"
        : "=r"(r[0]), "=r"(r[1]), "=r"(r[2]), "=r"(r[3]) : "r"(addr));
}
__device__ __forceinline__ void ldsm2(uint32_t* r, uint32_t addr) {
    asm volatile("ldmatrix.sync.aligned.m8n8.x2.shared.b16 {%0,%1}, [%2];"
        : "=r"(r[0]), "=r"(r[1]) : "r"(addr));
}
__device__ __forceinline__ void ldsm4t(uint32_t* r, uint32_t addr) {
    asm volatile("ldmatrix.sync.aligned.m8n8.x4.trans.shared.b16 {%0,%1,%2,%3}, [%4];"
        : "=r"(r[0]), "=r"(r[1]), "=r"(r[2]), "=r"(r[3]) : "r"(addr));
}
__device__ __forceinline__ void mma_bf16(float* c, const uint32_t* a, const uint32_t* b) {
    asm volatile(
        "mma.sync.aligned.m16n8k16.row.col.f32.bf16.bf16.f32 "
        "{%0,%1,%2,%3}, {%4,%5,%6,%7}, {%8,%9}, {%0,%1,%2,%3};"
        : "+f"(c[0]), "+f"(c[1]), "+f"(c[2]), "+f"(c[3])
        : "r"(a[0]), "r"(a[1]), "r"(a[2]), "r"(a[3]), "r"(b[0]), "r"(b[1]));
}
__device__ __forceinline__ float gelu_exact(float v) {
    return 0.5f * v * (1.0f + erff(v * 0.7071067811865476f));
}
__device__ __forceinline__ uint32_t packbf(float a, float b) {
    __nv_bfloat162 t = __floats2bfloat162_rn(a, b);
    return *(uint32_t*)&t;
}

// ---------------------------------------------------------------------------
__global__ void wcvt(const float* __restrict__ wqkv, const float* __restrict__ wout,
                     const float* __restrict__ w2) {
    int i = blockIdx.x * 256 + threadIdx.x;
    if (i < 110592)       g_wqkv[i]          = __float2bfloat16(wqkv[i]);
    else if (i < 147456)  g_wout[i - 110592] = __float2bfloat16(wout[i - 110592]);
    else                  g_w2[i - 147456]   = __float2bfloat16(w2[i - 147456]);
    if (i < 16) g_zbuf[i] = __float2bfloat16(0.0f);
}

__global__ void prep1(const float* __restrict__ w1, const float* __restrict__ g2,
                      const float* __restrict__ b2) {
    int n = blockIdx.x * 8 + (threadIdx.x >> 5);
    int lane = threadIdx.x & 31;
    float S = 0.0f, T = 0.0f;
#pragma unroll
    for (int j = 0; j < 6; j++) {
        int k = lane + 32 * j;
        float w = w1[n * 192 + k];
        __nv_bfloat16 wb = __float2bfloat16(w * g2[k]);
        g_w1[n * 192 + k] = wb;
        S += __bfloat162float(wb);
        T += b2[k] * w;
    }
#pragma unroll
    for (int o = 16; o; o >>= 1) {
        S += __shfl_xor_sync(0xffffffffu, S, o);
        T += __shfl_xor_sync(0xffffffffu, T, o);
    }
    if (lane == 0) g_st1[n] = make_float2(S, T);
}

__global__ void finstats() {
    int i = blockIdx.x * 256 + threadIdx.x;
    float s = 0.0f, q = 0.0f;
#pragma unroll
    for (int k = 0; k < 4; k++) {
        float2 p = g_pbuf[k * NTOK + i];
        s += p.x; q += p.y;
    }
    float mean = s * (1.0f / 192.0f);
    float var  = q * (1.0f / 192.0f) - mean * mean;
    g_mstat[i] = make_float2(mean, rsqrtf(var + 1e-5f));
}

__global__ void ln1_kernel(const float* __restrict__ x,
                           const float* __restrict__ gam,
                           const float* __restrict__ bet,
                           __nv_bfloat16* __restrict__ out) {
    int t    = blockIdx.x * 8 + (threadIdx.x >> 5);
    int lane = threadIdx.x & 31;
    const float* xr = x + (size_t)src_index(t) * DIM;

    float v[6];
#pragma unroll
    for (int i = 0; i < 6; i++) v[i] = xr[lane + 32 * i];

    float s = v[0] + v[1] + v[2] + v[3] + v[4] + v[5];
#pragma unroll
    for (int o = 16; o; o >>= 1) s += __shfl_xor_sync(0xffffffffu, s, o);
    float mean = s * (1.0f / 192.0f);

    float q = 0.0f;
#pragma unroll
    for (int i = 0; i < 6; i++) { float d = v[i] - mean; q += d * d; }
#pragma unroll
    for (int o = 16; o; o >>= 1) q += __shfl_xor_sync(0xffffffffu, q, o);
    float rstd = rsqrtf(q * (1.0f / 192.0f) + 1e-5f);

    __nv_bfloat16* orow = out + (size_t)t * DIM;
#pragma unroll
    for (int i = 0; i < 6; i++) {
        int c = lane + 32 * i;
        orow[c] = __float2bfloat16((v[i] - mean) * rstd * gam[c] + bet[c]);
    }
}

// ---------------------------------------------------------------------------
// Fused QKV-GEMM + window attention, head-pair version.
// CTA = (window pair p, head-pair hp). 256 thr, 8 warps.
// Phase 1: qkv[128 x 192] for heads {2hp, 2hp+1}; warp grid 2m(64) x 4n(48).
//   qkv layout in smem: col n -> s = n/64 (q/k/v), hh = (n/32)&1, c = n%32.
// Phase 2: loop hh over the two heads; per-head round-9 attention code.
// ---------------------------------------------------------------------------
#define FBK   16
#define FSTG  3
#define FAROW 24
#define FASZ  (128 * FAROW * 2)          // 6144
#define FWSZ  (192 * FAROW * 2)          // 9216
#define QS2   200                        // qkv smem row stride (bf16)
#define OFF_WS (FSTG * FASZ)             // 18432
#define OFF_QS (OFF_WS + FSTG * FWSZ)    // 46080
#define FUSED_SMEM (OFF_QS + 128 * QS2 * 2)  // 97280

__global__ __launch_bounds__(256, 2)
void attn_fused(const __nv_bfloat16* __restrict__ a1,
                const float* __restrict__ bqkv,
                __nv_bfloat16* __restrict__ ao) {
    extern __shared__ char smem[];
    const int tid  = threadIdx.x;
    const int warp = tid >> 5;
    const int lane = tid & 31;
    const int g    = lane >> 2;
    const int tin  = lane & 3;
    const int l15  = lane & 15;
    const int lhi  = lane >> 4;
    const int p    = blockIdx.x;          // window pair
    const int hp   = blockIdx.y;          // head pair
    const int R0   = p * 98;

    const uint32_t sb = smem_u32(smem);

    // ---- load assignments ----
    const int arow = tid >> 1, achk = tid & 1;
    const bool areal = arow < 98;
    const __nv_bfloat16* Ag = areal ? (a1 + (size_t)(R0 + arow) * 192 + achk * 8)
                                    : (const __nv_bfloat16*)g_zbuf;
    const uint32_t asb = sb + (arow * FAROW + achk * 8) * 2;

    // B: 192 rows x 2 chunks = 384; chunk idx0 = tid, idx1 = tid + 256 (tid<128)
    const int brow0 = tid >> 1,          bchk0 = tid & 1;
    const int brow1 = 128 + (tid >> 1),  bchk1 = tid & 1;
    const bool bld1 = tid < 128;
    const int s0 = brow0 >> 6, h20 = (brow0 >> 5) & 1, r0b = brow0 & 31;
    const int s1 = brow1 >> 6, h21 = (brow1 >> 5) & 1, r1b = brow1 & 31;
    const __nv_bfloat16* Wg0 = g_wqkv + (size_t)(s0 * 192 + (hp * 2 + h20) * 32 + r0b) * 192 + bchk0 * 8;
    const __nv_bfloat16* Wg1 = g_wqkv + (size_t)(s1 * 192 + (hp * 2 + h21) * 32 + r1b) * 192 + bchk1 * 8;
    const uint32_t wsb0 = sb + OFF_WS + (brow0 * FAROW + bchk0 * 8) * 2;
    const uint32_t wsb1 = sb + OFF_WS + (brow1 * FAROW + bchk1 * 8) * 2;

#pragma unroll
    for (int s = 0; s < FSTG - 1; s++) {
        cp_async16(asb + s * FASZ, areal ? (Ag + s * FBK) : Ag);
        cp_async16(wsb0 + s * FWSZ, Wg0 + s * FBK);
        if (bld1) cp_async16(wsb1 + s * FWSZ, Wg1 + s * FBK);
        CP_COMMIT();
    }

    // ---- Phase 1: warp grid 2m(64) x 4n(48) ----
    const int wm = (warp & 1) * 64;
    const int wn = (warp >> 1) * 48;

    float acc[4][6][4];
#pragma unroll
    for (int i = 0; i < 4; i++)
#pragma unroll
        for (int j = 0; j < 6; j++)
#pragma unroll
            for (int l = 0; l < 4; l++) acc[i][j][l] = 0.0f;

    const uint32_t albase = sb + (uint32_t)(wm + l15) * (FAROW * 2) + lhi * 16;
    const uint32_t wbbase = sb + OFF_WS
                          + (uint32_t)(wn + ((lane >> 4) & 1) * 8 + (lane & 7)) * (FAROW * 2)
                          + ((lane >> 3) & 1) * 16;

    for (int t = 0; t < 12; t++) {
        CP_WAIT(FSTG - 2);
        __syncthreads();
        const int tn = t + FSTG - 1;
        if (tn < 12) {
            const int s = tn % FSTG;
            cp_async16(asb + s * FASZ, areal ? (Ag + tn * FBK) : Ag);
            cp_async16(wsb0 + s * FWSZ, Wg0 + tn * FBK);
            if (bld1) cp_async16(wsb1 + s * FWSZ, Wg1 + tn * FBK);
        }
        CP_COMMIT();

        const int st = t % FSTG;
        uint32_t af[4][4];
#pragma unroll
        for (int mt = 0; mt < 4; mt++)
            ldsm4(af[mt], albase + st * FASZ + mt * 16 * (FAROW * 2));

#pragma unroll
        for (int pr = 0; pr < 3; pr++) {
            uint32_t bq[4];
            ldsm4(bq, wbbase + st * FWSZ + pr * 16 * (FAROW * 2));
#pragma unroll
            for (int mt = 0; mt < 4; mt++) {
                mma_bf16(acc[mt][2 * pr + 0], af[mt], &bq[0]);
                mma_bf16(acc[mt][2 * pr + 1], af[mt], &bq[2]);
            }
        }
    }

    // epilogue: + bias, store to qkv smem tile [128][200]
    __nv_bfloat16* qs = (__nv_bfloat16*)(smem + OFF_QS);
#pragma unroll
    for (int mt = 0; mt < 4; mt++) {
        const int r0 = wm + mt * 16 + g;
#pragma unroll
        for (int nt = 0; nt < 6; nt++) {
            const int n   = wn + nt * 8 + 2 * tin;
            const int seg = n >> 6;
            const int hh  = (n >> 5) & 1;
            const int bcol = seg * 192 + (hp * 2 + hh) * 32 + (n & 31);
            const float2 bv = *(const float2*)&bqkv[bcol];
            *(uint32_t*)&qs[r0 * QS2 + n]       = packbf(acc[mt][nt][0] + bv.x, acc[mt][nt][1] + bv.y);
            *(uint32_t*)&qs[(r0 + 8) * QS2 + n] = packbf(acc[mt][nt][2] + bv.x, acc[mt][nt][3] + bv.y);
        }
    }
    __syncthreads();

    // ---- Phase 2: attention, loop over the two heads ----
    const int wi = warp >> 2;             // window in pair
    const int mq = (warp & 3) * 16;       // row tile within window
    const int rb = wi * 49 + mq;
    const uint32_t qsu = sb + OFF_QS;
    const float scale = 0.17677669529663687f;   // 1/sqrt(32)

#pragma unroll 1
    for (int hh = 0; hh < 2; hh++) {
        const int qo = 64 * hh;           // byte offsets within a row
        const int ko = 128 + 64 * hh;
        const int vo = 256 + 64 * hh;

        float a7[7][4];
#pragma unroll
        for (int nt = 0; nt < 7; nt++)
#pragma unroll
            for (int c = 0; c < 4; c++) a7[nt][c] = 0.0f;

        const uint32_t kbase = qsu
            + (uint32_t)(wi * 49 + ((lane >> 4) & 1) * 8 + (lane & 7)) * (QS2 * 2)
            + ko + ((lane >> 3) & 1) * 16;

#pragma unroll
        for (int kc = 0; kc < 2; kc++) {
            uint32_t qa[4];
            ldsm4(qa, qsu + (uint32_t)(rb + l15) * (QS2 * 2) + qo + kc * 32 + lhi * 16);
            uint32_t kq[3][4];
#pragma unroll
            for (int pr = 0; pr < 3; pr++)
                ldsm4(kq[pr], kbase + kc * 32 + pr * 16 * (QS2 * 2));
            uint32_t k6[2];
            ldsm2(k6, qsu + (uint32_t)(wi * 49 + 48 + (lane & 7)) * (QS2 * 2)
                       + ko + kc * 32 + ((lane >> 3) & 1) * 16);
#pragma unroll
            for (int pr = 0; pr < 3; pr++) {
                mma_bf16(a7[2 * pr + 0], qa, &kq[pr][0]);
                mma_bf16(a7[2 * pr + 1], qa, &kq[pr][2]);
            }
            mma_bf16(a7[6], qa, k6);
        }

        float mx0 = -1e30f, mx1 = -1e30f;
#pragma unroll
        for (int nt = 0; nt < 7; nt++) {
            int c0 = nt * 8 + 2 * tin;
            float* a = a7[nt];
            a[0] = (c0     < 49) ? a[0] * scale : -1e30f;
            a[1] = (c0 + 1 < 49) ? a[1] * scale : -1e30f;
            a[2] = (c0     < 49) ? a[2] * scale : -1e30f;
            a[3] = (c0 + 1 < 49) ? a[3] * scale : -1e30f;
            mx0 = fmaxf(mx0, fmaxf(a[0], a[1]));
            mx1 = fmaxf(mx1, fmaxf(a[2], a[3]));
        }
        mx0 = fmaxf(mx0, __shfl_xor_sync(0xffffffffu, mx0, 1));
        mx0 = fmaxf(mx0, __shfl_xor_sync(0xffffffffu, mx0, 2));
        mx1 = fmaxf(mx1, __shfl_xor_sync(0xffffffffu, mx1, 1));
        mx1 = fmaxf(mx1, __shfl_xor_sync(0xffffffffu, mx1, 2));

        float ss0 = 0.0f, ss1 = 0.0f;
        uint32_t pk[8][2];
#pragma unroll
        for (int nt = 0; nt < 7; nt++) {
            float* a = a7[nt];
            a[0] = __expf(a[0] - mx0);
            a[1] = __expf(a[1] - mx0);
            a[2] = __expf(a[2] - mx1);
            a[3] = __expf(a[3] - mx1);
            ss0 += a[0] + a[1];
            ss1 += a[2] + a[3];
            pk[nt][0] = packbf(a[0], a[1]);
            pk[nt][1] = packbf(a[2], a[3]);
        }
        pk[7][0] = 0u; pk[7][1] = 0u;
        ss0 += __shfl_xor_sync(0xffffffffu, ss0, 1);
        ss0 += __shfl_xor_sync(0xffffffffu, ss0, 2);
        ss1 += __shfl_xor_sync(0xffffffffu, ss1, 1);
        ss1 += __shfl_xor_sync(0xffffffffu, ss1, 2);

        float pv[4][4];
#pragma unroll
        for (int nt = 0; nt < 4; nt++)
#pragma unroll
            for (int c = 0; c < 4; c++) pv[nt][c] = 0.0f;

        const uint32_t vbase = qsu + (uint32_t)(wi * 49 + l15) * (QS2 * 2) + vo + lhi * 16;

#pragma unroll
        for (int kc = 0; kc < 4; kc++) {
            uint32_t pa[4] = { pk[2 * kc][0], pk[2 * kc][1], pk[2 * kc + 1][0], pk[2 * kc + 1][1] };
            uint32_t vq[2][4];
#pragma unroll
            for (int pr = 0; pr < 2; pr++)
                ldsm4t(vq[pr], vbase + kc * 16 * (QS2 * 2) + pr * 32);
#pragma unroll
            for (int pr = 0; pr < 2; pr++) {
                mma_bf16(pv[2 * pr + 0], pa, &vq[pr][0]);
                mma_bf16(pv[2 * pr + 1], pa, &vq[pr][2]);
            }
        }

        const float inv0 = 1.0f / ss0;
        const float inv1 = 1.0f / ss1;
        const int head = hp * 2 + hh;
        const int rr0 = mq + g;
        if (rr0 < 49) {
            __nv_bfloat16* ob = ao + (size_t)(R0 + wi * 49 + rr0) * 192 + head * 32;
#pragma unroll
            for (int nt = 0; nt < 4; nt++)
                *(uint32_t*)&ob[nt * 8 + 2 * tin] = packbf(pv[nt][0] * inv0, pv[nt][1] * inv0);
        }
        if (rr0 + 8 < 49) {
            __nv_bfloat16* ob = ao + (size_t)(R0 + wi * 49 + rr0 + 8) * 192 + head * 32;
#pragma unroll
            for (int nt = 0; nt < 4; nt++)
                *(uint32_t*)&ob[nt * 8 + 2 * tin] = packbf(pv[nt][2] * inv1, pv[nt][3] * inv1);
        }
    }
}

// ---------------------------------------------------------------------------
// bf16 GEMM, tile 128x192, warp grid 2m(64) x 4n(48). Dynamic smem. EPIs:
//   2: v += res[row]; fp32 store (fc2 -> out)
//   3: v += res[src(row)]; fp32 scatter store + bf16 copy + LN2 stat partials
//   4: LN2-affine then GELU, bf16 store
// ---------------------------------------------------------------------------
#define BM 128
#define BN 192
#define BK 16
#define STG 4
#define AROW 24
#define GASZ (BM * AROW * 2)             // 6144
#define GWSZ (BN * AROW * 2)             // 9216
#define GOFF_WS (STG * GASZ)             // 24576
#define GEMM_SMEM (GOFF_WS + STG * GWSZ) // 61440

template <int EPI>
__global__ __launch_bounds__(256, 2)
void bgemm(const __nv_bfloat16* __restrict__ A, const __nv_bfloat16* __restrict__ W,
           const float* __restrict__ bias, void* __restrict__ outp,
           const float* __restrict__ res, int N, int K) {
    extern __shared__ char gsm[];
    const uint32_t sb = smem_u32(gsm);

    const int tid  = threadIdx.x;
    const int wid  = tid >> 5;
    const int lane = tid & 31;
    const int g    = lane >> 2;
    const int tin  = lane & 3;
    const int wm   = (wid & 1) * 64;
    const int wn   = (wid >> 1) * 48;
    const int row0 = blockIdx.y * BM;
    const int col0 = blockIdx.x * BN;

    const int arow = tid >> 1, achk = tid & 1;
    const int brow0 = tid >> 1,         bchk0 = tid & 1;
    const int brow1 = 128 + (tid >> 1), bchk1 = tid & 1;
    const bool bld1 = tid < 128;

    const __nv_bfloat16* Ag  = A + (size_t)(row0 + arow) * K + achk * 8;
    const __nv_bfloat16* Wg0 = W + (size_t)(col0 + brow0) * K + bchk0 * 8;
    const __nv_bfloat16* Wg1 = W + (size_t)(col0 + brow1) * K + bchk1 * 8;
    const uint32_t asb  = sb + (arow * AROW + achk * 8) * 2;
    const uint32_t wsb0 = sb + GOFF_WS + (brow0 * AROW + bchk0 * 8) * 2;
    const uint32_t wsb1 = sb + GOFF_WS + (brow1 * AROW + bchk1 * 8) * 2;

    const int T = K / BK;
#pragma unroll
    for (int s = 0; s < STG - 1; s++) {
        cp_async16(asb + s * GASZ, Ag + s * BK);
        cp_async16(wsb0 + s * GWSZ, Wg0 + s * BK);
        if (bld1) cp_async16(wsb1 + s * GWSZ, Wg1 + s * BK);
        CP_COMMIT();
    }

    float acc[4][6][4];
#pragma unroll
    for (int i = 0; i < 4; i++)
#pragma unroll
        for (int j = 0; j < 6; j++)
#pragma unroll
            for (int l = 0; l < 4; l++) acc[i][j][l] = 0.0f;

    const uint32_t albase = sb + (uint32_t)(wm + (lane & 15)) * (AROW * 2) + (lane >> 4) * 16;
    const uint32_t wbbase = sb + GOFF_WS
                          + (uint32_t)(wn + ((lane >> 4) & 1) * 8 + (lane & 7)) * (AROW * 2)
                          + ((lane >> 3) & 1) * 16;

    for (int t = 0; t < T; t++) {
        CP_WAIT(STG - 2);
        __syncthreads();
        const int tn = t + STG - 1;
        if (tn < T) {
            const int s = tn % STG;
            cp_async16(asb + s * GASZ, Ag + tn * BK);
            cp_async16(wsb0 + s * GWSZ, Wg0 + tn * BK);
            if (bld1) cp_async16(wsb1 + s * GWSZ, Wg1 + tn * BK);
        }
        CP_COMMIT();

        const int st = t % STG;
        uint32_t af[4][4];
#pragma unroll
        for (int mt = 0; mt < 4; mt++)
            ldsm4(af[mt], albase + st * GASZ + mt * 16 * (AROW * 2));

#pragma unroll
        for (int pr = 0; pr < 3; pr++) {
            uint32_t bq[4];
            ldsm4(bq, wbbase + st * GWSZ + pr * 16 * (AROW * 2));
#pragma unroll
            for (int mt = 0; mt < 4; mt++) {
                mma_bf16(acc[mt][2 * pr + 0], af[mt], &bq[0]);
                mma_bf16(acc[mt][2 * pr + 1], af[mt], &bq[2]);
            }
        }
    }

    __nv_bfloat16* outb = (__nv_bfloat16*)outp;
    float*         outf = (float*)outp;

#pragma unroll
    for (int mt = 0; mt < 4; mt++) {
        const int r0 = row0 + wm + mt * 16 + g;
        const int r1 = r0 + 8;

        if (EPI == 3) {
            const int d0 = src_index(r0);
            const int d1 = src_index(r1);
            float s0 = 0.0f, q0 = 0.0f, s1 = 0.0f, q1 = 0.0f;
#pragma unroll
            for (int nt = 0; nt < 6; nt++) {
                const int col = col0 + wn + nt * 8 + 2 * tin;
                const float2 bv = *(const float2*)&bias[col];
                float2 v0, v1;
                v0.x = acc[mt][nt][0] + bv.x;
                v0.y = acc[mt][nt][1] + bv.y;
                v1.x = acc[mt][nt][2] + bv.x;
                v1.y = acc[mt][nt][3] + bv.y;
                float2 e0 = *(const float2*)&res[(size_t)d0 * 192 + col];
                float2 e1 = *(const float2*)&res[(size_t)d1 * 192 + col];
                v0.x += e0.x; v0.y += e0.y;
                v1.x += e1.x; v1.y += e1.y;
                *(float2*)&outf[(size_t)d0 * 192 + col] = v0;
                *(float2*)&outf[(size_t)d1 * 192 + col] = v1;
                *(uint32_t*)&g_x2b[(size_t)d0 * 192 + col] = packbf(v0.x, v0.y);
                *(uint32_t*)&g_x2b[(size_t)d1 * 192 + col] = packbf(v1.x, v1.y);
                s0 += v0.x + v0.y; q0 += v0.x * v0.x + v0.y * v0.y;
                s1 += v1.x + v1.y; q1 += v1.x * v1.x + v1.y * v1.y;
            }
            s0 += __shfl_xor_sync(0xffffffffu, s0, 1);
            s0 += __shfl_xor_sync(0xffffffffu, s0, 2);
            q0 += __shfl_xor_sync(0xffffffffu, q0, 1);
            q0 += __shfl_xor_sync(0xffffffffu, q0, 2);
            s1 += __shfl_xor_sync(0xffffffffu, s1, 1);
            s1 += __shfl_xor_sync(0xffffffffu, s1, 2);
            q1 += __shfl_xor_sync(0xffffffffu, q1, 1);
            q1 += __shfl_xor_sync(0xffffffffu, q1, 2);
            if (tin == 0) {
                const int slot = wid >> 1;   // n-warp id, 4 slots
                g_pbuf[slot * NTOK + d0] = make_float2(s0, q0);
                g_pbuf[slot * NTOK + d1] = make_float2(s1, q1);
            }
        } else if (EPI == 4) {
            const float2 mr0 = g_mstat[r0];
            const float2 mr1 = g_mstat[r1];
            const float a0 = mr0.y, b0 = mr0.x * mr0.y;
            const float a1 = mr1.y, b1c = mr1.x * mr1.y;
#pragma unroll
            for (int nt = 0; nt < 6; nt++) {
                const int col = col0 + wn + nt * 8 + 2 * tin;
                const float2 bv = *(const float2*)&bias[col];
                const float2 stA = g_st1[col];
                const float2 stB = g_st1[col + 1];
                float v00 = gelu_exact(a0 * acc[mt][nt][0] - b0 * stA.x + stA.y + bv.x);
                float v01 = gelu_exact(a0 * acc[mt][nt][1] - b0 * stB.x + stB.y + bv.y);
                float v10 = gelu_exact(a1 * acc[mt][nt][2] - b1c * stA.x + stA.y + bv.x);
                float v11 = gelu_exact(a1 * acc[mt][nt][3] - b1c * stB.x + stB.y + bv.y);
                *(uint32_t*)&outb[(size_t)r0 * N + col] = packbf(v00, v01);
                *(uint32_t*)&outb[(size_t)r1 * N + col] = packbf(v10, v11);
            }
        } else {  // EPI 2
#pragma unroll
            for (int nt = 0; nt < 6; nt++) {
                const int col = col0 + wn + nt * 8 + 2 * tin;
                const float2 bv = *(const float2*)&bias[col];
                float2 v0, v1;
                v0.x = acc[mt][nt][0] + bv.x;
                v0.y = acc[mt][nt][1] + bv.y;
                v1.x = acc[mt][nt][2] + bv.x;
                v1.y = acc[mt][nt][3] + bv.y;
                float2 e0 = *(const float2*)&res[(size_t)r0 * N + col];
                float2 e1 = *(const float2*)&res[(size_t)r1 * N + col];
                v0.x += e0.x; v0.y += e0.y;
                v1.x += e1.x; v1.y += e1.y;
                *(float2*)&outf[(size_t)r0 * N + col] = v0;
                *(float2*)&outf[(size_t)r1 * N + col] = v1;
            }
        }
    }
}

// ---------------------------------------------------------------------------
// Launcher
// ---------------------------------------------------------------------------
extern "C" void kernel_launch(void* const* d_in, const int* in_sizes, int n_in,
                              void* d_out, int out_size) {
    const float* x     = (const float*)d_in[0];
    const float* ln1_g = (const float*)d_in[1];
    const float* ln1_b = (const float*)d_in[2];
    const float* ln2_g = (const float*)d_in[3];
    const float* ln2_b = (const float*)d_in[4];
    const float* w_qkv = (const float*)d_in[5];
    const float* b_qkv = (const float*)d_in[6];
    const float* w_out = (const float*)d_in[7];
    const float* b_out = (const float*)d_in[8];
    const float* w1    = (const float*)d_in[9];
    const float* b1    = (const float*)d_in[10];
    const float* w2    = (const float*)d_in[11];
    const float* b2    = (const float*)d_in[12];
    float* out = (float*)d_out;

    __nv_bfloat16 *a1, *aob, *x2b, *hid, *wo, *ww1, *ww2;
    float* x2;
    cudaGetSymbolAddress((void**)&a1,  g_a1);
    cudaGetSymbolAddress((void**)&aob, g_ao);
    cudaGetSymbolAddress((void**)&x2,  g_x2);
    cudaGetSymbolAddress((void**)&x2b, g_x2b);
    cudaGetSymbolAddress((void**)&hid, g_hid);
    cudaGetSymbolAddress((void**)&wo,  g_wout);
    cudaGetSymbolAddress((void**)&ww1, g_w1);
    cudaGetSymbolAddress((void**)&ww2, g_w2);

    cudaFuncSetAttribute(attn_fused, cudaFuncAttributeMaxDynamicSharedMemorySize, FUSED_SMEM);
    cudaFuncSetAttribute(bgemm<2>, cudaFuncAttributeMaxDynamicSharedMemorySize, GEMM_SMEM);
    cudaFuncSetAttribute(bgemm<3>, cudaFuncAttributeMaxDynamicSharedMemorySize, GEMM_SMEM);
    cudaFuncSetAttribute(bgemm<4>, cudaFuncAttributeMaxDynamicSharedMemorySize, GEMM_SMEM);

    // 0) weight prep
    wcvt<<<864, 256>>>(w_qkv, w_out, w2);
    prep1<<<48, 256>>>(w1, ln2_g, ln2_b);
    // 1) LN1 + shift + window partition -> a1 (bf16, window order)
    ln1_kernel<<<NTOK / 8, 256>>>(x, ln1_g, ln1_b, a1);
    // 2) fused QKV GEMM + attention (head pairs) -> ao
    attn_fused<<<dim3(1024, 3), 256, FUSED_SMEM>>>(a1, b_qkv, aob);
    // 3) proj + residual + scatter -> x2 fp32 + x2b bf16 + LN2 stat partials
    bgemm<3><<<dim3(1, NTOK / BM), 256, GEMM_SMEM>>>(aob, wo, b_out, x2, x, 192, 192);
    // 4) finalize LN2 stats
    finstats<<<NTOK / 256, 256>>>();
    // 5) fc1 (LN2 folded) + GELU -> hid
    bgemm<4><<<dim3(2, NTOK / BM), 256, GEMM_SMEM>>>(x2b, ww1, b1, hid, nullptr, 384, 192);
    // 6) fc2 + residual -> out
    bgemm<2><<<dim3(1, NTOK / BM), 256, GEMM_SMEM>>>(hid, ww2, b2, out, x2, 192, 384);
}

// round 11
// speedup vs baseline: 1.1642x; 1.1642x over previous
#include <cuda_runtime.h>
#include <cuda_bf16.h>
#include <math.h>
#include <stdint.h>

// ---------------------------------------------------------------------------
// Swin block: B=32, H=W=56, D=192, HEADS=6, DH=32, WS=7, SHIFT=3, no pad,
// no attention mask (per reference).
// R11: R9 base (best) + attn_fused as 512-thread head-pair CTA with the SAME
// 32x48 per-warp tile (48 acc regs -> no spills), halving A-side redundancy.
// ---------------------------------------------------------------------------

#define NHW   3136
#define NTOK  100352
#define DIM   192

__device__ __nv_bfloat16 g_a1 [(size_t)NTOK * DIM];   // LN1 out (window order)
__device__ __nv_bfloat16 g_ao [(size_t)NTOK * DIM];   // attn out (window order)
__device__ float         g_x2 [(size_t)NTOK * DIM];   // x2 fp32 (plain order)
__device__ __nv_bfloat16 g_x2b[(size_t)NTOK * DIM];   // x2 bf16 (plain order)
__device__ __nv_bfloat16 g_hid[(size_t)NTOK * 384];   // fc1 GELU out
__device__ __nv_bfloat16 g_wqkv[576 * 192];
__device__ __nv_bfloat16 g_wout[192 * 192];
__device__ __nv_bfloat16 g_w1  [384 * 192];           // gamma2-folded
__device__ __nv_bfloat16 g_w2  [192 * 384];
__device__ float2        g_st1 [384];
__device__ float2        g_pbuf[4 * NTOK];
__device__ float2        g_mstat[NTOK];
__device__ __align__(16) __nv_bfloat16 g_zbuf[16];

__device__ __forceinline__ int src_index(int r) {
    int w = r / 49, p = r % 49;
    int b  = w >> 6;
    int wy = (w & 63) >> 3;
    int wx = w & 7;
    int py = p / 7, px = p % 7;
    int h2 = wy * 7 + py;
    int w2 = wx * 7 + px;
    int hs = h2 + 3; if (hs >= 56) hs -= 56;
    int ws = w2 + 3; if (ws >= 56) ws -= 56;
    return b * NHW + hs * 56 + ws;
}

// ---------------------------------------------------------------------------
__device__ __forceinline__ uint32_t smem_u32(const void* p) {
    uint32_t a;
    asm("{ .reg .u64 t; cvta.to.shared.u64 t, %1; cvt.u32.u64 %0, t; }" : "=r"(a) : "l"(p));
    return a;
}
__device__ __forceinline__ void cp_async16(uint32_t dst, const void* src) {
    asm volatile("cp.async.ca.shared.global [%0], [%1], 16;" :: "r"(dst), "l"(src));
}
#define CP_COMMIT()  asm volatile("cp.async.commit_group;" ::: "memory")
#define CP_WAIT(n)   asm volatile("cp.async.wait_group %0;" :: "n"(n) : "memory")

__device__ __forceinline__ void ldsm4(uint32_t* r, uint32_t addr) {
    asm volatile("ldmatrix.sync.aligned.m8n8.x4.shared.b16 {%0,%1,%2,%3}, [%4];"
        : "=r"(r[0]), "=r"(r[1]), "=r"(r[2]), "=r"(r[3]) : "r"(addr));
}
__device__ __forceinline__ void ldsm2(uint32_t* r, uint32_t addr) {
    asm volatile("ldmatrix.sync.aligned.m8n8.x2.shared.b16 {%0,%1}, [%2];"
        : "=r"(r[0]), "=r"(r[1]) : "r"(addr));
}
__device__ __forceinline__ void ldsm4t(uint32_t* r, uint32_t addr) {
    asm volatile("ldmatrix.sync.aligned.m8n8.x4.trans.shared.b16 {%0,%1,%2,%3}, [%4];"
        : "=r"(r[0]), "=r"(r[1]), "=r"(r[2]), "=r"(r[3]) : "r"(addr));
}
__device__ __forceinline__ void mma_bf16(float* c, const uint32_t* a, const uint32_t* b) {
    asm volatile(
        "mma.sync.aligned.m16n8k16.row.col.f32.bf16.bf16.f32 "
        "{%0,%1,%2,%3}, {%4,%5,%6,%7}, {%8,%9}, {%0,%1,%2,%3};"
        : "+f"(c[0]), "+f"(c[1]), "+f"(c[2]), "+f"(c[3])
        : "r"(a[0]), "r"(a[1]), "r"(a[2]), "r"(a[3]), "r"(b[0]), "r"(b[1]));
}
__device__ __forceinline__ float gelu_exact(float v) {
    return 0.5f * v * (1.0f + erff(v * 0.7071067811865476f));
}
__device__ __forceinline__ uint32_t packbf(float a, float b) {
    __nv_bfloat162 t = __floats2bfloat162_rn(a, b);
    return *(uint32_t*)&t;
}

// ---------------------------------------------------------------------------
__global__ void wcvt(const float* __restrict__ wqkv, const float* __restrict__ wout,
                     const float* __restrict__ w2) {
    int i = blockIdx.x * 256 + threadIdx.x;
    if (i < 110592)       g_wqkv[i]          = __float2bfloat16(wqkv[i]);
    else if (i < 147456)  g_wout[i - 110592] = __float2bfloat16(wout[i - 110592]);
    else                  g_w2[i - 147456]   = __float2bfloat16(w2[i - 147456]);
    if (i < 16) g_zbuf[i] = __float2bfloat16(0.0f);
}

__global__ void prep1(const float* __restrict__ w1, const float* __restrict__ g2,
                      const float* __restrict__ b2) {
    int n = blockIdx.x * 8 + (threadIdx.x >> 5);
    int lane = threadIdx.x & 31;
    float S = 0.0f, T = 0.0f;
#pragma unroll
    for (int j = 0; j < 6; j++) {
        int k = lane + 32 * j;
        float w = w1[n * 192 + k];
        __nv_bfloat16 wb = __float2bfloat16(w * g2[k]);
        g_w1[n * 192 + k] = wb;
        S += __bfloat162float(wb);
        T += b2[k] * w;
    }
#pragma unroll
    for (int o = 16; o; o >>= 1) {
        S += __shfl_xor_sync(0xffffffffu, S, o);
        T += __shfl_xor_sync(0xffffffffu, T, o);
    }
    if (lane == 0) g_st1[n] = make_float2(S, T);
}

__global__ void finstats() {
    int i = blockIdx.x * 256 + threadIdx.x;
    float s = 0.0f, q = 0.0f;
#pragma unroll
    for (int k = 0; k < 4; k++) {
        float2 p = g_pbuf[k * NTOK + i];
        s += p.x; q += p.y;
    }
    float mean = s * (1.0f / 192.0f);
    float var  = q * (1.0f / 192.0f) - mean * mean;
    g_mstat[i] = make_float2(mean, rsqrtf(var + 1e-5f));
}

__global__ void ln1_kernel(const float* __restrict__ x,
                           const float* __restrict__ gam,
                           const float* __restrict__ bet,
                           __nv_bfloat16* __restrict__ out) {
    int t    = blockIdx.x * 8 + (threadIdx.x >> 5);
    int lane = threadIdx.x & 31;
    const float* xr = x + (size_t)src_index(t) * DIM;

    float v[6];
#pragma unroll
    for (int i = 0; i < 6; i++) v[i] = xr[lane + 32 * i];

    float s = v[0] + v[1] + v[2] + v[3] + v[4] + v[5];
#pragma unroll
    for (int o = 16; o; o >>= 1) s += __shfl_xor_sync(0xffffffffu, s, o);
    float mean = s * (1.0f / 192.0f);

    float q = 0.0f;
#pragma unroll
    for (int i = 0; i < 6; i++) { float d = v[i] - mean; q += d * d; }
#pragma unroll
    for (int o = 16; o; o >>= 1) q += __shfl_xor_sync(0xffffffffu, q, o);
    float rstd = rsqrtf(q * (1.0f / 192.0f) + 1e-5f);

    __nv_bfloat16* orow = out + (size_t)t * DIM;
#pragma unroll
    for (int i = 0; i < 6; i++) {
        int c = lane + 32 * i;
        orow[c] = __float2bfloat16((v[i] - mean) * rstd * gam[c] + bet[c]);
    }
}

// ---------------------------------------------------------------------------
// Fused QKV-GEMM + window attention, 512-thread head-pair CTA.
// CTA = (window pair p, head pair hp). 16 warps.
// Phase 1: qkv[128 x 192] for heads {2hp, 2hp+1}; warp grid 4m(32) x 4n(48),
//          per-warp tile 32x48 (acc[2][6][4] = 48 regs, same as R9).
//   qkv smem col n -> seg = n/64 (q/k/v), hh = (n/32)&1, c = n%32.
// Phase 2: warp -> (window wi, head hh, row-tile mq); per-head R9 body.
// ---------------------------------------------------------------------------
#define FBK   16
#define FSTG  4
#define FAROW 24
#define FASZ  (128 * FAROW * 2)          // 6144
#define FWSZ  (192 * FAROW * 2)          // 9216
#define QS2   200                        // qkv smem row stride (bf16)
#define OFF_WS (FSTG * FASZ)             // 24576
#define OFF_QS (OFF_WS + FSTG * FWSZ)    // 61440
#define FUSED_SMEM (OFF_QS + 128 * QS2 * 2)  // 112640

__global__ __launch_bounds__(512, 1)
void attn_fused(const __nv_bfloat16* __restrict__ a1,
                const float* __restrict__ bqkv,
                __nv_bfloat16* __restrict__ ao) {
    extern __shared__ char smem[];
    const int tid  = threadIdx.x;
    const int warp = tid >> 5;
    const int lane = tid & 31;
    const int g    = lane >> 2;
    const int tin  = lane & 3;
    const int l15  = lane & 15;
    const int lhi  = lane >> 4;
    const int p    = blockIdx.x;          // window pair
    const int hp   = blockIdx.y;          // head pair
    const int R0   = p * 98;

    const uint32_t sb = smem_u32(smem);

    // ---- load assignments ----
    // A: 128 rows x 2 chunks = 256 assignments (tid < 256)
    const bool ald = tid < 256;
    const int arow = (tid >> 1) & 127, achk = tid & 1;
    const bool areal = ald && arow < 98;
    const __nv_bfloat16* Ag = areal ? (a1 + (size_t)(R0 + arow) * 192 + achk * 8)
                                    : (const __nv_bfloat16*)g_zbuf;
    const uint32_t asb = sb + (arow * FAROW + achk * 8) * 2;

    // B: 192 rows x 2 chunks = 384 assignments (tid < 384)
    const bool bld = tid < 384;
    const int brow = bld ? (tid >> 1) : 0;   // 0..191
    const int bchk = tid & 1;
    const int bseg = brow >> 6;              // q/k/v
    const int bhh  = (brow >> 5) & 1;        // head within pair
    const int brr  = brow & 31;
    const __nv_bfloat16* Wg = g_wqkv
        + (size_t)(bseg * 192 + (hp * 2 + bhh) * 32 + brr) * 192 + bchk * 8;
    const uint32_t wsb = sb + OFF_WS + (brow * FAROW + bchk * 8) * 2;

#pragma unroll
    for (int s = 0; s < FSTG - 1; s++) {
        if (ald) cp_async16(asb + s * FASZ, areal ? (Ag + s * FBK) : Ag);
        if (bld) cp_async16(wsb + s * FWSZ, Wg + s * FBK);
        CP_COMMIT();
    }

    // ---- Phase 1: warp grid 4m(32) x 4n(48) ----
    const int wm = (warp & 3) * 32;
    const int wn = (warp >> 2) * 48;

    float acc[2][6][4];
#pragma unroll
    for (int i = 0; i < 2; i++)
#pragma unroll
        for (int j = 0; j < 6; j++)
#pragma unroll
            for (int l = 0; l < 4; l++) acc[i][j][l] = 0.0f;

    const uint32_t albase = sb + (uint32_t)(wm + l15) * (FAROW * 2) + lhi * 16;
    const uint32_t wbbase = sb + OFF_WS
                          + (uint32_t)(wn + ((lane >> 4) & 1) * 8 + (lane & 7)) * (FAROW * 2)
                          + ((lane >> 3) & 1) * 16;

    for (int t = 0; t < 12; t++) {
        CP_WAIT(FSTG - 2);
        __syncthreads();
        const int tn = t + FSTG - 1;
        if (tn < 12) {
            const int s = tn % FSTG;
            if (ald) cp_async16(asb + s * FASZ, areal ? (Ag + tn * FBK) : Ag);
            if (bld) cp_async16(wsb + s * FWSZ, Wg + tn * FBK);
        }
        CP_COMMIT();

        const int st = t % FSTG;
        uint32_t af[2][4];
        ldsm4(af[0], albase + st * FASZ);
        ldsm4(af[1], albase + st * FASZ + 16 * (FAROW * 2));

        uint32_t bq[3][4];
#pragma unroll
        for (int pr = 0; pr < 3; pr++)
            ldsm4(bq[pr], wbbase + st * FWSZ + pr * 16 * (FAROW * 2));

#pragma unroll
        for (int mt = 0; mt < 2; mt++)
#pragma unroll
            for (int pr = 0; pr < 3; pr++) {
                mma_bf16(acc[mt][2 * pr + 0], af[mt], &bq[pr][0]);
                mma_bf16(acc[mt][2 * pr + 1], af[mt], &bq[pr][2]);
            }
    }

    // epilogue: + bias, store to qkv smem tile [128][QS2]
    __nv_bfloat16* qs = (__nv_bfloat16*)(smem + OFF_QS);
#pragma unroll
    for (int mt = 0; mt < 2; mt++) {
        const int r0 = wm + mt * 16 + g;
#pragma unroll
        for (int nt = 0; nt < 6; nt++) {
            const int n   = wn + nt * 8 + 2 * tin;
            const int seg = n >> 6;
            const int hh  = (n >> 5) & 1;
            const int bcol = seg * 192 + (hp * 2 + hh) * 32 + (n & 31);
            const float2 bv = *(const float2*)&bqkv[bcol];
            *(uint32_t*)&qs[r0 * QS2 + n]       = packbf(acc[mt][nt][0] + bv.x, acc[mt][nt][1] + bv.y);
            *(uint32_t*)&qs[(r0 + 8) * QS2 + n] = packbf(acc[mt][nt][2] + bv.x, acc[mt][nt][3] + bv.y);
        }
    }
    __syncthreads();

    // ---- Phase 2: warp -> (window, head, row-tile) ----
    const int wi = warp >> 3;             // window in pair
    const int hh = (warp >> 2) & 1;       // head in pair
    const int mq = (warp & 3) * 16;       // row tile within window
    const int rb = wi * 49 + mq;
    const uint32_t qsu = sb + OFF_QS;
    const float scale = 0.17677669529663687f;   // 1/sqrt(32)

    const int qo = 64 * hh;               // byte offsets within a row
    const int ko = 128 + 64 * hh;
    const int vo = 256 + 64 * hh;

    float a7[7][4];
#pragma unroll
    for (int nt = 0; nt < 7; nt++)
#pragma unroll
        for (int c = 0; c < 4; c++) a7[nt][c] = 0.0f;

    const uint32_t kbase = qsu
        + (uint32_t)(wi * 49 + ((lane >> 4) & 1) * 8 + (lane & 7)) * (QS2 * 2)
        + ko + ((lane >> 3) & 1) * 16;

#pragma unroll
    for (int kc = 0; kc < 2; kc++) {
        uint32_t qa[4];
        ldsm4(qa, qsu + (uint32_t)(rb + l15) * (QS2 * 2) + qo + kc * 32 + lhi * 16);
        uint32_t kq[3][4];
#pragma unroll
        for (int pr = 0; pr < 3; pr++)
            ldsm4(kq[pr], kbase + kc * 32 + pr * 16 * (QS2 * 2));
        uint32_t k6[2];
        ldsm2(k6, qsu + (uint32_t)(wi * 49 + 48 + (lane & 7)) * (QS2 * 2)
                   + ko + kc * 32 + ((lane >> 3) & 1) * 16);
#pragma unroll
        for (int pr = 0; pr < 3; pr++) {
            mma_bf16(a7[2 * pr + 0], qa, &kq[pr][0]);
            mma_bf16(a7[2 * pr + 1], qa, &kq[pr][2]);
        }
        mma_bf16(a7[6], qa, k6);
    }

    float mx0 = -1e30f, mx1 = -1e30f;
#pragma unroll
    for (int nt = 0; nt < 7; nt++) {
        int c0 = nt * 8 + 2 * tin;
        float* a = a7[nt];
        a[0] = (c0     < 49) ? a[0] * scale : -1e30f;
        a[1] = (c0 + 1 < 49) ? a[1] * scale : -1e30f;
        a[2] = (c0     < 49) ? a[2] * scale : -1e30f;
        a[3] = (c0 + 1 < 49) ? a[3] * scale : -1e30f;
        mx0 = fmaxf(mx0, fmaxf(a[0], a[1]));
        mx1 = fmaxf(mx1, fmaxf(a[2], a[3]));
    }
    mx0 = fmaxf(mx0, __shfl_xor_sync(0xffffffffu, mx0, 1));
    mx0 = fmaxf(mx0, __shfl_xor_sync(0xffffffffu, mx0, 2));
    mx1 = fmaxf(mx1, __shfl_xor_sync(0xffffffffu, mx1, 1));
    mx1 = fmaxf(mx1, __shfl_xor_sync(0xffffffffu, mx1, 2));

    float ss0 = 0.0f, ss1 = 0.0f;
    uint32_t pk[8][2];
#pragma unroll
    for (int nt = 0; nt < 7; nt++) {
        float* a = a7[nt];
        a[0] = __expf(a[0] - mx0);
        a[1] = __expf(a[1] - mx0);
        a[2] = __expf(a[2] - mx1);
        a[3] = __expf(a[3] - mx1);
        ss0 += a[0] + a[1];
        ss1 += a[2] + a[3];
        pk[nt][0] = packbf(a[0], a[1]);
        pk[nt][1] = packbf(a[2], a[3]);
    }
    pk[7][0] = 0u; pk[7][1] = 0u;
    ss0 += __shfl_xor_sync(0xffffffffu, ss0, 1);
    ss0 += __shfl_xor_sync(0xffffffffu, ss0, 2);
    ss1 += __shfl_xor_sync(0xffffffffu, ss1, 1);
    ss1 += __shfl_xor_sync(0xffffffffu, ss1, 2);

    float pv[4][4];
#pragma unroll
    for (int nt = 0; nt < 4; nt++)
#pragma unroll
        for (int c = 0; c < 4; c++) pv[nt][c] = 0.0f;

    const uint32_t vbase = qsu + (uint32_t)(wi * 49 + l15) * (QS2 * 2) + vo + lhi * 16;

#pragma unroll
    for (int kc = 0; kc < 4; kc++) {
        uint32_t pa[4] = { pk[2 * kc][0], pk[2 * kc][1], pk[2 * kc + 1][0], pk[2 * kc + 1][1] };
        uint32_t vq[2][4];
#pragma unroll
        for (int pr = 0; pr < 2; pr++)
            ldsm4t(vq[pr], vbase + kc * 16 * (QS2 * 2) + pr * 32);
#pragma unroll
        for (int pr = 0; pr < 2; pr++) {
            mma_bf16(pv[2 * pr + 0], pa, &vq[pr][0]);
            mma_bf16(pv[2 * pr + 1], pa, &vq[pr][2]);
        }
    }

    const float inv0 = 1.0f / ss0;
    const float inv1 = 1.0f / ss1;
    const int head = hp * 2 + hh;
    const int rr0 = mq + g;
    if (rr0 < 49) {
        __nv_bfloat16* ob = ao + (size_t)(R0 + wi * 49 + rr0) * 192 + head * 32;
#pragma unroll
        for (int nt = 0; nt < 4; nt++)
            *(uint32_t*)&ob[nt * 8 + 2 * tin] = packbf(pv[nt][0] * inv0, pv[nt][1] * inv0);
    }
    if (rr0 + 8 < 49) {
        __nv_bfloat16* ob = ao + (size_t)(R0 + wi * 49 + rr0 + 8) * 192 + head * 32;
#pragma unroll
        for (int nt = 0; nt < 4; nt++)
            *(uint32_t*)&ob[nt * 8 + 2 * tin] = packbf(pv[nt][2] * inv1, pv[nt][3] * inv1);
    }
}

// ---------------------------------------------------------------------------
// bf16 GEMM, BN=96 (R9 version, unchanged). EPIs:
//   2: v += res[row]; fp32 store (fc2 -> out)
//   3: v += res[src(row)]; fp32 scatter store + bf16 copy + LN2 stat partials
//   4: LN2-affine then GELU, bf16 store
// ---------------------------------------------------------------------------
#define BM 128
#define BN 96
#define BK 16
#define STG 4
#define AROW 24

template <int EPI>
__global__ __launch_bounds__(256, 2)
void bgemm(const __nv_bfloat16* __restrict__ A, const __nv_bfloat16* __restrict__ W,
           const float* __restrict__ bias, void* __restrict__ outp,
           const float* __restrict__ res, int N, int K) {
    __shared__ __align__(16) __nv_bfloat16 As[STG][BM * AROW];
    __shared__ __align__(16) __nv_bfloat16 Ws[STG][BN * AROW];

    const int tid  = threadIdx.x;
    const int wid  = tid >> 5;
    const int lane = tid & 31;
    const int g    = lane >> 2;
    const int tin  = lane & 3;
    const int wm   = (wid & 3) * 32;
    const int wn   = (wid >> 2) * 48;
    const int row0 = blockIdx.y * BM;
    const int col0 = blockIdx.x * BN;

    const int arow = tid >> 1, achk = tid & 1;
    const bool bld = tid < 192;
    const int brow = bld ? (tid >> 1) : 0;
    const int bchk = tid & 1;

    const __nv_bfloat16* Ag = A + (size_t)(row0 + arow) * K + achk * 8;
    const __nv_bfloat16* Wg = W + (size_t)(col0 + brow) * K + bchk * 8;
    const uint32_t asb = smem_u32(As) + (arow * AROW + achk * 8) * 2;
    const uint32_t wsb = smem_u32(Ws) + (brow * AROW + bchk * 8) * 2;
    const uint32_t ASZ = BM * AROW * 2;
    const uint32_t WSZ = BN * AROW * 2;

    const int T = K / BK;
#pragma unroll
    for (int s = 0; s < STG - 1; s++) {
        cp_async16(asb + s * ASZ, Ag + s * BK);
        if (bld) cp_async16(wsb + s * WSZ, Wg + s * BK);
        CP_COMMIT();
    }

    float acc[2][6][4];
#pragma unroll
    for (int i = 0; i < 2; i++)
#pragma unroll
        for (int j = 0; j < 6; j++)
#pragma unroll
            for (int l = 0; l < 4; l++) acc[i][j][l] = 0.0f;

    const uint32_t albase = smem_u32(As) + ((wm + (lane & 15)) * AROW) * 2 + (lane >> 4) * 16;
    const uint32_t wbbase = smem_u32(Ws)
                          + (uint32_t)(wn + ((lane >> 4) & 1) * 8 + (lane & 7)) * (AROW * 2)
                          + ((lane >> 3) & 1) * 16;

    for (int t = 0; t < T; t++) {
        CP_WAIT(STG - 2);
        __syncthreads();
        const int tn = t + STG - 1;
        if (tn < T) {
            const int s = tn % STG;
            cp_async16(asb + s * ASZ, Ag + tn * BK);
            if (bld) cp_async16(wsb + s * WSZ, Wg + tn * BK);
        }
        CP_COMMIT();

        const int st = t % STG;
        uint32_t af[2][4];
        ldsm4(af[0], albase + st * ASZ);
        ldsm4(af[1], albase + st * ASZ + 16 * AROW * 2);

        uint32_t bq[3][4];
#pragma unroll
        for (int pr = 0; pr < 3; pr++)
            ldsm4(bq[pr], wbbase + st * WSZ + pr * 16 * (AROW * 2));

#pragma unroll
        for (int mt = 0; mt < 2; mt++)
#pragma unroll
            for (int pr = 0; pr < 3; pr++) {
                mma_bf16(acc[mt][2 * pr + 0], af[mt], &bq[pr][0]);
                mma_bf16(acc[mt][2 * pr + 1], af[mt], &bq[pr][2]);
            }
    }

    __nv_bfloat16* outb = (__nv_bfloat16*)outp;
    float*         outf = (float*)outp;

#pragma unroll
    for (int mt = 0; mt < 2; mt++) {
        const int r0 = row0 + wm + mt * 16 + g;
        const int r1 = r0 + 8;

        if (EPI == 3) {
            const int d0 = src_index(r0);
            const int d1 = src_index(r1);
            float s0 = 0.0f, q0 = 0.0f, s1 = 0.0f, q1 = 0.0f;
#pragma unroll
            for (int nt = 0; nt < 6; nt++) {
                const int col = col0 + wn + nt * 8 + 2 * tin;
                const float2 bv = *(const float2*)&bias[col];
                float2 v0, v1;
                v0.x = acc[mt][nt][0] + bv.x;
                v0.y = acc[mt][nt][1] + bv.y;
                v1.x = acc[mt][nt][2] + bv.x;
                v1.y = acc[mt][nt][3] + bv.y;
                float2 e0 = *(const float2*)&res[(size_t)d0 * 192 + col];
                float2 e1 = *(const float2*)&res[(size_t)d1 * 192 + col];
                v0.x += e0.x; v0.y += e0.y;
                v1.x += e1.x; v1.y += e1.y;
                *(float2*)&outf[(size_t)d0 * 192 + col] = v0;
                *(float2*)&outf[(size_t)d1 * 192 + col] = v1;
                *(uint32_t*)&g_x2b[(size_t)d0 * 192 + col] = packbf(v0.x, v0.y);
                *(uint32_t*)&g_x2b[(size_t)d1 * 192 + col] = packbf(v1.x, v1.y);
                s0 += v0.x + v0.y; q0 += v0.x * v0.x + v0.y * v0.y;
                s1 += v1.x + v1.y; q1 += v1.x * v1.x + v1.y * v1.y;
            }
            s0 += __shfl_xor_sync(0xffffffffu, s0, 1);
            s0 += __shfl_xor_sync(0xffffffffu, s0, 2);
            q0 += __shfl_xor_sync(0xffffffffu, q0, 1);
            q0 += __shfl_xor_sync(0xffffffffu, q0, 2);
            s1 += __shfl_xor_sync(0xffffffffu, s1, 1);
            s1 += __shfl_xor_sync(0xffffffffu, s1, 2);
            q1 += __shfl_xor_sync(0xffffffffu, q1, 1);
            q1 += __shfl_xor_sync(0xffffffffu, q1, 2);
            if (tin == 0) {
                const int slot = blockIdx.x * 2 + (wid >> 2);
                g_pbuf[slot * NTOK + d0] = make_float2(s0, q0);
                g_pbuf[slot * NTOK + d1] = make_float2(s1, q1);
            }
        } else if (EPI == 4) {
            const float2 mr0 = g_mstat[r0];
            const float2 mr1 = g_mstat[r1];
            const float a0 = mr0.y, b0 = mr0.x * mr0.y;
            const float a1 = mr1.y, b1c = mr1.x * mr1.y;
#pragma unroll
            for (int nt = 0; nt < 6; nt++) {
                const int col = col0 + wn + nt * 8 + 2 * tin;
                const float2 bv = *(const float2*)&bias[col];
                const float2 stA = g_st1[col];
                const float2 stB = g_st1[col + 1];
                float v00 = gelu_exact(a0 * acc[mt][nt][0] - b0 * stA.x + stA.y + bv.x);
                float v01 = gelu_exact(a0 * acc[mt][nt][1] - b0 * stB.x + stB.y + bv.y);
                float v10 = gelu_exact(a1 * acc[mt][nt][2] - b1c * stA.x + stA.y + bv.x);
                float v11 = gelu_exact(a1 * acc[mt][nt][3] - b1c * stB.x + stB.y + bv.y);
                *(uint32_t*)&outb[(size_t)r0 * N + col] = packbf(v00, v01);
                *(uint32_t*)&outb[(size_t)r1 * N + col] = packbf(v10, v11);
            }
        } else {  // EPI 2
#pragma unroll
            for (int nt = 0; nt < 6; nt++) {
                const int col = col0 + wn + nt * 8 + 2 * tin;
                const float2 bv = *(const float2*)&bias[col];
                float2 v0, v1;
                v0.x = acc[mt][nt][0] + bv.x;
                v0.y = acc[mt][nt][1] + bv.y;
                v1.x = acc[mt][nt][2] + bv.x;
                v1.y = acc[mt][nt][3] + bv.y;
                float2 e0 = *(const float2*)&res[(size_t)r0 * N + col];
                float2 e1 = *(const float2*)&res[(size_t)r1 * N + col];
                v0.x += e0.x; v0.y += e0.y;
                v1.x += e1.x; v1.y += e1.y;
                *(float2*)&outf[(size_t)r0 * N + col] = v0;
                *(float2*)&outf[(size_t)r1 * N + col] = v1;
            }
        }
    }
}

// ---------------------------------------------------------------------------
// Launcher
// ---------------------------------------------------------------------------
extern "C" void kernel_launch(void* const* d_in, const int* in_sizes, int n_in,
                              void* d_out, int out_size) {
    const float* x     = (const float*)d_in[0];
    const float* ln1_g = (const float*)d_in[1];
    const float* ln1_b = (const float*)d_in[2];
    const float* ln2_g = (const float*)d_in[3];
    const float* ln2_b = (const float*)d_in[4];
    const float* w_qkv = (const float*)d_in[5];
    const float* b_qkv = (const float*)d_in[6];
    const float* w_out = (const float*)d_in[7];
    const float* b_out = (const float*)d_in[8];
    const float* w1    = (const float*)d_in[9];
    const float* b1    = (const float*)d_in[10];
    const float* w2    = (const float*)d_in[11];
    const float* b2    = (const float*)d_in[12];
    float* out = (float*)d_out;

    __nv_bfloat16 *a1, *aob, *x2b, *hid, *wo, *ww1, *ww2;
    float* x2;
    cudaGetSymbolAddress((void**)&a1,  g_a1);
    cudaGetSymbolAddress((void**)&aob, g_ao);
    cudaGetSymbolAddress((void**)&x2,  g_x2);
    cudaGetSymbolAddress((void**)&x2b, g_x2b);
    cudaGetSymbolAddress((void**)&hid, g_hid);
    cudaGetSymbolAddress((void**)&wo,  g_wout);
    cudaGetSymbolAddress((void**)&ww1, g_w1);
    cudaGetSymbolAddress((void**)&ww2, g_w2);

    cudaFuncSetAttribute(attn_fused, cudaFuncAttributeMaxDynamicSharedMemorySize, FUSED_SMEM);

    // 0) weight prep
    wcvt<<<864, 256>>>(w_qkv, w_out, w2);
    prep1<<<48, 256>>>(w1, ln2_g, ln2_b);
    // 1) LN1 + shift + window partition -> a1 (bf16, window order)
    ln1_kernel<<<NTOK / 8, 256>>>(x, ln1_g, ln1_b, a1);
    // 2) fused QKV GEMM + attention (512-thr head-pair CTAs) -> ao
    attn_fused<<<dim3(1024, 3), 512, FUSED_SMEM>>>(a1, b_qkv, aob);
    // 3) proj + residual + scatter -> x2 fp32 + x2b bf16 + LN2 stat partials
    bgemm<3><<<dim3(2, NTOK / BM), 256>>>(aob, wo, b_out, x2, x, 192, 192);
    // 4) finalize LN2 stats
    finstats<<<NTOK / 256, 256>>>();
    // 5) fc1 (LN2 folded) + GELU -> hid
    bgemm<4><<<dim3(4, NTOK / BM), 256>>>(x2b, ww1, b1, hid, nullptr, 384, 192);
    // 6) fc2 + residual -> out
    bgemm<2><<<dim3(2, NTOK / BM), 256>>>(hid, ww2, b2, out, x2, 192, 384);
}

// round 12
// speedup vs baseline: 1.2575x; 1.0801x over previous
#include <cuda_runtime.h>
#include <cuda_bf16.h>
#include <math.h>
#include <stdint.h>

// ---------------------------------------------------------------------------
// Swin block: B=32, H=W=56, D=192, HEADS=6, DH=32, WS=7, SHIFT=3, no pad,
// no attention mask (per reference).
// R12: R9 base (best, 503.8us) + fused MLP: fc1(+LN2 affine+GELU) and fc2
// in ONE kernel; hid lives only in SMEM (removes 154 MB DRAM round-trip).
// ---------------------------------------------------------------------------

#define NHW   3136
#define NTOK  100352
#define DIM   192

__device__ __nv_bfloat16 g_a1 [(size_t)NTOK * DIM];   // LN1 out (window order)
__device__ __nv_bfloat16 g_ao [(size_t)NTOK * DIM];   // attn out (window order)
__device__ float         g_x2 [(size_t)NTOK * DIM];   // x2 fp32 (plain order)
__device__ __nv_bfloat16 g_x2b[(size_t)NTOK * DIM];   // x2 bf16 (plain order)
__device__ __nv_bfloat16 g_wqkv[576 * 192];
__device__ __nv_bfloat16 g_wout[192 * 192];
__device__ __nv_bfloat16 g_w1  [384 * 192];           // gamma2-folded
__device__ __nv_bfloat16 g_w2  [192 * 384];
__device__ float2        g_st1 [384];
__device__ float2        g_pbuf[4 * NTOK];
__device__ float2        g_mstat[NTOK];
__device__ __align__(16) __nv_bfloat16 g_zbuf[16];

__device__ __forceinline__ int src_index(int r) {
    int w = r / 49, p = r % 49;
    int b  = w >> 6;
    int wy = (w & 63) >> 3;
    int wx = w & 7;
    int py = p / 7, px = p % 7;
    int h2 = wy * 7 + py;
    int w2 = wx * 7 + px;
    int hs = h2 + 3; if (hs >= 56) hs -= 56;
    int ws = w2 + 3; if (ws >= 56) ws -= 56;
    return b * NHW + hs * 56 + ws;
}

// ---------------------------------------------------------------------------
__device__ __forceinline__ uint32_t smem_u32(const void* p) {
    uint32_t a;
    asm("{ .reg .u64 t; cvta.to.shared.u64 t, %1; cvt.u32.u64 %0, t; }" : "=r"(a) : "l"(p));
    return a;
}
__device__ __forceinline__ void cp_async16(uint32_t dst, const void* src) {
    asm volatile("cp.async.ca.shared.global [%0], [%1], 16;" :: "r"(dst), "l"(src));
}
#define CP_COMMIT()  asm volatile("cp.async.commit_group;" ::: "memory")
#define CP_WAIT(n)   asm volatile("cp.async.wait_group %0;" :: "n"(n) : "memory")

__device__ __forceinline__ void ldsm4(uint32_t* r, uint32_t addr) {
    asm volatile("ldmatrix.sync.aligned.m8n8.x4.shared.b16 {%0,%1,%2,%3}, [%4];"
        : "=r"(r[0]), "=r"(r[1]), "=r"(r[2]), "=r"(r[3]) : "r"(addr));
}
__device__ __forceinline__ void ldsm2(uint32_t* r, uint32_t addr) {
    asm volatile("ldmatrix.sync.aligned.m8n8.x2.shared.b16 {%0,%1}, [%2];"
        : "=r"(r[0]), "=r"(r[1]) : "r"(addr));
}
__device__ __forceinline__ void ldsm4t(uint32_t* r, uint32_t addr) {
    asm volatile("ldmatrix.sync.aligned.m8n8.x4.trans.shared.b16 {%0,%1,%2,%3}, [%4];"
        : "=r"(r[0]), "=r"(r[1]), "=r"(r[2]), "=r"(r[3]) : "r"(addr));
}
__device__ __forceinline__ void mma_bf16(float* c, const uint32_t* a, const uint32_t* b) {
    asm volatile(
        "mma.sync.aligned.m16n8k16.row.col.f32.bf16.bf16.f32 "
        "{%0,%1,%2,%3}, {%4,%5,%6,%7}, {%8,%9}, {%0,%1,%2,%3};"
        : "+f"(c[0]), "+f"(c[1]), "+f"(c[2]), "+f"(c[3])
        : "r"(a[0]), "r"(a[1]), "r"(a[2]), "r"(a[3]), "r"(b[0]), "r"(b[1]));
}
__device__ __forceinline__ float gelu_exact(float v) {
    return 0.5f * v * (1.0f + erff(v * 0.7071067811865476f));
}
__device__ __forceinline__ uint32_t packbf(float a, float b) {
    __nv_bfloat162 t = __floats2bfloat162_rn(a, b);
    return *(uint32_t*)&t;
}

// ---------------------------------------------------------------------------
__global__ void wcvt(const float* __restrict__ wqkv, const float* __restrict__ wout,
                     const float* __restrict__ w2) {
    int i = blockIdx.x * 256 + threadIdx.x;
    if (i < 110592)       g_wqkv[i]          = __float2bfloat16(wqkv[i]);
    else if (i < 147456)  g_wout[i - 110592] = __float2bfloat16(wout[i - 110592]);
    else                  g_w2[i - 147456]   = __float2bfloat16(w2[i - 147456]);
    if (i < 16) g_zbuf[i] = __float2bfloat16(0.0f);
}

__global__ void prep1(const float* __restrict__ w1, const float* __restrict__ g2,
                      const float* __restrict__ b2) {
    int n = blockIdx.x * 8 + (threadIdx.x >> 5);
    int lane = threadIdx.x & 31;
    float S = 0.0f, T = 0.0f;
#pragma unroll
    for (int j = 0; j < 6; j++) {
        int k = lane + 32 * j;
        float w = w1[n * 192 + k];
        __nv_bfloat16 wb = __float2bfloat16(w * g2[k]);
        g_w1[n * 192 + k] = wb;
        S += __bfloat162float(wb);
        T += b2[k] * w;
    }
#pragma unroll
    for (int o = 16; o; o >>= 1) {
        S += __shfl_xor_sync(0xffffffffu, S, o);
        T += __shfl_xor_sync(0xffffffffu, T, o);
    }
    if (lane == 0) g_st1[n] = make_float2(S, T);
}

__global__ void finstats() {
    int i = blockIdx.x * 256 + threadIdx.x;
    float s = 0.0f, q = 0.0f;
#pragma unroll
    for (int k = 0; k < 4; k++) {
        float2 p = g_pbuf[k * NTOK + i];
        s += p.x; q += p.y;
    }
    float mean = s * (1.0f / 192.0f);
    float var  = q * (1.0f / 192.0f) - mean * mean;
    g_mstat[i] = make_float2(mean, rsqrtf(var + 1e-5f));
}

__global__ void ln1_kernel(const float* __restrict__ x,
                           const float* __restrict__ gam,
                           const float* __restrict__ bet,
                           __nv_bfloat16* __restrict__ out) {
    int t    = blockIdx.x * 8 + (threadIdx.x >> 5);
    int lane = threadIdx.x & 31;
    const float* xr = x + (size_t)src_index(t) * DIM;

    float v[6];
#pragma unroll
    for (int i = 0; i < 6; i++) v[i] = xr[lane + 32 * i];

    float s = v[0] + v[1] + v[2] + v[3] + v[4] + v[5];
#pragma unroll
    for (int o = 16; o; o >>= 1) s += __shfl_xor_sync(0xffffffffu, s, o);
    float mean = s * (1.0f / 192.0f);

    float q = 0.0f;
#pragma unroll
    for (int i = 0; i < 6; i++) { float d = v[i] - mean; q += d * d; }
#pragma unroll
    for (int o = 16; o; o >>= 1) q += __shfl_xor_sync(0xffffffffu, q, o);
    float rstd = rsqrtf(q * (1.0f / 192.0f) + 1e-5f);

    __nv_bfloat16* orow = out + (size_t)t * DIM;
#pragma unroll
    for (int i = 0; i < 6; i++) {
        int c = lane + 32 * i;
        orow[c] = __float2bfloat16((v[i] - mean) * rstd * gam[c] + bet[c]);
    }
}

// ---------------------------------------------------------------------------
// Fused QKV-GEMM + window attention (R9 version, unchanged).
// ---------------------------------------------------------------------------
#define FBK   16
#define FSTG  4
#define FAROW 24
#define FASZ  (128 * FAROW * 2)
#define FWSZ  (96 * FAROW * 2)
#define QSTR  104
#define OFF_WS (FSTG * FASZ)
#define OFF_QS (OFF_WS + FSTG * FWSZ)
#define FUSED_SMEM (OFF_QS + 128 * QSTR * 2)  // 69632 B

__global__ __launch_bounds__(256, 2)
void attn_fused(const __nv_bfloat16* __restrict__ a1,
                const float* __restrict__ bqkv,
                __nv_bfloat16* __restrict__ ao) {
    extern __shared__ char smem[];
    const int tid  = threadIdx.x;
    const int warp = tid >> 5;
    const int lane = tid & 31;
    const int g    = lane >> 2;
    const int tin  = lane & 3;
    const int l15  = lane & 15;
    const int lhi  = lane >> 4;
    const int p    = blockIdx.x;
    const int h    = blockIdx.y;
    const int R0   = p * 98;

    const int wm = (warp & 3) * 32;
    const int wn = (warp >> 2) * 48;

    const int arow = tid >> 1, achk = tid & 1;
    const bool areal = arow < 98;
    const __nv_bfloat16* Ag = areal ? (a1 + (size_t)(R0 + arow) * 192 + achk * 8)
                                    : (const __nv_bfloat16*)g_zbuf;
    const bool bld = tid < 192;
    int brow = (tid < 192) ? (tid >> 1) : 0;
    int bchk = tid & 1;
    const int bseg = brow >> 5;
    const __nv_bfloat16* Wg = g_wqkv + (size_t)(bseg * 192 + h * 32 + (brow & 31)) * 192 + bchk * 8;

    const uint32_t sb  = smem_u32(smem);
    const uint32_t asb = sb + (arow * FAROW + achk * 8) * 2;
    const uint32_t wsb = sb + OFF_WS + (brow * FAROW + bchk * 8) * 2;

#pragma unroll
    for (int s = 0; s < FSTG - 1; s++) {
        cp_async16(asb + s * FASZ, areal ? (Ag + s * FBK) : Ag);
        if (bld) cp_async16(wsb + s * FWSZ, Wg + s * FBK);
        CP_COMMIT();
    }

    float acc[2][6][4];
#pragma unroll
    for (int i = 0; i < 2; i++)
#pragma unroll
        for (int j = 0; j < 6; j++)
#pragma unroll
            for (int l = 0; l < 4; l++) acc[i][j][l] = 0.0f;

    const uint32_t albase = sb + ((wm + l15) * FAROW) * 2 + lhi * 16;
    const uint32_t wbbase = sb + OFF_WS
                          + (uint32_t)(wn + ((lane >> 4) & 1) * 8 + (lane & 7)) * (FAROW * 2)
                          + ((lane >> 3) & 1) * 16;

    for (int t = 0; t < 12; t++) {
        CP_WAIT(FSTG - 2);
        __syncthreads();
        const int tn = t + FSTG - 1;
        if (tn < 12) {
            const int s = tn % FSTG;
            cp_async16(asb + s * FASZ, areal ? (Ag + tn * FBK) : Ag);
            if (bld) cp_async16(wsb + s * FWSZ, Wg + tn * FBK);
        }
        CP_COMMIT();

        const int st = t % FSTG;
        uint32_t af[2][4];
        ldsm4(af[0], albase + st * FASZ);
        ldsm4(af[1], albase + st * FASZ + 16 * FAROW * 2);

        uint32_t bq[3][4];
#pragma unroll
        for (int pr = 0; pr < 3; pr++)
            ldsm4(bq[pr], wbbase + st * FWSZ + pr * 16 * (FAROW * 2));

#pragma unroll
        for (int mt = 0; mt < 2; mt++)
#pragma unroll
            for (int pr = 0; pr < 3; pr++) {
                mma_bf16(acc[mt][2 * pr + 0], af[mt], &bq[pr][0]);
                mma_bf16(acc[mt][2 * pr + 1], af[mt], &bq[pr][2]);
            }
    }

    __nv_bfloat16* qs = (__nv_bfloat16*)(smem + OFF_QS);
#pragma unroll
    for (int mt = 0; mt < 2; mt++) {
        const int r0 = wm + mt * 16 + g;
#pragma unroll
        for (int nt = 0; nt < 6; nt++) {
            const int nb  = wn + nt * 8;
            const int seg = nb >> 5;
            const int bcol = seg * 192 + h * 32 + (nb & 31) + 2 * tin;
            const float2 bv = *(const float2*)&bqkv[bcol];
            const int c = nb + 2 * tin;
            *(uint32_t*)&qs[r0 * QSTR + c]       = packbf(acc[mt][nt][0] + bv.x, acc[mt][nt][1] + bv.y);
            *(uint32_t*)&qs[(r0 + 8) * QSTR + c] = packbf(acc[mt][nt][2] + bv.x, acc[mt][nt][3] + bv.y);
        }
    }
    __syncthreads();

    // ---------------- Phase 2: attention ----------------
    const int wi = warp >> 2;
    const int mq = (warp & 3) * 16;
    const int rb = wi * 49 + mq;
    const uint32_t qsu = sb + OFF_QS;

    float a7[7][4];
#pragma unroll
    for (int nt = 0; nt < 7; nt++)
#pragma unroll
        for (int c = 0; c < 4; c++) a7[nt][c] = 0.0f;

    const uint32_t kbase = qsu
        + (uint32_t)(wi * 49 + ((lane >> 4) & 1) * 8 + (lane & 7)) * (QSTR * 2)
        + 64 + ((lane >> 3) & 1) * 16;

#pragma unroll
    for (int kc = 0; kc < 2; kc++) {
        uint32_t qa[4];
        ldsm4(qa, qsu + (uint32_t)(rb + l15) * (QSTR * 2) + kc * 32 + lhi * 16);
        uint32_t kq[3][4];
#pragma unroll
        for (int pr = 0; pr < 3; pr++)
            ldsm4(kq[pr], kbase + kc * 32 + pr * 16 * (QSTR * 2));
        uint32_t k6[2];
        ldsm2(k6, qsu + (uint32_t)(wi * 49 + 48 + (lane & 7)) * (QSTR * 2)
                   + 64 + kc * 32 + ((lane >> 3) & 1) * 16);
#pragma unroll
        for (int pr = 0; pr < 3; pr++) {
            mma_bf16(a7[2 * pr + 0], qa, &kq[pr][0]);
            mma_bf16(a7[2 * pr + 1], qa, &kq[pr][2]);
        }
        mma_bf16(a7[6], qa, k6);
    }

    const float scale = 0.17677669529663687f;
    float mx0 = -1e30f, mx1 = -1e30f;
#pragma unroll
    for (int nt = 0; nt < 7; nt++) {
        int c0 = nt * 8 + 2 * tin;
        float* a = a7[nt];
        a[0] = (c0     < 49) ? a[0] * scale : -1e30f;
        a[1] = (c0 + 1 < 49) ? a[1] * scale : -1e30f;
        a[2] = (c0     < 49) ? a[2] * scale : -1e30f;
        a[3] = (c0 + 1 < 49) ? a[3] * scale : -1e30f;
        mx0 = fmaxf(mx0, fmaxf(a[0], a[1]));
        mx1 = fmaxf(mx1, fmaxf(a[2], a[3]));
    }
    mx0 = fmaxf(mx0, __shfl_xor_sync(0xffffffffu, mx0, 1));
    mx0 = fmaxf(mx0, __shfl_xor_sync(0xffffffffu, mx0, 2));
    mx1 = fmaxf(mx1, __shfl_xor_sync(0xffffffffu, mx1, 1));
    mx1 = fmaxf(mx1, __shfl_xor_sync(0xffffffffu, mx1, 2));

    float s0 = 0.0f, s1 = 0.0f;
    uint32_t pk[8][2];
#pragma unroll
    for (int nt = 0; nt < 7; nt++) {
        float* a = a7[nt];
        a[0] = __expf(a[0] - mx0);
        a[1] = __expf(a[1] - mx0);
        a[2] = __expf(a[2] - mx1);
        a[3] = __expf(a[3] - mx1);
        s0 += a[0] + a[1];
        s1 += a[2] + a[3];
        pk[nt][0] = packbf(a[0], a[1]);
        pk[nt][1] = packbf(a[2], a[3]);
    }
    pk[7][0] = 0u; pk[7][1] = 0u;
    s0 += __shfl_xor_sync(0xffffffffu, s0, 1);
    s0 += __shfl_xor_sync(0xffffffffu, s0, 2);
    s1 += __shfl_xor_sync(0xffffffffu, s1, 1);
    s1 += __shfl_xor_sync(0xffffffffu, s1, 2);

    float pv[4][4];
#pragma unroll
    for (int nt = 0; nt < 4; nt++)
#pragma unroll
        for (int c = 0; c < 4; c++) pv[nt][c] = 0.0f;

    const uint32_t vbase = qsu + (uint32_t)(wi * 49 + l15) * (QSTR * 2) + 128 + lhi * 16;

#pragma unroll
    for (int kc = 0; kc < 4; kc++) {
        uint32_t pa[4] = { pk[2 * kc][0], pk[2 * kc][1], pk[2 * kc + 1][0], pk[2 * kc + 1][1] };
        uint32_t vq[2][4];
#pragma unroll
        for (int pr = 0; pr < 2; pr++)
            ldsm4t(vq[pr], vbase + kc * 16 * (QSTR * 2) + pr * 32);
#pragma unroll
        for (int pr = 0; pr < 2; pr++) {
            mma_bf16(pv[2 * pr + 0], pa, &vq[pr][0]);
            mma_bf16(pv[2 * pr + 1], pa, &vq[pr][2]);
        }
    }

    const float inv0 = 1.0f / s0;
    const float inv1 = 1.0f / s1;
    const int rr0 = mq + g;
    if (rr0 < 49) {
        __nv_bfloat16* ob = ao + (size_t)(R0 + wi * 49 + rr0) * 192 + h * 32;
#pragma unroll
        for (int nt = 0; nt < 4; nt++)
            *(uint32_t*)&ob[nt * 8 + 2 * tin] = packbf(pv[nt][0] * inv0, pv[nt][1] * inv0);
    }
    if (rr0 + 8 < 49) {
        __nv_bfloat16* ob = ao + (size_t)(R0 + wi * 49 + rr0 + 8) * 192 + h * 32;
#pragma unroll
        for (int nt = 0; nt < 4; nt++)
            *(uint32_t*)&ob[nt * 8 + 2 * tin] = packbf(pv[nt][2] * inv1, pv[nt][3] * inv1);
    }
}

// ---------------------------------------------------------------------------
// bf16 GEMM, BN=96 (R9 version) — used only for proj (EPI 3).
// ---------------------------------------------------------------------------
#define BM 128
#define BN 96
#define BK 16
#define STG 4
#define AROW 24

template <int EPI>
__global__ __launch_bounds__(256, 2)
void bgemm(const __nv_bfloat16* __restrict__ A, const __nv_bfloat16* __restrict__ W,
           const float* __restrict__ bias, void* __restrict__ outp,
           const float* __restrict__ res, int N, int K) {
    __shared__ __align__(16) __nv_bfloat16 As[STG][BM * AROW];
    __shared__ __align__(16) __nv_bfloat16 Ws[STG][BN * AROW];

    const int tid  = threadIdx.x;
    const int wid  = tid >> 5;
    const int lane = tid & 31;
    const int g    = lane >> 2;
    const int tin  = lane & 3;
    const int wm   = (wid & 3) * 32;
    const int wn   = (wid >> 2) * 48;
    const int row0 = blockIdx.y * BM;
    const int col0 = blockIdx.x * BN;

    const int arow = tid >> 1, achk = tid & 1;
    const bool bld = tid < 192;
    const int brow = bld ? (tid >> 1) : 0;
    const int bchk = tid & 1;

    const __nv_bfloat16* Ag = A + (size_t)(row0 + arow) * K + achk * 8;
    const __nv_bfloat16* Wg = W + (size_t)(col0 + brow) * K + bchk * 8;
    const uint32_t asb = smem_u32(As) + (arow * AROW + achk * 8) * 2;
    const uint32_t wsb = smem_u32(Ws) + (brow * AROW + bchk * 8) * 2;
    const uint32_t ASZ = BM * AROW * 2;
    const uint32_t WSZ = BN * AROW * 2;

    const int T = K / BK;
#pragma unroll
    for (int s = 0; s < STG - 1; s++) {
        cp_async16(asb + s * ASZ, Ag + s * BK);
        if (bld) cp_async16(wsb + s * WSZ, Wg + s * BK);
        CP_COMMIT();
    }

    float acc[2][6][4];
#pragma unroll
    for (int i = 0; i < 2; i++)
#pragma unroll
        for (int j = 0; j < 6; j++)
#pragma unroll
            for (int l = 0; l < 4; l++) acc[i][j][l] = 0.0f;

    const uint32_t albase = smem_u32(As) + ((wm + (lane & 15)) * AROW) * 2 + (lane >> 4) * 16;
    const uint32_t wbbase = smem_u32(Ws)
                          + (uint32_t)(wn + ((lane >> 4) & 1) * 8 + (lane & 7)) * (AROW * 2)
                          + ((lane >> 3) & 1) * 16;

    for (int t = 0; t < T; t++) {
        CP_WAIT(STG - 2);
        __syncthreads();
        const int tn = t + STG - 1;
        if (tn < T) {
            const int s = tn % STG;
            cp_async16(asb + s * ASZ, Ag + tn * BK);
            if (bld) cp_async16(wsb + s * WSZ, Wg + tn * BK);
        }
        CP_COMMIT();

        const int st = t % STG;
        uint32_t af[2][4];
        ldsm4(af[0], albase + st * ASZ);
        ldsm4(af[1], albase + st * ASZ + 16 * AROW * 2);

        uint32_t bq[3][4];
#pragma unroll
        for (int pr = 0; pr < 3; pr++)
            ldsm4(bq[pr], wbbase + st * WSZ + pr * 16 * (AROW * 2));

#pragma unroll
        for (int mt = 0; mt < 2; mt++)
#pragma unroll
            for (int pr = 0; pr < 3; pr++) {
                mma_bf16(acc[mt][2 * pr + 0], af[mt], &bq[pr][0]);
                mma_bf16(acc[mt][2 * pr + 1], af[mt], &bq[pr][2]);
            }
    }

    float* outf = (float*)outp;

#pragma unroll
    for (int mt = 0; mt < 2; mt++) {
        const int r0 = row0 + wm + mt * 16 + g;
        const int r1 = r0 + 8;

        const int d0 = src_index(r0);
        const int d1 = src_index(r1);
        float s0 = 0.0f, q0 = 0.0f, s1 = 0.0f, q1 = 0.0f;
#pragma unroll
        for (int nt = 0; nt < 6; nt++) {
            const int col = col0 + wn + nt * 8 + 2 * tin;
            const float2 bv = *(const float2*)&bias[col];
            float2 v0, v1;
            v0.x = acc[mt][nt][0] + bv.x;
            v0.y = acc[mt][nt][1] + bv.y;
            v1.x = acc[mt][nt][2] + bv.x;
            v1.y = acc[mt][nt][3] + bv.y;
            float2 e0 = *(const float2*)&res[(size_t)d0 * 192 + col];
            float2 e1 = *(const float2*)&res[(size_t)d1 * 192 + col];
            v0.x += e0.x; v0.y += e0.y;
            v1.x += e1.x; v1.y += e1.y;
            *(float2*)&outf[(size_t)d0 * 192 + col] = v0;
            *(float2*)&outf[(size_t)d1 * 192 + col] = v1;
            *(uint32_t*)&g_x2b[(size_t)d0 * 192 + col] = packbf(v0.x, v0.y);
            *(uint32_t*)&g_x2b[(size_t)d1 * 192 + col] = packbf(v1.x, v1.y);
            s0 += v0.x + v0.y; q0 += v0.x * v0.x + v0.y * v0.y;
            s1 += v1.x + v1.y; q1 += v1.x * v1.x + v1.y * v1.y;
        }
        s0 += __shfl_xor_sync(0xffffffffu, s0, 1);
        s0 += __shfl_xor_sync(0xffffffffu, s0, 2);
        q0 += __shfl_xor_sync(0xffffffffu, q0, 1);
        q0 += __shfl_xor_sync(0xffffffffu, q0, 2);
        s1 += __shfl_xor_sync(0xffffffffu, s1, 1);
        s1 += __shfl_xor_sync(0xffffffffu, s1, 2);
        q1 += __shfl_xor_sync(0xffffffffu, q1, 1);
        q1 += __shfl_xor_sync(0xffffffffu, q1, 2);
        if (tin == 0) {
            const int slot = blockIdx.x * 2 + (wid >> 2);
            g_pbuf[slot * NTOK + d0] = make_float2(s0, q0);
            g_pbuf[slot * NTOK + d1] = make_float2(s1, q1);
        }
    }
}

// ---------------------------------------------------------------------------
// Fused MLP: per-64-token CTA, 256 threads, 2 CTAs/SM.
//  - x2b tile resident in SMEM (stride 200 bf16, conflict-free)
//  - Phase 1: fc1 in two N=192 halves (w1 streamed, 4-stage), LN2-affine +
//    GELU epilogue -> hid SMEM tile [64][392] bf16
//  - Phase 2: fc2 (K=384), A-frags from hid tile, w2 streamed into the same
//    B stage buffers; epilogue = bias + fp32 residual + fp32 store.
// ---------------------------------------------------------------------------
#define MBM    64
#define ASTR   200                          // x2b tile row stride (bf16)
#define MOFF_B (MBM * ASTR * 2)             // 25600
#define MWSZ   (192 * AROW * 2)             // 9216
#define MOFF_H (MOFF_B + 4 * MWSZ)          // 62464
#define HSTR   392                          // hid tile row stride (bf16)
#define MLP_SMEM (MOFF_H + MBM * HSTR * 2)  // 112640

__global__ __launch_bounds__(256, 2)
void mlp_fused(const __nv_bfloat16* __restrict__ x2b,
               const float* __restrict__ b1v,
               const float* __restrict__ b2v,
               const float* __restrict__ x2,
               float* __restrict__ out) {
    extern __shared__ char smem[];
    const uint32_t sb = smem_u32(smem);
    const int tid  = threadIdx.x;
    const int warp = tid >> 5;
    const int lane = tid & 31;
    const int g    = lane >> 2;
    const int tin  = lane & 3;
    const int l15  = lane & 15;
    const int lhi  = lane >> 4;
    const int row0 = blockIdx.x * MBM;
    const int wm   = (warp & 1) * 32;
    const int wn   = (warp >> 1) * 48;

    // ---- resident A (x2b) load: 64 x 192 bf16, 1536 16B-chunks ----
#pragma unroll
    for (int i = 0; i < 6; i++) {
        int idx = tid + i * 256;
        int r = idx / 24, c = idx % 24;
        cp_async16(sb + (r * ASTR + c * 8) * 2,
                   x2b + (size_t)(row0 + r) * 192 + c * 8);
    }

    // B stage loader assignments (192 rows x 2 chunks)
    const int brow0 = tid >> 1,         bchk0 = tid & 1;
    const int brow1 = 128 + (tid >> 1), bchk1 = tid & 1;
    const bool bld1 = tid < 128;
    const uint32_t wsb0 = sb + MOFF_B + (brow0 * AROW + bchk0 * 8) * 2;
    const uint32_t wsb1 = sb + MOFF_B + (brow1 * AROW + bchk1 * 8) * 2;

    const uint32_t a1base = sb + (uint32_t)(wm + l15) * (ASTR * 2) + lhi * 16;
    const uint32_t wbbase = sb + MOFF_B
        + (uint32_t)(wn + ((lane >> 4) & 1) * 8 + (lane & 7)) * (AROW * 2)
        + ((lane >> 3) & 1) * 16;

    __nv_bfloat16* hid = (__nv_bfloat16*)(smem + MOFF_H);
    const uint32_t hbase = sb + MOFF_H;

    // ---------------- Phase 1: fc1, two N=192 halves ----------------
#pragma unroll 1
    for (int nh = 0; nh < 2; nh++) {
        const __nv_bfloat16* Wg0 = g_w1 + (size_t)(nh * 192 + brow0) * 192 + bchk0 * 8;
        const __nv_bfloat16* Wg1 = g_w1 + (size_t)(nh * 192 + brow1) * 192 + bchk1 * 8;
#pragma unroll
        for (int s = 0; s < 3; s++) {
            cp_async16(wsb0 + s * MWSZ, Wg0 + s * 16);
            if (bld1) cp_async16(wsb1 + s * MWSZ, Wg1 + s * 16);
            CP_COMMIT();
        }

        float acc[2][6][4];
#pragma unroll
        for (int i = 0; i < 2; i++)
#pragma unroll
            for (int j = 0; j < 6; j++)
#pragma unroll
                for (int l = 0; l < 4; l++) acc[i][j][l] = 0.0f;

        for (int t = 0; t < 12; t++) {
            CP_WAIT(2);
            __syncthreads();
            const int tn = t + 3;
            if (tn < 12) {
                const int s = tn & 3;
                cp_async16(wsb0 + s * MWSZ, Wg0 + tn * 16);
                if (bld1) cp_async16(wsb1 + s * MWSZ, Wg1 + tn * 16);
            }
            CP_COMMIT();

            const int st = t & 3;
            uint32_t af[2][4];
            ldsm4(af[0], a1base + t * 32);
            ldsm4(af[1], a1base + 16 * (ASTR * 2) + t * 32);

            uint32_t bq[3][4];
#pragma unroll
            for (int pr = 0; pr < 3; pr++)
                ldsm4(bq[pr], wbbase + st * MWSZ + pr * 16 * (AROW * 2));

#pragma unroll
            for (int mt = 0; mt < 2; mt++)
#pragma unroll
                for (int pr = 0; pr < 3; pr++) {
                    mma_bf16(acc[mt][2 * pr + 0], af[mt], &bq[pr][0]);
                    mma_bf16(acc[mt][2 * pr + 1], af[mt], &bq[pr][2]);
                }
        }

        // epilogue: LN2 affine + GELU -> hid smem
#pragma unroll
        for (int mt = 0; mt < 2; mt++) {
            const int lr = wm + mt * 16 + g;
            const int r  = row0 + lr;
            const float2 mr0 = g_mstat[r];
            const float2 mr1 = g_mstat[r + 8];
            const float A0 = mr0.y, B0 = mr0.x * mr0.y;
            const float A1 = mr1.y, B1 = mr1.x * mr1.y;
#pragma unroll
            for (int nt = 0; nt < 6; nt++) {
                const int col = nh * 192 + wn + nt * 8 + 2 * tin;
                const float2 bv = *(const float2*)&b1v[col];
                const float2 stA = g_st1[col];
                const float2 stB = g_st1[col + 1];
                float v00 = gelu_exact(A0 * acc[mt][nt][0] - B0 * stA.x + stA.y + bv.x);
                float v01 = gelu_exact(A0 * acc[mt][nt][1] - B0 * stB.x + stB.y + bv.y);
                float v10 = gelu_exact(A1 * acc[mt][nt][2] - B1 * stA.x + stA.y + bv.x);
                float v11 = gelu_exact(A1 * acc[mt][nt][3] - B1 * stB.x + stB.y + bv.y);
                *(uint32_t*)&hid[lr * HSTR + col]       = packbf(v00, v01);
                *(uint32_t*)&hid[(lr + 8) * HSTR + col] = packbf(v10, v11);
            }
        }
    }

    // ---------------- Phase 2: fc2 (K = 384) ----------------
    const __nv_bfloat16* W2g0 = g_w2 + (size_t)brow0 * 384 + bchk0 * 8;
    const __nv_bfloat16* W2g1 = g_w2 + (size_t)brow1 * 384 + bchk1 * 8;
#pragma unroll
    for (int s = 0; s < 3; s++) {
        cp_async16(wsb0 + s * MWSZ, W2g0 + s * 16);
        if (bld1) cp_async16(wsb1 + s * MWSZ, W2g1 + s * 16);
        CP_COMMIT();
    }

    float acc[2][6][4];
#pragma unroll
    for (int i = 0; i < 2; i++)
#pragma unroll
        for (int j = 0; j < 6; j++)
#pragma unroll
            for (int l = 0; l < 4; l++) acc[i][j][l] = 0.0f;

    const uint32_t h_albase = hbase + (uint32_t)(wm + l15) * (HSTR * 2) + lhi * 16;

    for (int t = 0; t < 24; t++) {
        CP_WAIT(2);
        __syncthreads();
        const int tn = t + 3;
        if (tn < 24) {
            const int s = tn & 3;
            cp_async16(wsb0 + s * MWSZ, W2g0 + tn * 16);
            if (bld1) cp_async16(wsb1 + s * MWSZ, W2g1 + tn * 16);
        }
        CP_COMMIT();

        const int st = t & 3;
        uint32_t af[2][4];
        ldsm4(af[0], h_albase + t * 32);
        ldsm4(af[1], h_albase + 16 * (HSTR * 2) + t * 32);

        uint32_t bq[3][4];
#pragma unroll
        for (int pr = 0; pr < 3; pr++)
            ldsm4(bq[pr], wbbase + st * MWSZ + pr * 16 * (AROW * 2));

#pragma unroll
        for (int mt = 0; mt < 2; mt++)
#pragma unroll
            for (int pr = 0; pr < 3; pr++) {
                mma_bf16(acc[mt][2 * pr + 0], af[mt], &bq[pr][0]);
                mma_bf16(acc[mt][2 * pr + 1], af[mt], &bq[pr][2]);
            }
    }

    // epilogue: bias + fp32 residual + fp32 store
#pragma unroll
    for (int mt = 0; mt < 2; mt++) {
        const int r0 = row0 + wm + mt * 16 + g;
        const int r1 = r0 + 8;
#pragma unroll
        for (int nt = 0; nt < 6; nt++) {
            const int col = wn + nt * 8 + 2 * tin;
            const float2 bv = *(const float2*)&b2v[col];
            float2 v0, v1;
            v0.x = acc[mt][nt][0] + bv.x;
            v0.y = acc[mt][nt][1] + bv.y;
            v1.x = acc[mt][nt][2] + bv.x;
            v1.y = acc[mt][nt][3] + bv.y;
            float2 e0 = *(const float2*)&x2[(size_t)r0 * 192 + col];
            float2 e1 = *(const float2*)&x2[(size_t)r1 * 192 + col];
            v0.x += e0.x; v0.y += e0.y;
            v1.x += e1.x; v1.y += e1.y;
            *(float2*)&out[(size_t)r0 * 192 + col] = v0;
            *(float2*)&out[(size_t)r1 * 192 + col] = v1;
        }
    }
}

// ---------------------------------------------------------------------------
// Launcher
// ---------------------------------------------------------------------------
extern "C" void kernel_launch(void* const* d_in, const int* in_sizes, int n_in,
                              void* d_out, int out_size) {
    const float* x     = (const float*)d_in[0];
    const float* ln1_g = (const float*)d_in[1];
    const float* ln1_b = (const float*)d_in[2];
    const float* ln2_g = (const float*)d_in[3];
    const float* ln2_b = (const float*)d_in[4];
    const float* w_qkv = (const float*)d_in[5];
    const float* b_qkv = (const float*)d_in[6];
    const float* w_out = (const float*)d_in[7];
    const float* b_out = (const float*)d_in[8];
    const float* w1    = (const float*)d_in[9];
    const float* b1    = (const float*)d_in[10];
    const float* w2    = (const float*)d_in[11];
    const float* b2    = (const float*)d_in[12];
    float* out = (float*)d_out;

    __nv_bfloat16 *a1, *aob, *x2b, *wo;
    float* x2;
    cudaGetSymbolAddress((void**)&a1,  g_a1);
    cudaGetSymbolAddress((void**)&aob, g_ao);
    cudaGetSymbolAddress((void**)&x2,  g_x2);
    cudaGetSymbolAddress((void**)&x2b, g_x2b);
    cudaGetSymbolAddress((void**)&wo,  g_wout);

    cudaFuncSetAttribute(attn_fused, cudaFuncAttributeMaxDynamicSharedMemorySize, FUSED_SMEM);
    cudaFuncSetAttribute(mlp_fused, cudaFuncAttributeMaxDynamicSharedMemorySize, MLP_SMEM);

    // 0) weight prep
    wcvt<<<864, 256>>>(w_qkv, w_out, w2);
    prep1<<<48, 256>>>(w1, ln2_g, ln2_b);
    // 1) LN1 + shift + window partition -> a1 (bf16, window order)
    ln1_kernel<<<NTOK / 8, 256>>>(x, ln1_g, ln1_b, a1);
    // 2) fused QKV GEMM + attention -> ao
    attn_fused<<<dim3(1024, 6), 256, FUSED_SMEM>>>(a1, b_qkv, aob);
    // 3) proj + residual + scatter -> x2 fp32 + x2b bf16 + LN2 stat partials
    bgemm<3><<<dim3(2, NTOK / BM), 256>>>(aob, wo, b_out, x2, x, 192, 192);
    // 4) finalize LN2 stats
    finstats<<<NTOK / 256, 256>>>();
    // 5) fused MLP: fc1 (LN2 folded) + GELU + fc2 + residual -> out
    mlp_fused<<<NTOK / MBM, 256, MLP_SMEM>>>(x2b, b1, b2, x2, out);
}

// round 14
// speedup vs baseline: 1.3037x; 1.0367x over previous
#include <cuda_runtime.h>
#include <cuda_bf16.h>
#include <math.h>
#include <stdint.h>

// ---------------------------------------------------------------------------
// Swin block: B=32, H=W=56, D=192, HEADS=6, DH=32, WS=7, SHIFT=3, no pad,
// no attention mask (per reference).
// R14 (= R13 resubmit; infra failed last round): R12 base minus the x2b bf16
// shadow buffer (mlp converts x2 fp32 -> bf16 during A-tile staging) and
// minus the finstats kernel (LN2 stats folded into mlp_fused's prologue).
// ---------------------------------------------------------------------------

#define NHW   3136
#define NTOK  100352
#define DIM   192

__device__ __nv_bfloat16 g_a1 [(size_t)NTOK * DIM];   // LN1 out (window order)
__device__ __nv_bfloat16 g_ao [(size_t)NTOK * DIM];   // attn out (window order)
__device__ float         g_x2 [(size_t)NTOK * DIM];   // x2 fp32 (plain order)
__device__ __nv_bfloat16 g_wqkv[576 * 192];
__device__ __nv_bfloat16 g_wout[192 * 192];
__device__ __nv_bfloat16 g_w1  [384 * 192];           // gamma2-folded
__device__ __nv_bfloat16 g_w2  [192 * 384];
__device__ float2        g_st1 [384];
__device__ float2        g_pbuf[4 * NTOK];            // per-slot (sum, sumsq)
__device__ __align__(16) __nv_bfloat16 g_zbuf[16];

__device__ __forceinline__ int src_index(int r) {
    int w = r / 49, p = r % 49;
    int b  = w >> 6;
    int wy = (w & 63) >> 3;
    int wx = w & 7;
    int py = p / 7, px = p % 7;
    int h2 = wy * 7 + py;
    int w2 = wx * 7 + px;
    int hs = h2 + 3; if (hs >= 56) hs -= 56;
    int ws = w2 + 3; if (ws >= 56) ws -= 56;
    return b * NHW + hs * 56 + ws;
}

// ---------------------------------------------------------------------------
__device__ __forceinline__ uint32_t smem_u32(const void* p) {
    uint32_t a;
    asm("{ .reg .u64 t; cvta.to.shared.u64 t, %1; cvt.u32.u64 %0, t; }" : "=r"(a) : "l"(p));
    return a;
}
__device__ __forceinline__ void cp_async16(uint32_t dst, const void* src) {
    asm volatile("cp.async.ca.shared.global [%0], [%1], 16;" :: "r"(dst), "l"(src));
}
#define CP_COMMIT()  asm volatile("cp.async.commit_group;" ::: "memory")
#define CP_WAIT(n)   asm volatile("cp.async.wait_group %0;" :: "n"(n) : "memory")

__device__ __forceinline__ void ldsm4(uint32_t* r, uint32_t addr) {
    asm volatile("ldmatrix.sync.aligned.m8n8.x4.shared.b16 {%0,%1,%2,%3}, [%4];"
        : "=r"(r[0]), "=r"(r[1]), "=r"(r[2]), "=r"(r[3]) : "r"(addr));
}
__device__ __forceinline__ void ldsm2(uint32_t* r, uint32_t addr) {
    asm volatile("ldmatrix.sync.aligned.m8n8.x2.shared.b16 {%0,%1}, [%2];"
        : "=r"(r[0]), "=r"(r[1]) : "r"(addr));
}
__device__ __forceinline__ void ldsm4t(uint32_t* r, uint32_t addr) {
    asm volatile("ldmatrix.sync.aligned.m8n8.x4.trans.shared.b16 {%0,%1,%2,%3}, [%4];"
        : "=r"(r[0]), "=r"(r[1]), "=r"(r[2]), "=r"(r[3]) : "r"(addr));
}
__device__ __forceinline__ void mma_bf16(float* c, const uint32_t* a, const uint32_t* b) {
    asm volatile(
        "mma.sync.aligned.m16n8k16.row.col.f32.bf16.bf16.f32 "
        "{%0,%1,%2,%3}, {%4,%5,%6,%7}, {%8,%9}, {%0,%1,%2,%3};"
        : "+f"(c[0]), "+f"(c[1]), "+f"(c[2]), "+f"(c[3])
        : "r"(a[0]), "r"(a[1]), "r"(a[2]), "r"(a[3]), "r"(b[0]), "r"(b[1]));
}
__device__ __forceinline__ float gelu_exact(float v) {
    return 0.5f * v * (1.0f + erff(v * 0.7071067811865476f));
}
__device__ __forceinline__ uint32_t packbf(float a, float b) {
    __nv_bfloat162 t = __floats2bfloat162_rn(a, b);
    return *(uint32_t*)&t;
}

// ---------------------------------------------------------------------------
__global__ void wcvt(const float* __restrict__ wqkv, const float* __restrict__ wout,
                     const float* __restrict__ w2) {
    int i = blockIdx.x * 256 + threadIdx.x;
    if (i < 110592)       g_wqkv[i]          = __float2bfloat16(wqkv[i]);
    else if (i < 147456)  g_wout[i - 110592] = __float2bfloat16(wout[i - 110592]);
    else                  g_w2[i - 147456]   = __float2bfloat16(w2[i - 147456]);
    if (i < 16) g_zbuf[i] = __float2bfloat16(0.0f);
}

__global__ void prep1(const float* __restrict__ w1, const float* __restrict__ g2,
                      const float* __restrict__ b2) {
    int n = blockIdx.x * 8 + (threadIdx.x >> 5);
    int lane = threadIdx.x & 31;
    float S = 0.0f, T = 0.0f;
#pragma unroll
    for (int j = 0; j < 6; j++) {
        int k = lane + 32 * j;
        float w = w1[n * 192 + k];
        __nv_bfloat16 wb = __float2bfloat16(w * g2[k]);
        g_w1[n * 192 + k] = wb;
        S += __bfloat162float(wb);
        T += b2[k] * w;
    }
#pragma unroll
    for (int o = 16; o; o >>= 1) {
        S += __shfl_xor_sync(0xffffffffu, S, o);
        T += __shfl_xor_sync(0xffffffffu, T, o);
    }
    if (lane == 0) g_st1[n] = make_float2(S, T);
}

__global__ void ln1_kernel(const float* __restrict__ x,
                           const float* __restrict__ gam,
                           const float* __restrict__ bet,
                           __nv_bfloat16* __restrict__ out) {
    int t    = blockIdx.x * 8 + (threadIdx.x >> 5);
    int lane = threadIdx.x & 31;
    const float* xr = x + (size_t)src_index(t) * DIM;

    float v[6];
#pragma unroll
    for (int i = 0; i < 6; i++) v[i] = xr[lane + 32 * i];

    float s = v[0] + v[1] + v[2] + v[3] + v[4] + v[5];
#pragma unroll
    for (int o = 16; o; o >>= 1) s += __shfl_xor_sync(0xffffffffu, s, o);
    float mean = s * (1.0f / 192.0f);

    float q = 0.0f;
#pragma unroll
    for (int i = 0; i < 6; i++) { float d = v[i] - mean; q += d * d; }
#pragma unroll
    for (int o = 16; o; o >>= 1) q += __shfl_xor_sync(0xffffffffu, q, o);
    float rstd = rsqrtf(q * (1.0f / 192.0f) + 1e-5f);

    __nv_bfloat16* orow = out + (size_t)t * DIM;
#pragma unroll
    for (int i = 0; i < 6; i++) {
        int c = lane + 32 * i;
        orow[c] = __float2bfloat16((v[i] - mean) * rstd * gam[c] + bet[c]);
    }
}

// ---------------------------------------------------------------------------
// Fused QKV-GEMM + window attention (R9 version, unchanged).
// ---------------------------------------------------------------------------
#define FBK   16
#define FSTG  4
#define FAROW 24
#define FASZ  (128 * FAROW * 2)
#define FWSZ  (96 * FAROW * 2)
#define QSTR  104
#define OFF_WS (FSTG * FASZ)
#define OFF_QS (OFF_WS + FSTG * FWSZ)
#define FUSED_SMEM (OFF_QS + 128 * QSTR * 2)  // 69632 B

__global__ __launch_bounds__(256, 2)
void attn_fused(const __nv_bfloat16* __restrict__ a1,
                const float* __restrict__ bqkv,
                __nv_bfloat16* __restrict__ ao) {
    extern __shared__ char smem[];
    const int tid  = threadIdx.x;
    const int warp = tid >> 5;
    const int lane = tid & 31;
    const int g    = lane >> 2;
    const int tin  = lane & 3;
    const int l15  = lane & 15;
    const int lhi  = lane >> 4;
    const int p    = blockIdx.x;
    const int h    = blockIdx.y;
    const int R0   = p * 98;

    const int wm = (warp & 3) * 32;
    const int wn = (warp >> 2) * 48;

    const int arow = tid >> 1, achk = tid & 1;
    const bool areal = arow < 98;
    const __nv_bfloat16* Ag = areal ? (a1 + (size_t)(R0 + arow) * 192 + achk * 8)
                                    : (const __nv_bfloat16*)g_zbuf;
    const bool bld = tid < 192;
    int brow = (tid < 192) ? (tid >> 1) : 0;
    int bchk = tid & 1;
    const int bseg = brow >> 5;
    const __nv_bfloat16* Wg = g_wqkv + (size_t)(bseg * 192 + h * 32 + (brow & 31)) * 192 + bchk * 8;

    const uint32_t sb  = smem_u32(smem);
    const uint32_t asb = sb + (arow * FAROW + achk * 8) * 2;
    const uint32_t wsb = sb + OFF_WS + (brow * FAROW + bchk * 8) * 2;

#pragma unroll
    for (int s = 0; s < FSTG - 1; s++) {
        cp_async16(asb + s * FASZ, areal ? (Ag + s * FBK) : Ag);
        if (bld) cp_async16(wsb + s * FWSZ, Wg + s * FBK);
        CP_COMMIT();
    }

    float acc[2][6][4];
#pragma unroll
    for (int i = 0; i < 2; i++)
#pragma unroll
        for (int j = 0; j < 6; j++)
#pragma unroll
            for (int l = 0; l < 4; l++) acc[i][j][l] = 0.0f;

    const uint32_t albase = sb + ((wm + l15) * FAROW) * 2 + lhi * 16;
    const uint32_t wbbase = sb + OFF_WS
                          + (uint32_t)(wn + ((lane >> 4) & 1) * 8 + (lane & 7)) * (FAROW * 2)
                          + ((lane >> 3) & 1) * 16;

    for (int t = 0; t < 12; t++) {
        CP_WAIT(FSTG - 2);
        __syncthreads();
        const int tn = t + FSTG - 1;
        if (tn < 12) {
            const int s = tn % FSTG;
            cp_async16(asb + s * FASZ, areal ? (Ag + tn * FBK) : Ag);
            if (bld) cp_async16(wsb + s * FWSZ, Wg + tn * FBK);
        }
        CP_COMMIT();

        const int st = t % FSTG;
        uint32_t af[2][4];
        ldsm4(af[0], albase + st * FASZ);
        ldsm4(af[1], albase + st * FASZ + 16 * FAROW * 2);

        uint32_t bq[3][4];
#pragma unroll
        for (int pr = 0; pr < 3; pr++)
            ldsm4(bq[pr], wbbase + st * FWSZ + pr * 16 * (FAROW * 2));

#pragma unroll
        for (int mt = 0; mt < 2; mt++)
#pragma unroll
            for (int pr = 0; pr < 3; pr++) {
                mma_bf16(acc[mt][2 * pr + 0], af[mt], &bq[pr][0]);
                mma_bf16(acc[mt][2 * pr + 1], af[mt], &bq[pr][2]);
            }
    }

    __nv_bfloat16* qs = (__nv_bfloat16*)(smem + OFF_QS);
#pragma unroll
    for (int mt = 0; mt < 2; mt++) {
        const int r0 = wm + mt * 16 + g;
#pragma unroll
        for (int nt = 0; nt < 6; nt++) {
            const int nb  = wn + nt * 8;
            const int seg = nb >> 5;
            const int bcol = seg * 192 + h * 32 + (nb & 31) + 2 * tin;
            const float2 bv = *(const float2*)&bqkv[bcol];
            const int c = nb + 2 * tin;
            *(uint32_t*)&qs[r0 * QSTR + c]       = packbf(acc[mt][nt][0] + bv.x, acc[mt][nt][1] + bv.y);
            *(uint32_t*)&qs[(r0 + 8) * QSTR + c] = packbf(acc[mt][nt][2] + bv.x, acc[mt][nt][3] + bv.y);
        }
    }
    __syncthreads();

    // ---------------- Phase 2: attention ----------------
    const int wi = warp >> 2;
    const int mq = (warp & 3) * 16;
    const int rb = wi * 49 + mq;
    const uint32_t qsu = sb + OFF_QS;

    float a7[7][4];
#pragma unroll
    for (int nt = 0; nt < 7; nt++)
#pragma unroll
        for (int c = 0; c < 4; c++) a7[nt][c] = 0.0f;

    const uint32_t kbase = qsu
        + (uint32_t)(wi * 49 + ((lane >> 4) & 1) * 8 + (lane & 7)) * (QSTR * 2)
        + 64 + ((lane >> 3) & 1) * 16;

#pragma unroll
    for (int kc = 0; kc < 2; kc++) {
        uint32_t qa[4];
        ldsm4(qa, qsu + (uint32_t)(rb + l15) * (QSTR * 2) + kc * 32 + lhi * 16);
        uint32_t kq[3][4];
#pragma unroll
        for (int pr = 0; pr < 3; pr++)
            ldsm4(kq[pr], kbase + kc * 32 + pr * 16 * (QSTR * 2));
        uint32_t k6[2];
        ldsm2(k6, qsu + (uint32_t)(wi * 49 + 48 + (lane & 7)) * (QSTR * 2)
                   + 64 + kc * 32 + ((lane >> 3) & 1) * 16);
#pragma unroll
        for (int pr = 0; pr < 3; pr++) {
            mma_bf16(a7[2 * pr + 0], qa, &kq[pr][0]);
            mma_bf16(a7[2 * pr + 1], qa, &kq[pr][2]);
        }
        mma_bf16(a7[6], qa, k6);
    }

    const float scale = 0.17677669529663687f;
    float mx0 = -1e30f, mx1 = -1e30f;
#pragma unroll
    for (int nt = 0; nt < 7; nt++) {
        int c0 = nt * 8 + 2 * tin;
        float* a = a7[nt];
        a[0] = (c0     < 49) ? a[0] * scale : -1e30f;
        a[1] = (c0 + 1 < 49) ? a[1] * scale : -1e30f;
        a[2] = (c0     < 49) ? a[2] * scale : -1e30f;
        a[3] = (c0 + 1 < 49) ? a[3] * scale : -1e30f;
        mx0 = fmaxf(mx0, fmaxf(a[0], a[1]));
        mx1 = fmaxf(mx1, fmaxf(a[2], a[3]));
    }
    mx0 = fmaxf(mx0, __shfl_xor_sync(0xffffffffu, mx0, 1));
    mx0 = fmaxf(mx0, __shfl_xor_sync(0xffffffffu, mx0, 2));
    mx1 = fmaxf(mx1, __shfl_xor_sync(0xffffffffu, mx1, 1));
    mx1 = fmaxf(mx1, __shfl_xor_sync(0xffffffffu, mx1, 2));

    float s0 = 0.0f, s1 = 0.0f;
    uint32_t pk[8][2];
#pragma unroll
    for (int nt = 0; nt < 7; nt++) {
        float* a = a7[nt];
        a[0] = __expf(a[0] - mx0);
        a[1] = __expf(a[1] - mx0);
        a[2] = __expf(a[2] - mx1);
        a[3] = __expf(a[3] - mx1);
        s0 += a[0] + a[1];
        s1 += a[2] + a[3];
        pk[nt][0] = packbf(a[0], a[1]);
        pk[nt][1] = packbf(a[2], a[3]);
    }
    pk[7][0] = 0u; pk[7][1] = 0u;
    s0 += __shfl_xor_sync(0xffffffffu, s0, 1);
    s0 += __shfl_xor_sync(0xffffffffu, s0, 2);
    s1 += __shfl_xor_sync(0xffffffffu, s1, 1);
    s1 += __shfl_xor_sync(0xffffffffu, s1, 2);

    float pv[4][4];
#pragma unroll
    for (int nt = 0; nt < 4; nt++)
#pragma unroll
        for (int c = 0; c < 4; c++) pv[nt][c] = 0.0f;

    const uint32_t vbase = qsu + (uint32_t)(wi * 49 + l15) * (QSTR * 2) + 128 + lhi * 16;

#pragma unroll
    for (int kc = 0; kc < 4; kc++) {
        uint32_t pa[4] = { pk[2 * kc][0], pk[2 * kc][1], pk[2 * kc + 1][0], pk[2 * kc + 1][1] };
        uint32_t vq[2][4];
#pragma unroll
        for (int pr = 0; pr < 2; pr++)
            ldsm4t(vq[pr], vbase + kc * 16 * (QSTR * 2) + pr * 32);
#pragma unroll
        for (int pr = 0; pr < 2; pr++) {
            mma_bf16(pv[2 * pr + 0], pa, &vq[pr][0]);
            mma_bf16(pv[2 * pr + 1], pa, &vq[pr][2]);
        }
    }

    const float inv0 = 1.0f / s0;
    const float inv1 = 1.0f / s1;
    const int rr0 = mq + g;
    if (rr0 < 49) {
        __nv_bfloat16* ob = ao + (size_t)(R0 + wi * 49 + rr0) * 192 + h * 32;
#pragma unroll
        for (int nt = 0; nt < 4; nt++)
            *(uint32_t*)&ob[nt * 8 + 2 * tin] = packbf(pv[nt][0] * inv0, pv[nt][1] * inv0);
    }
    if (rr0 + 8 < 49) {
        __nv_bfloat16* ob = ao + (size_t)(R0 + wi * 49 + rr0 + 8) * 192 + h * 32;
#pragma unroll
        for (int nt = 0; nt < 4; nt++)
            *(uint32_t*)&ob[nt * 8 + 2 * tin] = packbf(pv[nt][2] * inv1, pv[nt][3] * inv1);
    }
}

// ---------------------------------------------------------------------------
// Proj GEMM (BN=96): EPI = residual scatter + LN2 stat partials.
// ---------------------------------------------------------------------------
#define BM 128
#define BN 96
#define BK 16
#define STG 4
#define AROW 24

__global__ __launch_bounds__(256, 2)
void proj_gemm(const __nv_bfloat16* __restrict__ A, const __nv_bfloat16* __restrict__ W,
               const float* __restrict__ bias, float* __restrict__ outf,
               const float* __restrict__ res, int N, int K) {
    __shared__ __align__(16) __nv_bfloat16 As[STG][BM * AROW];
    __shared__ __align__(16) __nv_bfloat16 Ws[STG][BN * AROW];

    const int tid  = threadIdx.x;
    const int wid  = tid >> 5;
    const int lane = tid & 31;
    const int g    = lane >> 2;
    const int tin  = lane & 3;
    const int wm   = (wid & 3) * 32;
    const int wn   = (wid >> 2) * 48;
    const int row0 = blockIdx.y * BM;
    const int col0 = blockIdx.x * BN;

    const int arow = tid >> 1, achk = tid & 1;
    const bool bld = tid < 192;
    const int brow = bld ? (tid >> 1) : 0;
    const int bchk = tid & 1;

    const __nv_bfloat16* Ag = A + (size_t)(row0 + arow) * K + achk * 8;
    const __nv_bfloat16* Wg = W + (size_t)(col0 + brow) * K + bchk * 8;
    const uint32_t asb = smem_u32(As) + (arow * AROW + achk * 8) * 2;
    const uint32_t wsb = smem_u32(Ws) + (brow * AROW + bchk * 8) * 2;
    const uint32_t ASZ = BM * AROW * 2;
    const uint32_t WSZ = BN * AROW * 2;

    const int T = K / BK;
#pragma unroll
    for (int s = 0; s < STG - 1; s++) {
        cp_async16(asb + s * ASZ, Ag + s * BK);
        if (bld) cp_async16(wsb + s * WSZ, Wg + s * BK);
        CP_COMMIT();
    }

    float acc[2][6][4];
#pragma unroll
    for (int i = 0; i < 2; i++)
#pragma unroll
        for (int j = 0; j < 6; j++)
#pragma unroll
            for (int l = 0; l < 4; l++) acc[i][j][l] = 0.0f;

    const uint32_t albase = smem_u32(As) + ((wm + (lane & 15)) * AROW) * 2 + (lane >> 4) * 16;
    const uint32_t wbbase = smem_u32(Ws)
                          + (uint32_t)(wn + ((lane >> 4) & 1) * 8 + (lane & 7)) * (AROW * 2)
                          + ((lane >> 3) & 1) * 16;

    for (int t = 0; t < T; t++) {
        CP_WAIT(STG - 2);
        __syncthreads();
        const int tn = t + STG - 1;
        if (tn < T) {
            const int s = tn % STG;
            cp_async16(asb + s * ASZ, Ag + tn * BK);
            if (bld) cp_async16(wsb + s * WSZ, Wg + tn * BK);
        }
        CP_COMMIT();

        const int st = t % STG;
        uint32_t af[2][4];
        ldsm4(af[0], albase + st * ASZ);
        ldsm4(af[1], albase + st * ASZ + 16 * AROW * 2);

        uint32_t bq[3][4];
#pragma unroll
        for (int pr = 0; pr < 3; pr++)
            ldsm4(bq[pr], wbbase + st * WSZ + pr * 16 * (AROW * 2));

#pragma unroll
        for (int mt = 0; mt < 2; mt++)
#pragma unroll
            for (int pr = 0; pr < 3; pr++) {
                mma_bf16(acc[mt][2 * pr + 0], af[mt], &bq[pr][0]);
                mma_bf16(acc[mt][2 * pr + 1], af[mt], &bq[pr][2]);
            }
    }

#pragma unroll
    for (int mt = 0; mt < 2; mt++) {
        const int r0 = row0 + wm + mt * 16 + g;
        const int r1 = r0 + 8;

        const int d0 = src_index(r0);
        const int d1 = src_index(r1);
        float s0 = 0.0f, q0 = 0.0f, s1 = 0.0f, q1 = 0.0f;
#pragma unroll
        for (int nt = 0; nt < 6; nt++) {
            const int col = col0 + wn + nt * 8 + 2 * tin;
            const float2 bv = *(const float2*)&bias[col];
            float2 v0, v1;
            v0.x = acc[mt][nt][0] + bv.x;
            v0.y = acc[mt][nt][1] + bv.y;
            v1.x = acc[mt][nt][2] + bv.x;
            v1.y = acc[mt][nt][3] + bv.y;
            float2 e0 = *(const float2*)&res[(size_t)d0 * 192 + col];
            float2 e1 = *(const float2*)&res[(size_t)d1 * 192 + col];
            v0.x += e0.x; v0.y += e0.y;
            v1.x += e1.x; v1.y += e1.y;
            *(float2*)&outf[(size_t)d0 * 192 + col] = v0;
            *(float2*)&outf[(size_t)d1 * 192 + col] = v1;
            s0 += v0.x + v0.y; q0 += v0.x * v0.x + v0.y * v0.y;
            s1 += v1.x + v1.y; q1 += v1.x * v1.x + v1.y * v1.y;
        }
        s0 += __shfl_xor_sync(0xffffffffu, s0, 1);
        s0 += __shfl_xor_sync(0xffffffffu, s0, 2);
        q0 += __shfl_xor_sync(0xffffffffu, q0, 1);
        q0 += __shfl_xor_sync(0xffffffffu, q0, 2);
        s1 += __shfl_xor_sync(0xffffffffu, s1, 1);
        s1 += __shfl_xor_sync(0xffffffffu, s1, 2);
        q1 += __shfl_xor_sync(0xffffffffu, q1, 1);
        q1 += __shfl_xor_sync(0xffffffffu, q1, 2);
        if (tin == 0) {
            const int slot = blockIdx.x * 2 + (wid >> 2);
            g_pbuf[slot * NTOK + d0] = make_float2(s0, q0);
            g_pbuf[slot * NTOK + d1] = make_float2(s1, q1);
        }
    }
}

// ---------------------------------------------------------------------------
// Fused MLP: per-64-token CTA, 256 threads, 2 CTAs/SM.
//  - prologue: LN2 stats from g_pbuf -> smem; x2 fp32 loaded, converted to
//    bf16, staged into resident A tile (stride 200)
//  - Phase 1: fc1 in two N=192 halves, LN2-affine + GELU -> hid smem tile
//  - Phase 2: fc2 (K=384) from hid tile; bias + fp32 residual + fp32 store.
// ---------------------------------------------------------------------------
#define MBM    64
#define ASTR   200                          // x2 tile row stride (bf16)
#define MOFF_B (MBM * ASTR * 2)             // 25600
#define MWSZ   (192 * AROW * 2)             // 9216
#define MOFF_H (MOFF_B + 4 * MWSZ)          // 62464
#define HSTR   392                          // hid tile row stride (bf16)
#define MOFF_ST (MOFF_H + MBM * HSTR * 2)   // 112640
#define MLP_SMEM (MOFF_ST + MBM * 8)        // 113152

__global__ __launch_bounds__(256, 2)
void mlp_fused(const float* __restrict__ x2,
               const float* __restrict__ b1v,
               const float* __restrict__ b2v,
               float* __restrict__ out) {
    extern __shared__ char smem[];
    const uint32_t sb = smem_u32(smem);
    const int tid  = threadIdx.x;
    const int warp = tid >> 5;
    const int lane = tid & 31;
    const int g    = lane >> 2;
    const int tin  = lane & 3;
    const int l15  = lane & 15;
    const int lhi  = lane >> 4;
    const int row0 = blockIdx.x * MBM;
    const int wm   = (warp & 1) * 32;
    const int wn   = (warp >> 1) * 48;

    __nv_bfloat16* At  = (__nv_bfloat16*)smem;
    __nv_bfloat16* hid = (__nv_bfloat16*)(smem + MOFF_H);
    float2* mstat_s    = (float2*)(smem + MOFF_ST);

    // ---- prologue: LN2 stats for the 64 tokens ----
    if (tid < MBM) {
        const int r = row0 + tid;
        float s = 0.0f, q = 0.0f;
#pragma unroll
        for (int k = 0; k < 4; k++) {
            float2 pp = g_pbuf[k * NTOK + r];
            s += pp.x; q += pp.y;
        }
        float mean = s * (1.0f / 192.0f);
        float var  = q * (1.0f / 192.0f) - mean * mean;
        mstat_s[tid] = make_float2(mean, rsqrtf(var + 1e-5f));
    }

    // ---- prologue: A tile load fp32 -> bf16 (64 x 192 = 3072 float4 chunks) ----
#pragma unroll
    for (int i = 0; i < 12; i++) {
        int idx = tid + i * 256;
        int r = idx / 48, c4 = idx % 48;
        float4 v = *(const float4*)(x2 + (size_t)(row0 + r) * 192 + c4 * 4);
        *(uint32_t*)&At[r * ASTR + c4 * 4]     = packbf(v.x, v.y);
        *(uint32_t*)&At[r * ASTR + c4 * 4 + 2] = packbf(v.z, v.w);
    }

    // B stage loader assignments (192 rows x 2 chunks)
    const int brow0 = tid >> 1,         bchk0 = tid & 1;
    const int brow1 = 128 + (tid >> 1), bchk1 = tid & 1;
    const bool bld1 = tid < 128;
    const uint32_t wsb0 = sb + MOFF_B + (brow0 * AROW + bchk0 * 8) * 2;
    const uint32_t wsb1 = sb + MOFF_B + (brow1 * AROW + bchk1 * 8) * 2;

    const uint32_t a1base = sb + (uint32_t)(wm + l15) * (ASTR * 2) + lhi * 16;
    const uint32_t wbbase = sb + MOFF_B
        + (uint32_t)(wn + ((lane >> 4) & 1) * 8 + (lane & 7)) * (AROW * 2)
        + ((lane >> 3) & 1) * 16;
    const uint32_t hbase = sb + MOFF_H;

    // ---------------- Phase 1: fc1, two N=192 halves ----------------
#pragma unroll 1
    for (int nh = 0; nh < 2; nh++) {
        const __nv_bfloat16* Wg0 = g_w1 + (size_t)(nh * 192 + brow0) * 192 + bchk0 * 8;
        const __nv_bfloat16* Wg1 = g_w1 + (size_t)(nh * 192 + brow1) * 192 + bchk1 * 8;
#pragma unroll
        for (int s = 0; s < 3; s++) {
            cp_async16(wsb0 + s * MWSZ, Wg0 + s * 16);
            if (bld1) cp_async16(wsb1 + s * MWSZ, Wg1 + s * 16);
            CP_COMMIT();
        }

        float acc[2][6][4];
#pragma unroll
        for (int i = 0; i < 2; i++)
#pragma unroll
            for (int j = 0; j < 6; j++)
#pragma unroll
                for (int l = 0; l < 4; l++) acc[i][j][l] = 0.0f;

        for (int t = 0; t < 12; t++) {
            CP_WAIT(2);
            __syncthreads();
            const int tn = t + 3;
            if (tn < 12) {
                const int s = tn & 3;
                cp_async16(wsb0 + s * MWSZ, Wg0 + tn * 16);
                if (bld1) cp_async16(wsb1 + s * MWSZ, Wg1 + tn * 16);
            }
            CP_COMMIT();

            const int st = t & 3;
            uint32_t af[2][4];
            ldsm4(af[0], a1base + t * 32);
            ldsm4(af[1], a1base + 16 * (ASTR * 2) + t * 32);

            uint32_t bq[3][4];
#pragma unroll
            for (int pr = 0; pr < 3; pr++)
                ldsm4(bq[pr], wbbase + st * MWSZ + pr * 16 * (AROW * 2));

#pragma unroll
            for (int mt = 0; mt < 2; mt++)
#pragma unroll
                for (int pr = 0; pr < 3; pr++) {
                    mma_bf16(acc[mt][2 * pr + 0], af[mt], &bq[pr][0]);
                    mma_bf16(acc[mt][2 * pr + 1], af[mt], &bq[pr][2]);
                }
        }

        // epilogue: LN2 affine + GELU -> hid smem
#pragma unroll
        for (int mt = 0; mt < 2; mt++) {
            const int lr = wm + mt * 16 + g;
            const float2 mr0 = mstat_s[lr];
            const float2 mr1 = mstat_s[lr + 8];
            const float A0 = mr0.y, B0 = mr0.x * mr0.y;
            const float A1 = mr1.y, B1 = mr1.x * mr1.y;
#pragma unroll
            for (int nt = 0; nt < 6; nt++) {
                const int col = nh * 192 + wn + nt * 8 + 2 * tin;
                const float2 bv = *(const float2*)&b1v[col];
                const float2 stA = g_st1[col];
                const float2 stB = g_st1[col + 1];
                float v00 = gelu_exact(A0 * acc[mt][nt][0] - B0 * stA.x + stA.y + bv.x);
                float v01 = gelu_exact(A0 * acc[mt][nt][1] - B0 * stB.x + stB.y + bv.y);
                float v10 = gelu_exact(A1 * acc[mt][nt][2] - B1 * stA.x + stA.y + bv.x);
                float v11 = gelu_exact(A1 * acc[mt][nt][3] - B1 * stB.x + stB.y + bv.y);
                *(uint32_t*)&hid[lr * HSTR + col]       = packbf(v00, v01);
                *(uint32_t*)&hid[(lr + 8) * HSTR + col] = packbf(v10, v11);
            }
        }
    }

    // ---------------- Phase 2: fc2 (K = 384) ----------------
    const __nv_bfloat16* W2g0 = g_w2 + (size_t)brow0 * 384 + bchk0 * 8;
    const __nv_bfloat16* W2g1 = g_w2 + (size_t)brow1 * 384 + bchk1 * 8;
#pragma unroll
    for (int s = 0; s < 3; s++) {
        cp_async16(wsb0 + s * MWSZ, W2g0 + s * 16);
        if (bld1) cp_async16(wsb1 + s * MWSZ, W2g1 + s * 16);
        CP_COMMIT();
    }

    float acc[2][6][4];
#pragma unroll
    for (int i = 0; i < 2; i++)
#pragma unroll
        for (int j = 0; j < 6; j++)
#pragma unroll
            for (int l = 0; l < 4; l++) acc[i][j][l] = 0.0f;

    const uint32_t h_albase = hbase + (uint32_t)(wm + l15) * (HSTR * 2) + lhi * 16;

    for (int t = 0; t < 24; t++) {
        CP_WAIT(2);
        __syncthreads();
        const int tn = t + 3;
        if (tn < 24) {
            const int s = tn & 3;
            cp_async16(wsb0 + s * MWSZ, W2g0 + tn * 16);
            if (bld1) cp_async16(wsb1 + s * MWSZ, W2g1 + tn * 16);
        }
        CP_COMMIT();

        const int st = t & 3;
        uint32_t af[2][4];
        ldsm4(af[0], h_albase + t * 32);
        ldsm4(af[1], h_albase + 16 * (HSTR * 2) + t * 32);

        uint32_t bq[3][4];
#pragma unroll
        for (int pr = 0; pr < 3; pr++)
            ldsm4(bq[pr], wbbase + st * MWSZ + pr * 16 * (AROW * 2));

#pragma unroll
        for (int mt = 0; mt < 2; mt++)
#pragma unroll
            for (int pr = 0; pr < 3; pr++) {
                mma_bf16(acc[mt][2 * pr + 0], af[mt], &bq[pr][0]);
                mma_bf16(acc[mt][2 * pr + 1], af[mt], &bq[pr][2]);
            }
    }

    // epilogue: bias + fp32 residual + fp32 store
#pragma unroll
    for (int mt = 0; mt < 2; mt++) {
        const int r0 = row0 + wm + mt * 16 + g;
        const int r1 = r0 + 8;
#pragma unroll
        for (int nt = 0; nt < 6; nt++) {
            const int col = wn + nt * 8 + 2 * tin;
            const float2 bv = *(const float2*)&b2v[col];
            float2 v0, v1;
            v0.x = acc[mt][nt][0] + bv.x;
            v0.y = acc[mt][nt][1] + bv.y;
            v1.x = acc[mt][nt][2] + bv.x;
            v1.y = acc[mt][nt][3] + bv.y;
            float2 e0 = *(const float2*)&x2[(size_t)r0 * 192 + col];
            float2 e1 = *(const float2*)&x2[(size_t)r1 * 192 + col];
            v0.x += e0.x; v0.y += e0.y;
            v1.x += e1.x; v1.y += e1.y;
            *(float2*)&out[(size_t)r0 * 192 + col] = v0;
            *(float2*)&out[(size_t)r1 * 192 + col] = v1;
        }
    }
}

// ---------------------------------------------------------------------------
// Launcher
// ---------------------------------------------------------------------------
extern "C" void kernel_launch(void* const* d_in, const int* in_sizes, int n_in,
                              void* d_out, int out_size) {
    const float* x     = (const float*)d_in[0];
    const float* ln1_g = (const float*)d_in[1];
    const float* ln1_b = (const float*)d_in[2];
    const float* ln2_g = (const float*)d_in[3];
    const float* ln2_b = (const float*)d_in[4];
    const float* w_qkv = (const float*)d_in[5];
    const float* b_qkv = (const float*)d_in[6];
    const float* w_out = (const float*)d_in[7];
    const float* b_out = (const float*)d_in[8];
    const float* w1    = (const float*)d_in[9];
    const float* b1    = (const float*)d_in[10];
    const float* w2    = (const float*)d_in[11];
    const float* b2    = (const float*)d_in[12];
    float* out = (float*)d_out;

    __nv_bfloat16 *a1, *aob, *wo;
    float* x2;
    cudaGetSymbolAddress((void**)&a1,  g_a1);
    cudaGetSymbolAddress((void**)&aob, g_ao);
    cudaGetSymbolAddress((void**)&x2,  g_x2);
    cudaGetSymbolAddress((void**)&wo,  g_wout);

    cudaFuncSetAttribute(attn_fused, cudaFuncAttributeMaxDynamicSharedMemorySize, FUSED_SMEM);
    cudaFuncSetAttribute(mlp_fused, cudaFuncAttributeMaxDynamicSharedMemorySize, MLP_SMEM);

    // 0) weight prep
    wcvt<<<864, 256>>>(w_qkv, w_out, w2);
    prep1<<<48, 256>>>(w1, ln2_g, ln2_b);
    // 1) LN1 + shift + window partition -> a1 (bf16, window order)
    ln1_kernel<<<NTOK / 8, 256>>>(x, ln1_g, ln1_b, a1);
    // 2) fused QKV GEMM + attention -> ao
    attn_fused<<<dim3(1024, 6), 256, FUSED_SMEM>>>(a1, b_qkv, aob);
    // 3) proj + residual + scatter -> x2 fp32 + LN2 stat partials
    proj_gemm<<<dim3(2, NTOK / BM), 256>>>(aob, wo, b_out, x2, x, 192, 192);
    // 4) fused MLP (LN2 stats + fc1 + GELU + fc2 + residual) -> out
    mlp_fused<<<NTOK / MBM, 256, MLP_SMEM>>>(x2, b1, b2, out);
}

// round 15
// speedup vs baseline: 1.3326x; 1.0222x over previous
#include <cuda_runtime.h>
#include <cuda_bf16.h>
#include <math.h>
#include <stdint.h>

// ---------------------------------------------------------------------------
// Swin block: B=32, H=W=56, D=192, HEADS=6, DH=32, WS=7, SHIFT=3, no pad,
// no attention mask (per reference).
// R15: mega-fusion: proj + residual + LN2 + fc1 + GELU + fc2 + residual in
// ONE kernel (CTA = 64 window-order tokens). x2 never hits DRAM (bf16 copy
// in smem for fc1; fp32 residual kept thread-local between the proj and fc2
// epilogues, which share the same fragment ownership).
// ---------------------------------------------------------------------------

#define NHW   3136
#define NTOK  100352
#define DIM   192

__device__ __nv_bfloat16 g_a1 [(size_t)NTOK * DIM];   // LN1 out (window order)
__device__ __nv_bfloat16 g_ao [(size_t)NTOK * DIM];   // attn out (window order)
__device__ __nv_bfloat16 g_wqkv[576 * 192];
__device__ __nv_bfloat16 g_wout[192 * 192];
__device__ __nv_bfloat16 g_w1  [384 * 192];           // gamma2-folded
__device__ __nv_bfloat16 g_w2  [192 * 384];
__device__ float2        g_st1 [384];
__device__ __align__(16) __nv_bfloat16 g_zbuf[16];

__device__ __forceinline__ int src_index(int r) {
    int w = r / 49, p = r % 49;
    int b  = w >> 6;
    int wy = (w & 63) >> 3;
    int wx = w & 7;
    int py = p / 7, px = p % 7;
    int h2 = wy * 7 + py;
    int w2 = wx * 7 + px;
    int hs = h2 + 3; if (hs >= 56) hs -= 56;
    int ws = w2 + 3; if (ws >= 56) ws -= 56;
    return b * NHW + hs * 56 + ws;
}

// ---------------------------------------------------------------------------
__device__ __forceinline__ uint32_t smem_u32(const void* p) {
    uint32_t a;
    asm("{ .reg .u64 t; cvta.to.shared.u64 t, %1; cvt.u32.u64 %0, t; }" : "=r"(a) : "l"(p));
    return a;
}
__device__ __forceinline__ void cp_async16(uint32_t dst, const void* src) {
    asm volatile("cp.async.ca.shared.global [%0], [%1], 16;" :: "r"(dst), "l"(src));
}
#define CP_COMMIT()  asm volatile("cp.async.commit_group;" ::: "memory")
#define CP_WAIT(n)   asm volatile("cp.async.wait_group %0;" :: "n"(n) : "memory")

__device__ __forceinline__ void ldsm4(uint32_t* r, uint32_t addr) {
    asm volatile("ldmatrix.sync.aligned.m8n8.x4.shared.b16 {%0,%1,%2,%3}, [%4];"
        : "=r"(r[0]), "=r"(r[1]), "=r"(r[2]), "=r"(r[3]) : "r"(addr));
}
__device__ __forceinline__ void ldsm2(uint32_t* r, uint32_t addr) {
    asm volatile("ldmatrix.sync.aligned.m8n8.x2.shared.b16 {%0,%1}, [%2];"
        : "=r"(r[0]), "=r"(r[1]) : "r"(addr));
}
__device__ __forceinline__ void ldsm4t(uint32_t* r, uint32_t addr) {
    asm volatile("ldmatrix.sync.aligned.m8n8.x4.trans.shared.b16 {%0,%1,%2,%3}, [%4];"
        : "=r"(r[0]), "=r"(r[1]), "=r"(r[2]), "=r"(r[3]) : "r"(addr));
}
__device__ __forceinline__ void mma_bf16(float* c, const uint32_t* a, const uint32_t* b) {
    asm volatile(
        "mma.sync.aligned.m16n8k16.row.col.f32.bf16.bf16.f32 "
        "{%0,%1,%2,%3}, {%4,%5,%6,%7}, {%8,%9}, {%0,%1,%2,%3};"
        : "+f"(c[0]), "+f"(c[1]), "+f"(c[2]), "+f"(c[3])
        : "r"(a[0]), "r"(a[1]), "r"(a[2]), "r"(a[3]), "r"(b[0]), "r"(b[1]));
}
__device__ __forceinline__ float gelu_exact(float v) {
    return 0.5f * v * (1.0f + erff(v * 0.7071067811865476f));
}
__device__ __forceinline__ uint32_t packbf(float a, float b) {
    __nv_bfloat162 t = __floats2bfloat162_rn(a, b);
    return *(uint32_t*)&t;
}

// ---------------------------------------------------------------------------
__global__ void wcvt(const float* __restrict__ wqkv, const float* __restrict__ wout,
                     const float* __restrict__ w2) {
    int i = blockIdx.x * 256 + threadIdx.x;
    if (i < 110592)       g_wqkv[i]          = __float2bfloat16(wqkv[i]);
    else if (i < 147456)  g_wout[i - 110592] = __float2bfloat16(wout[i - 110592]);
    else                  g_w2[i - 147456]   = __float2bfloat16(w2[i - 147456]);
    if (i < 16) g_zbuf[i] = __float2bfloat16(0.0f);
}

__global__ void prep1(const float* __restrict__ w1, const float* __restrict__ g2,
                      const float* __restrict__ b2) {
    int n = blockIdx.x * 8 + (threadIdx.x >> 5);
    int lane = threadIdx.x & 31;
    float S = 0.0f, T = 0.0f;
#pragma unroll
    for (int j = 0; j < 6; j++) {
        int k = lane + 32 * j;
        float w = w1[n * 192 + k];
        __nv_bfloat16 wb = __float2bfloat16(w * g2[k]);
        g_w1[n * 192 + k] = wb;
        S += __bfloat162float(wb);
        T += b2[k] * w;
    }
#pragma unroll
    for (int o = 16; o; o >>= 1) {
        S += __shfl_xor_sync(0xffffffffu, S, o);
        T += __shfl_xor_sync(0xffffffffu, T, o);
    }
    if (lane == 0) g_st1[n] = make_float2(S, T);
}

__global__ void ln1_kernel(const float* __restrict__ x,
                           const float* __restrict__ gam,
                           const float* __restrict__ bet,
                           __nv_bfloat16* __restrict__ out) {
    int t    = blockIdx.x * 8 + (threadIdx.x >> 5);
    int lane = threadIdx.x & 31;
    const float* xr = x + (size_t)src_index(t) * DIM;

    float v[6];
#pragma unroll
    for (int i = 0; i < 6; i++) v[i] = xr[lane + 32 * i];

    float s = v[0] + v[1] + v[2] + v[3] + v[4] + v[5];
#pragma unroll
    for (int o = 16; o; o >>= 1) s += __shfl_xor_sync(0xffffffffu, s, o);
    float mean = s * (1.0f / 192.0f);

    float q = 0.0f;
#pragma unroll
    for (int i = 0; i < 6; i++) { float d = v[i] - mean; q += d * d; }
#pragma unroll
    for (int o = 16; o; o >>= 1) q += __shfl_xor_sync(0xffffffffu, q, o);
    float rstd = rsqrtf(q * (1.0f / 192.0f) + 1e-5f);

    __nv_bfloat16* orow = out + (size_t)t * DIM;
#pragma unroll
    for (int i = 0; i < 6; i++) {
        int c = lane + 32 * i;
        orow[c] = __float2bfloat16((v[i] - mean) * rstd * gam[c] + bet[c]);
    }
}

// ---------------------------------------------------------------------------
// Fused QKV-GEMM + window attention (R9 version, unchanged).
// ---------------------------------------------------------------------------
#define FBK   16
#define FSTG  4
#define FAROW 24
#define FASZ  (128 * FAROW * 2)
#define FWSZ  (96 * FAROW * 2)
#define QSTR  104
#define OFF_WS (FSTG * FASZ)
#define OFF_QS (OFF_WS + FSTG * FWSZ)
#define FUSED_SMEM (OFF_QS + 128 * QSTR * 2)  // 69632 B

__global__ __launch_bounds__(256, 2)
void attn_fused(const __nv_bfloat16* __restrict__ a1,
                const float* __restrict__ bqkv,
                __nv_bfloat16* __restrict__ ao) {
    extern __shared__ char smem[];
    const int tid  = threadIdx.x;
    const int warp = tid >> 5;
    const int lane = tid & 31;
    const int g    = lane >> 2;
    const int tin  = lane & 3;
    const int l15  = lane & 15;
    const int lhi  = lane >> 4;
    const int p    = blockIdx.x;
    const int h    = blockIdx.y;
    const int R0   = p * 98;

    const int wm = (warp & 3) * 32;
    const int wn = (warp >> 2) * 48;

    const int arow = tid >> 1, achk = tid & 1;
    const bool areal = arow < 98;
    const __nv_bfloat16* Ag = areal ? (a1 + (size_t)(R0 + arow) * 192 + achk * 8)
                                    : (const __nv_bfloat16*)g_zbuf;
    const bool bld = tid < 192;
    int brow = (tid < 192) ? (tid >> 1) : 0;
    int bchk = tid & 1;
    const int bseg = brow >> 5;
    const __nv_bfloat16* Wg = g_wqkv + (size_t)(bseg * 192 + h * 32 + (brow & 31)) * 192 + bchk * 8;

    const uint32_t sb  = smem_u32(smem);
    const uint32_t asb = sb + (arow * FAROW + achk * 8) * 2;
    const uint32_t wsb = sb + OFF_WS + (brow * FAROW + bchk * 8) * 2;

#pragma unroll
    for (int s = 0; s < FSTG - 1; s++) {
        cp_async16(asb + s * FASZ, areal ? (Ag + s * FBK) : Ag);
        if (bld) cp_async16(wsb + s * FWSZ, Wg + s * FBK);
        CP_COMMIT();
    }

    float acc[2][6][4];
#pragma unroll
    for (int i = 0; i < 2; i++)
#pragma unroll
        for (int j = 0; j < 6; j++)
#pragma unroll
            for (int l = 0; l < 4; l++) acc[i][j][l] = 0.0f;

    const uint32_t albase = sb + ((wm + l15) * FAROW) * 2 + lhi * 16;
    const uint32_t wbbase = sb + OFF_WS
                          + (uint32_t)(wn + ((lane >> 4) & 1) * 8 + (lane & 7)) * (FAROW * 2)
                          + ((lane >> 3) & 1) * 16;

    for (int t = 0; t < 12; t++) {
        CP_WAIT(FSTG - 2);
        __syncthreads();
        const int tn = t + FSTG - 1;
        if (tn < 12) {
            const int s = tn % FSTG;
            cp_async16(asb + s * FASZ, areal ? (Ag + tn * FBK) : Ag);
            if (bld) cp_async16(wsb + s * FWSZ, Wg + tn * FBK);
        }
        CP_COMMIT();

        const int st = t % FSTG;
        uint32_t af[2][4];
        ldsm4(af[0], albase + st * FASZ);
        ldsm4(af[1], albase + st * FASZ + 16 * FAROW * 2);

        uint32_t bq[3][4];
#pragma unroll
        for (int pr = 0; pr < 3; pr++)
            ldsm4(bq[pr], wbbase + st * FWSZ + pr * 16 * (FAROW * 2));

#pragma unroll
        for (int mt = 0; mt < 2; mt++)
#pragma unroll
            for (int pr = 0; pr < 3; pr++) {
                mma_bf16(acc[mt][2 * pr + 0], af[mt], &bq[pr][0]);
                mma_bf16(acc[mt][2 * pr + 1], af[mt], &bq[pr][2]);
            }
    }

    __nv_bfloat16* qs = (__nv_bfloat16*)(smem + OFF_QS);
#pragma unroll
    for (int mt = 0; mt < 2; mt++) {
        const int r0 = wm + mt * 16 + g;
#pragma unroll
        for (int nt = 0; nt < 6; nt++) {
            const int nb  = wn + nt * 8;
            const int seg = nb >> 5;
            const int bcol = seg * 192 + h * 32 + (nb & 31) + 2 * tin;
            const float2 bv = *(const float2*)&bqkv[bcol];
            const int c = nb + 2 * tin;
            *(uint32_t*)&qs[r0 * QSTR + c]       = packbf(acc[mt][nt][0] + bv.x, acc[mt][nt][1] + bv.y);
            *(uint32_t*)&qs[(r0 + 8) * QSTR + c] = packbf(acc[mt][nt][2] + bv.x, acc[mt][nt][3] + bv.y);
        }
    }
    __syncthreads();

    const int wi = warp >> 2;
    const int mq = (warp & 3) * 16;
    const int rb = wi * 49 + mq;
    const uint32_t qsu = sb + OFF_QS;

    float a7[7][4];
#pragma unroll
    for (int nt = 0; nt < 7; nt++)
#pragma unroll
        for (int c = 0; c < 4; c++) a7[nt][c] = 0.0f;

    const uint32_t kbase = qsu
        + (uint32_t)(wi * 49 + ((lane >> 4) & 1) * 8 + (lane & 7)) * (QSTR * 2)
        + 64 + ((lane >> 3) & 1) * 16;

#pragma unroll
    for (int kc = 0; kc < 2; kc++) {
        uint32_t qa[4];
        ldsm4(qa, qsu + (uint32_t)(rb + l15) * (QSTR * 2) + kc * 32 + lhi * 16);
        uint32_t kq[3][4];
#pragma unroll
        for (int pr = 0; pr < 3; pr++)
            ldsm4(kq[pr], kbase + kc * 32 + pr * 16 * (QSTR * 2));
        uint32_t k6[2];
        ldsm2(k6, qsu + (uint32_t)(wi * 49 + 48 + (lane & 7)) * (QSTR * 2)
                   + 64 + kc * 32 + ((lane >> 3) & 1) * 16);
#pragma unroll
        for (int pr = 0; pr < 3; pr++) {
            mma_bf16(a7[2 * pr + 0], qa, &kq[pr][0]);
            mma_bf16(a7[2 * pr + 1], qa, &kq[pr][2]);
        }
        mma_bf16(a7[6], qa, k6);
    }

    const float scale = 0.17677669529663687f;
    float mx0 = -1e30f, mx1 = -1e30f;
#pragma unroll
    for (int nt = 0; nt < 7; nt++) {
        int c0 = nt * 8 + 2 * tin;
        float* a = a7[nt];
        a[0] = (c0     < 49) ? a[0] * scale : -1e30f;
        a[1] = (c0 + 1 < 49) ? a[1] * scale : -1e30f;
        a[2] = (c0     < 49) ? a[2] * scale : -1e30f;
        a[3] = (c0 + 1 < 49) ? a[3] * scale : -1e30f;
        mx0 = fmaxf(mx0, fmaxf(a[0], a[1]));
        mx1 = fmaxf(mx1, fmaxf(a[2], a[3]));
    }
    mx0 = fmaxf(mx0, __shfl_xor_sync(0xffffffffu, mx0, 1));
    mx0 = fmaxf(mx0, __shfl_xor_sync(0xffffffffu, mx0, 2));
    mx1 = fmaxf(mx1, __shfl_xor_sync(0xffffffffu, mx1, 1));
    mx1 = fmaxf(mx1, __shfl_xor_sync(0xffffffffu, mx1, 2));

    float s0 = 0.0f, s1 = 0.0f;
    uint32_t pk[8][2];
#pragma unroll
    for (int nt = 0; nt < 7; nt++) {
        float* a = a7[nt];
        a[0] = __expf(a[0] - mx0);
        a[1] = __expf(a[1] - mx0);
        a[2] = __expf(a[2] - mx1);
        a[3] = __expf(a[3] - mx1);
        s0 += a[0] + a[1];
        s1 += a[2] + a[3];
        pk[nt][0] = packbf(a[0], a[1]);
        pk[nt][1] = packbf(a[2], a[3]);
    }
    pk[7][0] = 0u; pk[7][1] = 0u;
    s0 += __shfl_xor_sync(0xffffffffu, s0, 1);
    s0 += __shfl_xor_sync(0xffffffffu, s0, 2);
    s1 += __shfl_xor_sync(0xffffffffu, s1, 1);
    s1 += __shfl_xor_sync(0xffffffffu, s1, 2);

    float pv[4][4];
#pragma unroll
    for (int nt = 0; nt < 4; nt++)
#pragma unroll
        for (int c = 0; c < 4; c++) pv[nt][c] = 0.0f;

    const uint32_t vbase = qsu + (uint32_t)(wi * 49 + l15) * (QSTR * 2) + 128 + lhi * 16;

#pragma unroll
    for (int kc = 0; kc < 4; kc++) {
        uint32_t pa[4] = { pk[2 * kc][0], pk[2 * kc][1], pk[2 * kc + 1][0], pk[2 * kc + 1][1] };
        uint32_t vq[2][4];
#pragma unroll
        for (int pr = 0; pr < 2; pr++)
            ldsm4t(vq[pr], vbase + kc * 16 * (QSTR * 2) + pr * 32);
#pragma unroll
        for (int pr = 0; pr < 2; pr++) {
            mma_bf16(pv[2 * pr + 0], pa, &vq[pr][0]);
            mma_bf16(pv[2 * pr + 1], pa, &vq[pr][2]);
        }
    }

    const float inv0 = 1.0f / s0;
    const float inv1 = 1.0f / s1;
    const int rr0 = mq + g;
    if (rr0 < 49) {
        __nv_bfloat16* ob = ao + (size_t)(R0 + wi * 49 + rr0) * 192 + h * 32;
#pragma unroll
        for (int nt = 0; nt < 4; nt++)
            *(uint32_t*)&ob[nt * 8 + 2 * tin] = packbf(pv[nt][0] * inv0, pv[nt][1] * inv0);
    }
    if (rr0 + 8 < 49) {
        __nv_bfloat16* ob = ao + (size_t)(R0 + wi * 49 + rr0 + 8) * 192 + h * 32;
#pragma unroll
        for (int nt = 0; nt < 4; nt++)
            *(uint32_t*)&ob[nt * 8 + 2 * tin] = packbf(pv[nt][2] * inv1, pv[nt][3] * inv1);
    }
}

// ---------------------------------------------------------------------------
// MEGA: proj + residual + LN2 stats + fc1(+affine+GELU) + fc2 + residual.
// CTA = 64 window-order rows, 256 threads, 2 CTAs/SM.
// Warp layout for ALL GEMMs: wm=(warp&1)*32, wn=(warp>>1)*48 (M=64, N=192).
// SMEM: x2b [0,25600) | At_ao [25600,51200) overlaid later by hid
//       [25600,75776) | B stages [75776,112640) | stats | mstat.
// ---------------------------------------------------------------------------
#define MBM    64
#define AROW   24
#define ASTR   200
#define HSTR   392
#define X2B_OFF 0
#define AT_OFF  25600
#define HID_OFF 25600
#define MB_OFF  75776
#define MWSZ    (192 * AROW * 2)          // 9216
#define ST_OFF  112640                    // stats 64*4 float2 = 2048
#define MS_OFF  114688                    // mstat 64 float2 = 512
#define MEGA_SMEM 115200

__global__ __launch_bounds__(256, 2)
void mega(const __nv_bfloat16* __restrict__ ao,
          const float* __restrict__ x,
          const float* __restrict__ bo,
          const float* __restrict__ b1v,
          const float* __restrict__ b2v,
          float* __restrict__ out) {
    extern __shared__ char smem[];
    const uint32_t sb = smem_u32(smem);
    const int tid  = threadIdx.x;
    const int warp = tid >> 5;
    const int lane = tid & 31;
    const int g    = lane >> 2;
    const int tin  = lane & 3;
    const int l15  = lane & 15;
    const int lhi  = lane >> 4;
    const int row0 = blockIdx.x * MBM;
    const int wm   = (warp & 1) * 32;
    const int wn   = (warp >> 1) * 48;
    const int nw   = warp >> 1;            // n-warp id 0..3

    __nv_bfloat16* x2b = (__nv_bfloat16*)smem;
    __nv_bfloat16* hid = (__nv_bfloat16*)(smem + HID_OFF);
    float2* stats  = (float2*)(smem + ST_OFF);
    float2* mstat  = (float2*)(smem + MS_OFF);

    // B stage loader assignments (192 rows x 2 chunks)
    const int brow0 = tid >> 1,         bchk0 = tid & 1;
    const int brow1 = 128 + (tid >> 1), bchk1 = tid & 1;
    const bool bld1 = tid < 128;
    const uint32_t wsb0 = sb + MB_OFF + (brow0 * AROW + bchk0 * 8) * 2;
    const uint32_t wsb1 = sb + MB_OFF + (brow1 * AROW + bchk1 * 8) * 2;

    const uint32_t wbbase = sb + MB_OFF
        + (uint32_t)(wn + ((lane >> 4) & 1) * 8 + (lane & 7)) * (AROW * 2)
        + ((lane >> 3) & 1) * 16;

    // ---- prologue: stage ao tile + first wout stages ----
    const __nv_bfloat16* Wo0 = g_wout + (size_t)brow0 * 192 + bchk0 * 8;
    const __nv_bfloat16* Wo1 = g_wout + (size_t)brow1 * 192 + bchk1 * 8;
#pragma unroll
    for (int i = 0; i < 6; i++) {          // 1536 chunks of 16B
        int idx = tid + i * 256;
        int r = idx / 24, c = idx % 24;
        cp_async16(sb + AT_OFF + (r * ASTR + c * 8) * 2,
                   ao + (size_t)(row0 + r) * 192 + c * 8);
    }
    cp_async16(wsb0, Wo0);
    if (bld1) cp_async16(wsb1, Wo1);
    CP_COMMIT();
#pragma unroll
    for (int s = 1; s < 3; s++) {
        cp_async16(wsb0 + s * MWSZ, Wo0 + s * 16);
        if (bld1) cp_async16(wsb1 + s * MWSZ, Wo1 + s * 16);
        CP_COMMIT();
    }

    // ---------------- Phase A: proj GEMM (K=192) ----------------
    float acc[2][6][4];
#pragma unroll
    for (int i = 0; i < 2; i++)
#pragma unroll
        for (int j = 0; j < 6; j++)
#pragma unroll
            for (int l = 0; l < 4; l++) acc[i][j][l] = 0.0f;

    const uint32_t atbase = sb + AT_OFF + (uint32_t)(wm + l15) * (ASTR * 2) + lhi * 16;

    for (int t = 0; t < 12; t++) {
        CP_WAIT(2);
        __syncthreads();
        const int tn = t + 3;
        if (tn < 12) {
            const int s = tn & 3;
            cp_async16(wsb0 + s * MWSZ, Wo0 + tn * 16);
            if (bld1) cp_async16(wsb1 + s * MWSZ, Wo1 + tn * 16);
        }
        CP_COMMIT();

        const int st = t & 3;
        uint32_t af[2][4];
        ldsm4(af[0], atbase + t * 32);
        ldsm4(af[1], atbase + 16 * (ASTR * 2) + t * 32);

        uint32_t bq[3][4];
#pragma unroll
        for (int pr = 0; pr < 3; pr++)
            ldsm4(bq[pr], wbbase + st * MWSZ + pr * 16 * (AROW * 2));

#pragma unroll
        for (int mt = 0; mt < 2; mt++)
#pragma unroll
            for (int pr = 0; pr < 3; pr++) {
                mma_bf16(acc[mt][2 * pr + 0], af[mt], &bq[pr][0]);
                mma_bf16(acc[mt][2 * pr + 1], af[mt], &bq[pr][2]);
            }
    }

    // ---- Phase A epilogue: + bias + gathered x residual; x2 -> smem bf16,
    //      fp32 residual kept in xf[]; LN2 partial stats -> smem. ----
    float xf[2][6][4];
#pragma unroll
    for (int mt = 0; mt < 2; mt++) {
        const int lr0 = wm + mt * 16 + g;
        const int lr1 = lr0 + 8;
        const int d0 = src_index(row0 + lr0);
        const int d1 = src_index(row0 + lr1);
        float s0 = 0.0f, q0 = 0.0f, s1 = 0.0f, q1 = 0.0f;
#pragma unroll
        for (int nt = 0; nt < 6; nt++) {
            const int col = wn + nt * 8 + 2 * tin;
            const float2 bv = *(const float2*)&bo[col];
            float2 e0 = *(const float2*)&x[(size_t)d0 * 192 + col];
            float2 e1 = *(const float2*)&x[(size_t)d1 * 192 + col];
            float v00 = acc[mt][nt][0] + bv.x + e0.x;
            float v01 = acc[mt][nt][1] + bv.y + e0.y;
            float v10 = acc[mt][nt][2] + bv.x + e1.x;
            float v11 = acc[mt][nt][3] + bv.y + e1.y;
            xf[mt][nt][0] = v00; xf[mt][nt][1] = v01;
            xf[mt][nt][2] = v10; xf[mt][nt][3] = v11;
            *(uint32_t*)&x2b[lr0 * ASTR + col] = packbf(v00, v01);
            *(uint32_t*)&x2b[lr1 * ASTR + col] = packbf(v10, v11);
            s0 += v00 + v01; q0 += v00 * v00 + v01 * v01;
            s1 += v10 + v11; q1 += v10 * v10 + v11 * v11;
        }
        s0 += __shfl_xor_sync(0xffffffffu, s0, 1);
        s0 += __shfl_xor_sync(0xffffffffu, s0, 2);
        q0 += __shfl_xor_sync(0xffffffffu, q0, 1);
        q0 += __shfl_xor_sync(0xffffffffu, q0, 2);
        s1 += __shfl_xor_sync(0xffffffffu, s1, 1);
        s1 += __shfl_xor_sync(0xffffffffu, s1, 2);
        q1 += __shfl_xor_sync(0xffffffffu, q1, 1);
        q1 += __shfl_xor_sync(0xffffffffu, q1, 2);
        if (tin == 0) {
            stats[lr0 * 4 + nw] = make_float2(s0, q0);
            stats[lr1 * 4 + nw] = make_float2(s1, q1);
        }
    }
    __syncthreads();
    if (tid < MBM) {
        float s = 0.0f, q = 0.0f;
#pragma unroll
        for (int k = 0; k < 4; k++) {
            float2 pp = stats[tid * 4 + k];
            s += pp.x; q += pp.y;
        }
        float mean = s * (1.0f / 192.0f);
        float var  = q * (1.0f / 192.0f) - mean * mean;
        mstat[tid] = make_float2(mean, rsqrtf(var + 1e-5f));
    }

    // ---------------- Phase B: fc1, two N=192 halves ----------------
    const uint32_t x2base = sb + X2B_OFF + (uint32_t)(wm + l15) * (ASTR * 2) + lhi * 16;

#pragma unroll 1
    for (int nh = 0; nh < 2; nh++) {
        const __nv_bfloat16* Wg0 = g_w1 + (size_t)(nh * 192 + brow0) * 192 + bchk0 * 8;
        const __nv_bfloat16* Wg1 = g_w1 + (size_t)(nh * 192 + brow1) * 192 + bchk1 * 8;
#pragma unroll
        for (int s = 0; s < 3; s++) {
            cp_async16(wsb0 + s * MWSZ, Wg0 + s * 16);
            if (bld1) cp_async16(wsb1 + s * MWSZ, Wg1 + s * 16);
            CP_COMMIT();
        }

#pragma unroll
        for (int i = 0; i < 2; i++)
#pragma unroll
            for (int j = 0; j < 6; j++)
#pragma unroll
                for (int l = 0; l < 4; l++) acc[i][j][l] = 0.0f;

        for (int t = 0; t < 12; t++) {
            CP_WAIT(2);
            __syncthreads();
            const int tn = t + 3;
            if (tn < 12) {
                const int s = tn & 3;
                cp_async16(wsb0 + s * MWSZ, Wg0 + tn * 16);
                if (bld1) cp_async16(wsb1 + s * MWSZ, Wg1 + tn * 16);
            }
            CP_COMMIT();

            const int st = t & 3;
            uint32_t af[2][4];
            ldsm4(af[0], x2base + t * 32);
            ldsm4(af[1], x2base + 16 * (ASTR * 2) + t * 32);

            uint32_t bq[3][4];
#pragma unroll
            for (int pr = 0; pr < 3; pr++)
                ldsm4(bq[pr], wbbase + st * MWSZ + pr * 16 * (AROW * 2));

#pragma unroll
            for (int mt = 0; mt < 2; mt++)
#pragma unroll
                for (int pr = 0; pr < 3; pr++) {
                    mma_bf16(acc[mt][2 * pr + 0], af[mt], &bq[pr][0]);
                    mma_bf16(acc[mt][2 * pr + 1], af[mt], &bq[pr][2]);
                }
        }

        // epilogue: LN2 affine + GELU -> hid smem
#pragma unroll
        for (int mt = 0; mt < 2; mt++) {
            const int lr = wm + mt * 16 + g;
            const float2 mr0 = mstat[lr];
            const float2 mr1 = mstat[lr + 8];
            const float A0 = mr0.y, B0 = mr0.x * mr0.y;
            const float A1 = mr1.y, B1 = mr1.x * mr1.y;
#pragma unroll
            for (int nt = 0; nt < 6; nt++) {
                const int col = nh * 192 + wn + nt * 8 + 2 * tin;
                const float2 bv = *(const float2*)&b1v[col];
                const float2 stA = g_st1[col];
                const float2 stB = g_st1[col + 1];
                float v00 = gelu_exact(A0 * acc[mt][nt][0] - B0 * stA.x + stA.y + bv.x);
                float v01 = gelu_exact(A0 * acc[mt][nt][1] - B0 * stB.x + stB.y + bv.y);
                float v10 = gelu_exact(A1 * acc[mt][nt][2] - B1 * stA.x + stA.y + bv.x);
                float v11 = gelu_exact(A1 * acc[mt][nt][3] - B1 * stB.x + stB.y + bv.y);
                *(uint32_t*)&hid[lr * HSTR + col]       = packbf(v00, v01);
                *(uint32_t*)&hid[(lr + 8) * HSTR + col] = packbf(v10, v11);
            }
        }
    }

    // ---------------- Phase C: fc2 (K = 384) ----------------
    const __nv_bfloat16* W2g0 = g_w2 + (size_t)brow0 * 384 + bchk0 * 8;
    const __nv_bfloat16* W2g1 = g_w2 + (size_t)brow1 * 384 + bchk1 * 8;
#pragma unroll
    for (int s = 0; s < 3; s++) {
        cp_async16(wsb0 + s * MWSZ, W2g0 + s * 16);
        if (bld1) cp_async16(wsb1 + s * MWSZ, W2g1 + s * 16);
        CP_COMMIT();
    }

#pragma unroll
    for (int i = 0; i < 2; i++)
#pragma unroll
        for (int j = 0; j < 6; j++)
#pragma unroll
            for (int l = 0; l < 4; l++) acc[i][j][l] = 0.0f;

    const uint32_t h_albase = sb + HID_OFF + (uint32_t)(wm + l15) * (HSTR * 2) + lhi * 16;

    for (int t = 0; t < 24; t++) {
        CP_WAIT(2);
        __syncthreads();
        const int tn = t + 3;
        if (tn < 24) {
            const int s = tn & 3;
            cp_async16(wsb0 + s * MWSZ, W2g0 + tn * 16);
            if (bld1) cp_async16(wsb1 + s * MWSZ, W2g1 + tn * 16);
        }
        CP_COMMIT();

        const int st = t & 3;
        uint32_t af[2][4];
        ldsm4(af[0], h_albase + t * 32);
        ldsm4(af[1], h_albase + 16 * (HSTR * 2) + t * 32);

        uint32_t bq[3][4];
#pragma unroll
        for (int pr = 0; pr < 3; pr++)
            ldsm4(bq[pr], wbbase + st * MWSZ + pr * 16 * (AROW * 2));

#pragma unroll
        for (int mt = 0; mt < 2; mt++)
#pragma unroll
            for (int pr = 0; pr < 3; pr++) {
                mma_bf16(acc[mt][2 * pr + 0], af[mt], &bq[pr][0]);
                mma_bf16(acc[mt][2 * pr + 1], af[mt], &bq[pr][2]);
            }
    }

    // epilogue: bias + thread-local fp32 residual, scattered store
#pragma unroll
    for (int mt = 0; mt < 2; mt++) {
        const int lr0 = wm + mt * 16 + g;
        const int d0 = src_index(row0 + lr0);
        const int d1 = src_index(row0 + lr0 + 8);
#pragma unroll
        for (int nt = 0; nt < 6; nt++) {
            const int col = wn + nt * 8 + 2 * tin;
            const float2 bv = *(const float2*)&b2v[col];
            float2 v0, v1;
            v0.x = acc[mt][nt][0] + bv.x + xf[mt][nt][0];
            v0.y = acc[mt][nt][1] + bv.y + xf[mt][nt][1];
            v1.x = acc[mt][nt][2] + bv.x + xf[mt][nt][2];
            v1.y = acc[mt][nt][3] + bv.y + xf[mt][nt][3];
            *(float2*)&out[(size_t)d0 * 192 + col] = v0;
            *(float2*)&out[(size_t)d1 * 192 + col] = v1;
        }
    }
}

// ---------------------------------------------------------------------------
// Launcher
// ---------------------------------------------------------------------------
extern "C" void kernel_launch(void* const* d_in, const int* in_sizes, int n_in,
                              void* d_out, int out_size) {
    const float* x     = (const float*)d_in[0];
    const float* ln1_g = (const float*)d_in[1];
    const float* ln1_b = (const float*)d_in[2];
    const float* ln2_g = (const float*)d_in[3];
    const float* ln2_b = (const float*)d_in[4];
    const float* w_qkv = (const float*)d_in[5];
    const float* b_qkv = (const float*)d_in[6];
    const float* w_out = (const float*)d_in[7];
    const float* b_out = (const float*)d_in[8];
    const float* w1    = (const float*)d_in[9];
    const float* b1    = (const float*)d_in[10];
    const float* w2    = (const float*)d_in[11];
    const float* b2    = (const float*)d_in[12];
    float* out = (float*)d_out;

    __nv_bfloat16 *a1, *aob;
    cudaGetSymbolAddress((void**)&a1,  g_a1);
    cudaGetSymbolAddress((void**)&aob, g_ao);

    cudaFuncSetAttribute(attn_fused, cudaFuncAttributeMaxDynamicSharedMemorySize, FUSED_SMEM);
    cudaFuncSetAttribute(mega, cudaFuncAttributeMaxDynamicSharedMemorySize, MEGA_SMEM);

    // 0) weight prep
    wcvt<<<864, 256>>>(w_qkv, w_out, w2);
    prep1<<<48, 256>>>(w1, ln2_g, ln2_b);
    // 1) LN1 + shift + window partition -> a1 (bf16, window order)
    ln1_kernel<<<NTOK / 8, 256>>>(x, ln1_g, ln1_b, a1);
    // 2) fused QKV GEMM + attention -> ao
    attn_fused<<<dim3(1024, 6), 256, FUSED_SMEM>>>(a1, b_qkv, aob);
    // 3) mega: proj + residual + LN2 + fc1 + GELU + fc2 + residual -> out
    mega<<<NTOK / MBM, 256, MEGA_SMEM>>>(aob, x, b_out, b1, b2, out);
}

// round 16
// speedup vs baseline: 1.3872x; 1.0409x over previous
#include <cuda_runtime.h>
#include <cuda_bf16.h>
#include <math.h>
#include <stdint.h>

// ---------------------------------------------------------------------------
// Swin block: B=32, H=W=56, D=192, HEADS=6, DH=32, WS=7, SHIFT=3, no pad,
// no attention mask (per reference).
// R16: R15 base (460.8us) + tanh-GELU (cheap, below bf16 quantization noise),
// attn phase-1 pipeline -> 6 stages consuming 2 k-tiles per sync (half the
// barriers), wcvt+prep1 merged into one launch.
// ---------------------------------------------------------------------------

#define NHW   3136
#define NTOK  100352
#define DIM   192

__device__ __nv_bfloat16 g_a1 [(size_t)NTOK * DIM];   // LN1 out (window order)
__device__ __nv_bfloat16 g_ao [(size_t)NTOK * DIM];   // attn out (window order)
__device__ __nv_bfloat16 g_wqkv[576 * 192];
__device__ __nv_bfloat16 g_wout[192 * 192];
__device__ __nv_bfloat16 g_w1  [384 * 192];           // gamma2-folded
__device__ __nv_bfloat16 g_w2  [192 * 384];
__device__ float2        g_st1 [384];
__device__ __align__(16) __nv_bfloat16 g_zbuf[16];

__device__ __forceinline__ int src_index(int r) {
    int w = r / 49, p = r % 49;
    int b  = w >> 6;
    int wy = (w & 63) >> 3;
    int wx = w & 7;
    int py = p / 7, px = p % 7;
    int h2 = wy * 7 + py;
    int w2 = wx * 7 + px;
    int hs = h2 + 3; if (hs >= 56) hs -= 56;
    int ws = w2 + 3; if (ws >= 56) ws -= 56;
    return b * NHW + hs * 56 + ws;
}

// ---------------------------------------------------------------------------
__device__ __forceinline__ uint32_t smem_u32(const void* p) {
    uint32_t a;
    asm("{ .reg .u64 t; cvta.to.shared.u64 t, %1; cvt.u32.u64 %0, t; }" : "=r"(a) : "l"(p));
    return a;
}
__device__ __forceinline__ void cp_async16(uint32_t dst, const void* src) {
    asm volatile("cp.async.ca.shared.global [%0], [%1], 16;" :: "r"(dst), "l"(src));
}
#define CP_COMMIT()  asm volatile("cp.async.commit_group;" ::: "memory")
#define CP_WAIT(n)   asm volatile("cp.async.wait_group %0;" :: "n"(n) : "memory")

__device__ __forceinline__ void ldsm4(uint32_t* r, uint32_t addr) {
    asm volatile("ldmatrix.sync.aligned.m8n8.x4.shared.b16 {%0,%1,%2,%3}, [%4];"
        : "=r"(r[0]), "=r"(r[1]), "=r"(r[2]), "=r"(r[3]) : "r"(addr));
}
__device__ __forceinline__ void ldsm2(uint32_t* r, uint32_t addr) {
    asm volatile("ldmatrix.sync.aligned.m8n8.x2.shared.b16 {%0,%1}, [%2];"
        : "=r"(r[0]), "=r"(r[1]) : "r"(addr));
}
__device__ __forceinline__ void ldsm4t(uint32_t* r, uint32_t addr) {
    asm volatile("ldmatrix.sync.aligned.m8n8.x4.trans.shared.b16 {%0,%1,%2,%3}, [%4];"
        : "=r"(r[0]), "=r"(r[1]), "=r"(r[2]), "=r"(r[3]) : "r"(addr));
}
__device__ __forceinline__ void mma_bf16(float* c, const uint32_t* a, const uint32_t* b) {
    asm volatile(
        "mma.sync.aligned.m16n8k16.row.col.f32.bf16.bf16.f32 "
        "{%0,%1,%2,%3}, {%4,%5,%6,%7}, {%8,%9}, {%0,%1,%2,%3};"
        : "+f"(c[0]), "+f"(c[1]), "+f"(c[2]), "+f"(c[3])
        : "r"(a[0]), "r"(a[1]), "r"(a[2]), "r"(a[3]), "r"(b[0]), "r"(b[1]));
}
// tanh-approx GELU: deviation from exact-erf GELU < 1e-4 for |x|<1 (fc1
// outputs ~N(0,0.28)); strictly below the bf16 quantization of hid.
__device__ __forceinline__ float gelu_fast(float v) {
    float t = v * (1.5957691216f + 0.0713548162f * v * v);
    return __fdividef(v, 1.0f + __expf(-t));
}
__device__ __forceinline__ uint32_t packbf(float a, float b) {
    __nv_bfloat162 t = __floats2bfloat162_rn(a, b);
    return *(uint32_t*)&t;
}

// ---------------------------------------------------------------------------
// Weight prep: blocks 0..863 convert wqkv/wout/w2 to bf16; blocks 864..911
// fold ln2 gamma into w1 and compute per-n (S, T).
// ---------------------------------------------------------------------------
__global__ void prep_all(const float* __restrict__ wqkv, const float* __restrict__ wout,
                         const float* __restrict__ w2,   const float* __restrict__ w1,
                         const float* __restrict__ g2,   const float* __restrict__ b2) {
    if (blockIdx.x < 864) {
        int i = blockIdx.x * 256 + threadIdx.x;
        if (i < 110592)       g_wqkv[i]          = __float2bfloat16(wqkv[i]);
        else if (i < 147456)  g_wout[i - 110592] = __float2bfloat16(wout[i - 110592]);
        else                  g_w2[i - 147456]   = __float2bfloat16(w2[i - 147456]);
        if (i < 16) g_zbuf[i] = __float2bfloat16(0.0f);
    } else {
        int n = (blockIdx.x - 864) * 8 + (threadIdx.x >> 5);
        int lane = threadIdx.x & 31;
        float S = 0.0f, T = 0.0f;
#pragma unroll
        for (int j = 0; j < 6; j++) {
            int k = lane + 32 * j;
            float w = w1[n * 192 + k];
            __nv_bfloat16 wb = __float2bfloat16(w * g2[k]);
            g_w1[n * 192 + k] = wb;
            S += __bfloat162float(wb);
            T += b2[k] * w;
        }
#pragma unroll
        for (int o = 16; o; o >>= 1) {
            S += __shfl_xor_sync(0xffffffffu, S, o);
            T += __shfl_xor_sync(0xffffffffu, T, o);
        }
        if (lane == 0) g_st1[n] = make_float2(S, T);
    }
}

__global__ void ln1_kernel(const float* __restrict__ x,
                           const float* __restrict__ gam,
                           const float* __restrict__ bet,
                           __nv_bfloat16* __restrict__ out) {
    int t    = blockIdx.x * 8 + (threadIdx.x >> 5);
    int lane = threadIdx.x & 31;
    const float* xr = x + (size_t)src_index(t) * DIM;

    float v[6];
#pragma unroll
    for (int i = 0; i < 6; i++) v[i] = xr[lane + 32 * i];

    float s = v[0] + v[1] + v[2] + v[3] + v[4] + v[5];
#pragma unroll
    for (int o = 16; o; o >>= 1) s += __shfl_xor_sync(0xffffffffu, s, o);
    float mean = s * (1.0f / 192.0f);

    float q = 0.0f;
#pragma unroll
    for (int i = 0; i < 6; i++) { float d = v[i] - mean; q += d * d; }
#pragma unroll
    for (int o = 16; o; o >>= 1) q += __shfl_xor_sync(0xffffffffu, q, o);
    float rstd = rsqrtf(q * (1.0f / 192.0f) + 1e-5f);

    __nv_bfloat16* orow = out + (size_t)t * DIM;
#pragma unroll
    for (int i = 0; i < 6; i++) {
        int c = lane + 32 * i;
        orow[c] = __float2bfloat16((v[i] - mean) * rstd * gam[c] + bet[c]);
    }
}

// ---------------------------------------------------------------------------
// Fused QKV-GEMM + window attention. R16: 6-stage pipeline, 2 k-tiles/sync.
// ---------------------------------------------------------------------------
#define FBK   16
#define FSTG  6
#define FAROW 24
#define FASZ  (128 * FAROW * 2)           // 6144
#define FWSZ  (96 * FAROW * 2)            // 4608
#define QSTR  104
#define OFF_WS (FSTG * FASZ)              // 36864
#define OFF_QS (OFF_WS + FSTG * FWSZ)     // 64512
#define FUSED_SMEM (OFF_QS + 128 * QSTR * 2)  // 91136 B

__global__ __launch_bounds__(256, 2)
void attn_fused(const __nv_bfloat16* __restrict__ a1,
                const float* __restrict__ bqkv,
                __nv_bfloat16* __restrict__ ao) {
    extern __shared__ char smem[];
    const int tid  = threadIdx.x;
    const int warp = tid >> 5;
    const int lane = tid & 31;
    const int g    = lane >> 2;
    const int tin  = lane & 3;
    const int l15  = lane & 15;
    const int lhi  = lane >> 4;
    const int p    = blockIdx.x;
    const int h    = blockIdx.y;
    const int R0   = p * 98;

    const int wm = (warp & 3) * 32;
    const int wn = (warp >> 2) * 48;

    const int arow = tid >> 1, achk = tid & 1;
    const bool areal = arow < 98;
    const __nv_bfloat16* Ag = areal ? (a1 + (size_t)(R0 + arow) * 192 + achk * 8)
                                    : (const __nv_bfloat16*)g_zbuf;
    const bool bld = tid < 192;
    int brow = (tid < 192) ? (tid >> 1) : 0;
    int bchk = tid & 1;
    const int bseg = brow >> 5;
    const __nv_bfloat16* Wg = g_wqkv + (size_t)(bseg * 192 + h * 32 + (brow & 31)) * 192 + bchk * 8;

    const uint32_t sb  = smem_u32(smem);
    const uint32_t asb = sb + (arow * FAROW + achk * 8) * 2;
    const uint32_t wsb = sb + OFF_WS + (brow * FAROW + bchk * 8) * 2;

    // prologue: stages 0..3
#pragma unroll
    for (int s = 0; s < 4; s++) {
        cp_async16(asb + s * FASZ, areal ? (Ag + s * FBK) : Ag);
        if (bld) cp_async16(wsb + s * FWSZ, Wg + s * FBK);
        CP_COMMIT();
    }

    float acc[2][6][4];
#pragma unroll
    for (int i = 0; i < 2; i++)
#pragma unroll
        for (int j = 0; j < 6; j++)
#pragma unroll
            for (int l = 0; l < 4; l++) acc[i][j][l] = 0.0f;

    const uint32_t albase = sb + ((wm + l15) * FAROW) * 2 + lhi * 16;
    const uint32_t wbbase = sb + OFF_WS
                          + (uint32_t)(wn + ((lane >> 4) & 1) * 8 + (lane & 7)) * (FAROW * 2)
                          + ((lane >> 3) & 1) * 16;

#pragma unroll
    for (int tt = 0; tt < 6; tt++) {
        const int t = tt * 2;
        if (tt < 5) { CP_WAIT(2); } else { CP_WAIT(0); }
        __syncthreads();
        if (tt < 4) {
            const int u0 = t + 4, u1 = t + 5;
            cp_async16(asb + (u0 % 6) * FASZ, areal ? (Ag + u0 * FBK) : Ag);
            if (bld) cp_async16(wsb + (u0 % 6) * FWSZ, Wg + u0 * FBK);
            CP_COMMIT();
            cp_async16(asb + (u1 % 6) * FASZ, areal ? (Ag + u1 * FBK) : Ag);
            if (bld) cp_async16(wsb + (u1 % 6) * FWSZ, Wg + u1 * FBK);
            CP_COMMIT();
        }

#pragma unroll
        for (int q = 0; q < 2; q++) {
            const int st = (t + q) % 6;
            uint32_t af[2][4];
            ldsm4(af[0], albase + st * FASZ);
            ldsm4(af[1], albase + st * FASZ + 16 * FAROW * 2);

            uint32_t bq[3][4];
#pragma unroll
            for (int pr = 0; pr < 3; pr++)
                ldsm4(bq[pr], wbbase + st * FWSZ + pr * 16 * (FAROW * 2));

#pragma unroll
            for (int mt = 0; mt < 2; mt++)
#pragma unroll
                for (int pr = 0; pr < 3; pr++) {
                    mma_bf16(acc[mt][2 * pr + 0], af[mt], &bq[pr][0]);
                    mma_bf16(acc[mt][2 * pr + 1], af[mt], &bq[pr][2]);
                }
        }
    }

    __nv_bfloat16* qs = (__nv_bfloat16*)(smem + OFF_QS);
#pragma unroll
    for (int mt = 0; mt < 2; mt++) {
        const int r0 = wm + mt * 16 + g;
#pragma unroll
        for (int nt = 0; nt < 6; nt++) {
            const int nb  = wn + nt * 8;
            const int seg = nb >> 5;
            const int bcol = seg * 192 + h * 32 + (nb & 31) + 2 * tin;
            const float2 bv = *(const float2*)&bqkv[bcol];
            const int c = nb + 2 * tin;
            *(uint32_t*)&qs[r0 * QSTR + c]       = packbf(acc[mt][nt][0] + bv.x, acc[mt][nt][1] + bv.y);
            *(uint32_t*)&qs[(r0 + 8) * QSTR + c] = packbf(acc[mt][nt][2] + bv.x, acc[mt][nt][3] + bv.y);
        }
    }
    __syncthreads();

    // ---------------- Phase 2: attention ----------------
    const int wi = warp >> 2;
    const int mq = (warp & 3) * 16;
    const int rb = wi * 49 + mq;
    const uint32_t qsu = sb + OFF_QS;

    float a7[7][4];
#pragma unroll
    for (int nt = 0; nt < 7; nt++)
#pragma unroll
        for (int c = 0; c < 4; c++) a7[nt][c] = 0.0f;

    const uint32_t kbase = qsu
        + (uint32_t)(wi * 49 + ((lane >> 4) & 1) * 8 + (lane & 7)) * (QSTR * 2)
        + 64 + ((lane >> 3) & 1) * 16;

#pragma unroll
    for (int kc = 0; kc < 2; kc++) {
        uint32_t qa[4];
        ldsm4(qa, qsu + (uint32_t)(rb + l15) * (QSTR * 2) + kc * 32 + lhi * 16);
        uint32_t kq[3][4];
#pragma unroll
        for (int pr = 0; pr < 3; pr++)
            ldsm4(kq[pr], kbase + kc * 32 + pr * 16 * (QSTR * 2));
        uint32_t k6[2];
        ldsm2(k6, qsu + (uint32_t)(wi * 49 + 48 + (lane & 7)) * (QSTR * 2)
                   + 64 + kc * 32 + ((lane >> 3) & 1) * 16);
#pragma unroll
        for (int pr = 0; pr < 3; pr++) {
            mma_bf16(a7[2 * pr + 0], qa, &kq[pr][0]);
            mma_bf16(a7[2 * pr + 1], qa, &kq[pr][2]);
        }
        mma_bf16(a7[6], qa, k6);
    }

    const float scale = 0.17677669529663687f;
    float mx0 = -1e30f, mx1 = -1e30f;
#pragma unroll
    for (int nt = 0; nt < 7; nt++) {
        int c0 = nt * 8 + 2 * tin;
        float* a = a7[nt];
        a[0] = (c0     < 49) ? a[0] * scale : -1e30f;
        a[1] = (c0 + 1 < 49) ? a[1] * scale : -1e30f;
        a[2] = (c0     < 49) ? a[2] * scale : -1e30f;
        a[3] = (c0 + 1 < 49) ? a[3] * scale : -1e30f;
        mx0 = fmaxf(mx0, fmaxf(a[0], a[1]));
        mx1 = fmaxf(mx1, fmaxf(a[2], a[3]));
    }
    mx0 = fmaxf(mx0, __shfl_xor_sync(0xffffffffu, mx0, 1));
    mx0 = fmaxf(mx0, __shfl_xor_sync(0xffffffffu, mx0, 2));
    mx1 = fmaxf(mx1, __shfl_xor_sync(0xffffffffu, mx1, 1));
    mx1 = fmaxf(mx1, __shfl_xor_sync(0xffffffffu, mx1, 2));

    float s0 = 0.0f, s1 = 0.0f;
    uint32_t pk[8][2];
#pragma unroll
    for (int nt = 0; nt < 7; nt++) {
        float* a = a7[nt];
        a[0] = __expf(a[0] - mx0);
        a[1] = __expf(a[1] - mx0);
        a[2] = __expf(a[2] - mx1);
        a[3] = __expf(a[3] - mx1);
        s0 += a[0] + a[1];
        s1 += a[2] + a[3];
        pk[nt][0] = packbf(a[0], a[1]);
        pk[nt][1] = packbf(a[2], a[3]);
    }
    pk[7][0] = 0u; pk[7][1] = 0u;
    s0 += __shfl_xor_sync(0xffffffffu, s0, 1);
    s0 += __shfl_xor_sync(0xffffffffu, s0, 2);
    s1 += __shfl_xor_sync(0xffffffffu, s1, 1);
    s1 += __shfl_xor_sync(0xffffffffu, s1, 2);

    float pv[4][4];
#pragma unroll
    for (int nt = 0; nt < 4; nt++)
#pragma unroll
        for (int c = 0; c < 4; c++) pv[nt][c] = 0.0f;

    const uint32_t vbase = qsu + (uint32_t)(wi * 49 + l15) * (QSTR * 2) + 128 + lhi * 16;

#pragma unroll
    for (int kc = 0; kc < 4; kc++) {
        uint32_t pa[4] = { pk[2 * kc][0], pk[2 * kc][1], pk[2 * kc + 1][0], pk[2 * kc + 1][1] };
        uint32_t vq[2][4];
#pragma unroll
        for (int pr = 0; pr < 2; pr++)
            ldsm4t(vq[pr], vbase + kc * 16 * (QSTR * 2) + pr * 32);
#pragma unroll
        for (int pr = 0; pr < 2; pr++) {
            mma_bf16(pv[2 * pr + 0], pa, &vq[pr][0]);
            mma_bf16(pv[2 * pr + 1], pa, &vq[pr][2]);
        }
    }

    const float inv0 = 1.0f / s0;
    const float inv1 = 1.0f / s1;
    const int rr0 = mq + g;
    if (rr0 < 49) {
        __nv_bfloat16* ob = ao + (size_t)(R0 + wi * 49 + rr0) * 192 + h * 32;
#pragma unroll
        for (int nt = 0; nt < 4; nt++)
            *(uint32_t*)&ob[nt * 8 + 2 * tin] = packbf(pv[nt][0] * inv0, pv[nt][1] * inv0);
    }
    if (rr0 + 8 < 49) {
        __nv_bfloat16* ob = ao + (size_t)(R0 + wi * 49 + rr0 + 8) * 192 + h * 32;
#pragma unroll
        for (int nt = 0; nt < 4; nt++)
            *(uint32_t*)&ob[nt * 8 + 2 * tin] = packbf(pv[nt][2] * inv1, pv[nt][3] * inv1);
    }
}

// ---------------------------------------------------------------------------
// MEGA: proj + residual + LN2 stats + fc1(+affine+GELU) + fc2 + residual.
// (R15 structure; gelu_fast in fc1 epilogue.)
// ---------------------------------------------------------------------------
#define MBM    64
#define AROW   24
#define ASTR   200
#define HSTR   392
#define X2B_OFF 0
#define AT_OFF  25600
#define HID_OFF 25600
#define MB_OFF  75776
#define MWSZ    (192 * AROW * 2)          // 9216
#define ST_OFF  112640
#define MS_OFF  114688
#define MEGA_SMEM 115200

__global__ __launch_bounds__(256, 2)
void mega(const __nv_bfloat16* __restrict__ ao,
          const float* __restrict__ x,
          const float* __restrict__ bo,
          const float* __restrict__ b1v,
          const float* __restrict__ b2v,
          float* __restrict__ out) {
    extern __shared__ char smem[];
    const uint32_t sb = smem_u32(smem);
    const int tid  = threadIdx.x;
    const int warp = tid >> 5;
    const int lane = tid & 31;
    const int g    = lane >> 2;
    const int tin  = lane & 3;
    const int l15  = lane & 15;
    const int lhi  = lane >> 4;
    const int row0 = blockIdx.x * MBM;
    const int wm   = (warp & 1) * 32;
    const int wn   = (warp >> 1) * 48;
    const int nw   = warp >> 1;

    __nv_bfloat16* x2b = (__nv_bfloat16*)smem;
    __nv_bfloat16* hid = (__nv_bfloat16*)(smem + HID_OFF);
    float2* stats  = (float2*)(smem + ST_OFF);
    float2* mstat  = (float2*)(smem + MS_OFF);

    const int brow0 = tid >> 1,         bchk0 = tid & 1;
    const int brow1 = 128 + (tid >> 1), bchk1 = tid & 1;
    const bool bld1 = tid < 128;
    const uint32_t wsb0 = sb + MB_OFF + (brow0 * AROW + bchk0 * 8) * 2;
    const uint32_t wsb1 = sb + MB_OFF + (brow1 * AROW + bchk1 * 8) * 2;

    const uint32_t wbbase = sb + MB_OFF
        + (uint32_t)(wn + ((lane >> 4) & 1) * 8 + (lane & 7)) * (AROW * 2)
        + ((lane >> 3) & 1) * 16;

    // ---- prologue: stage ao tile + first wout stages ----
    const __nv_bfloat16* Wo0 = g_wout + (size_t)brow0 * 192 + bchk0 * 8;
    const __nv_bfloat16* Wo1 = g_wout + (size_t)brow1 * 192 + bchk1 * 8;
#pragma unroll
    for (int i = 0; i < 6; i++) {
        int idx = tid + i * 256;
        int r = idx / 24, c = idx % 24;
        cp_async16(sb + AT_OFF + (r * ASTR + c * 8) * 2,
                   ao + (size_t)(row0 + r) * 192 + c * 8);
    }
    cp_async16(wsb0, Wo0);
    if (bld1) cp_async16(wsb1, Wo1);
    CP_COMMIT();
#pragma unroll
    for (int s = 1; s < 3; s++) {
        cp_async16(wsb0 + s * MWSZ, Wo0 + s * 16);
        if (bld1) cp_async16(wsb1 + s * MWSZ, Wo1 + s * 16);
        CP_COMMIT();
    }

    // ---------------- Phase A: proj GEMM (K=192) ----------------
    float acc[2][6][4];
#pragma unroll
    for (int i = 0; i < 2; i++)
#pragma unroll
        for (int j = 0; j < 6; j++)
#pragma unroll
            for (int l = 0; l < 4; l++) acc[i][j][l] = 0.0f;

    const uint32_t atbase = sb + AT_OFF + (uint32_t)(wm + l15) * (ASTR * 2) + lhi * 16;

    for (int t = 0; t < 12; t++) {
        CP_WAIT(2);
        __syncthreads();
        const int tn = t + 3;
        if (tn < 12) {
            const int s = tn & 3;
            cp_async16(wsb0 + s * MWSZ, Wo0 + tn * 16);
            if (bld1) cp_async16(wsb1 + s * MWSZ, Wo1 + tn * 16);
        }
        CP_COMMIT();

        const int st = t & 3;
        uint32_t af[2][4];
        ldsm4(af[0], atbase + t * 32);
        ldsm4(af[1], atbase + 16 * (ASTR * 2) + t * 32);

        uint32_t bq[3][4];
#pragma unroll
        for (int pr = 0; pr < 3; pr++)
            ldsm4(bq[pr], wbbase + st * MWSZ + pr * 16 * (AROW * 2));

#pragma unroll
        for (int mt = 0; mt < 2; mt++)
#pragma unroll
            for (int pr = 0; pr < 3; pr++) {
                mma_bf16(acc[mt][2 * pr + 0], af[mt], &bq[pr][0]);
                mma_bf16(acc[mt][2 * pr + 1], af[mt], &bq[pr][2]);
            }
    }

    // ---- Phase A epilogue ----
    float xf[2][6][4];
#pragma unroll
    for (int mt = 0; mt < 2; mt++) {
        const int lr0 = wm + mt * 16 + g;
        const int lr1 = lr0 + 8;
        const int d0 = src_index(row0 + lr0);
        const int d1 = src_index(row0 + lr1);
        float s0 = 0.0f, q0 = 0.0f, s1 = 0.0f, q1 = 0.0f;
#pragma unroll
        for (int nt = 0; nt < 6; nt++) {
            const int col = wn + nt * 8 + 2 * tin;
            const float2 bv = *(const float2*)&bo[col];
            float2 e0 = *(const float2*)&x[(size_t)d0 * 192 + col];
            float2 e1 = *(const float2*)&x[(size_t)d1 * 192 + col];
            float v00 = acc[mt][nt][0] + bv.x + e0.x;
            float v01 = acc[mt][nt][1] + bv.y + e0.y;
            float v10 = acc[mt][nt][2] + bv.x + e1.x;
            float v11 = acc[mt][nt][3] + bv.y + e1.y;
            xf[mt][nt][0] = v00; xf[mt][nt][1] = v01;
            xf[mt][nt][2] = v10; xf[mt][nt][3] = v11;
            *(uint32_t*)&x2b[lr0 * ASTR + col] = packbf(v00, v01);
            *(uint32_t*)&x2b[lr1 * ASTR + col] = packbf(v10, v11);
            s0 += v00 + v01; q0 += v00 * v00 + v01 * v01;
            s1 += v10 + v11; q1 += v10 * v10 + v11 * v11;
        }
        s0 += __shfl_xor_sync(0xffffffffu, s0, 1);
        s0 += __shfl_xor_sync(0xffffffffu, s0, 2);
        q0 += __shfl_xor_sync(0xffffffffu, q0, 1);
        q0 += __shfl_xor_sync(0xffffffffu, q0, 2);
        s1 += __shfl_xor_sync(0xffffffffu, s1, 1);
        s1 += __shfl_xor_sync(0xffffffffu, s1, 2);
        q1 += __shfl_xor_sync(0xffffffffu, q1, 1);
        q1 += __shfl_xor_sync(0xffffffffu, q1, 2);
        if (tin == 0) {
            stats[lr0 * 4 + nw] = make_float2(s0, q0);
            stats[lr1 * 4 + nw] = make_float2(s1, q1);
        }
    }
    __syncthreads();
    if (tid < MBM) {
        float s = 0.0f, q = 0.0f;
#pragma unroll
        for (int k = 0; k < 4; k++) {
            float2 pp = stats[tid * 4 + k];
            s += pp.x; q += pp.y;
        }
        float mean = s * (1.0f / 192.0f);
        float var  = q * (1.0f / 192.0f) - mean * mean;
        mstat[tid] = make_float2(mean, rsqrtf(var + 1e-5f));
    }

    // ---------------- Phase B: fc1, two N=192 halves ----------------
    const uint32_t x2base = sb + X2B_OFF + (uint32_t)(wm + l15) * (ASTR * 2) + lhi * 16;

#pragma unroll 1
    for (int nh = 0; nh < 2; nh++) {
        const __nv_bfloat16* Wg0 = g_w1 + (size_t)(nh * 192 + brow0) * 192 + bchk0 * 8;
        const __nv_bfloat16* Wg1 = g_w1 + (size_t)(nh * 192 + brow1) * 192 + bchk1 * 8;
#pragma unroll
        for (int s = 0; s < 3; s++) {
            cp_async16(wsb0 + s * MWSZ, Wg0 + s * 16);
            if (bld1) cp_async16(wsb1 + s * MWSZ, Wg1 + s * 16);
            CP_COMMIT();
        }

#pragma unroll
        for (int i = 0; i < 2; i++)
#pragma unroll
            for (int j = 0; j < 6; j++)
#pragma unroll
                for (int l = 0; l < 4; l++) acc[i][j][l] = 0.0f;

        for (int t = 0; t < 12; t++) {
            CP_WAIT(2);
            __syncthreads();
            const int tn = t + 3;
            if (tn < 12) {
                const int s = tn & 3;
                cp_async16(wsb0 + s * MWSZ, Wg0 + tn * 16);
                if (bld1) cp_async16(wsb1 + s * MWSZ, Wg1 + tn * 16);
            }
            CP_COMMIT();

            const int st = t & 3;
            uint32_t af[2][4];
            ldsm4(af[0], x2base + t * 32);
            ldsm4(af[1], x2base + 16 * (ASTR * 2) + t * 32);

            uint32_t bq[3][4];
#pragma unroll
            for (int pr = 0; pr < 3; pr++)
                ldsm4(bq[pr], wbbase + st * MWSZ + pr * 16 * (AROW * 2));

#pragma unroll
            for (int mt = 0; mt < 2; mt++)
#pragma unroll
                for (int pr = 0; pr < 3; pr++) {
                    mma_bf16(acc[mt][2 * pr + 0], af[mt], &bq[pr][0]);
                    mma_bf16(acc[mt][2 * pr + 1], af[mt], &bq[pr][2]);
                }
        }

        // epilogue: LN2 affine + GELU -> hid smem
#pragma unroll
        for (int mt = 0; mt < 2; mt++) {
            const int lr = wm + mt * 16 + g;
            const float2 mr0 = mstat[lr];
            const float2 mr1 = mstat[lr + 8];
            const float A0 = mr0.y, B0 = mr0.x * mr0.y;
            const float A1 = mr1.y, B1 = mr1.x * mr1.y;
#pragma unroll
            for (int nt = 0; nt < 6; nt++) {
                const int col = nh * 192 + wn + nt * 8 + 2 * tin;
                const float2 bv = *(const float2*)&b1v[col];
                const float2 stA = g_st1[col];
                const float2 stB = g_st1[col + 1];
                float v00 = gelu_fast(A0 * acc[mt][nt][0] - B0 * stA.x + stA.y + bv.x);
                float v01 = gelu_fast(A0 * acc[mt][nt][1] - B0 * stB.x + stB.y + bv.y);
                float v10 = gelu_fast(A1 * acc[mt][nt][2] - B1 * stA.x + stA.y + bv.x);
                float v11 = gelu_fast(A1 * acc[mt][nt][3] - B1 * stB.x + stB.y + bv.y);
                *(uint32_t*)&hid[lr * HSTR + col]       = packbf(v00, v01);
                *(uint32_t*)&hid[(lr + 8) * HSTR + col] = packbf(v10, v11);
            }
        }
    }

    // ---------------- Phase C: fc2 (K = 384) ----------------
    const __nv_bfloat16* W2g0 = g_w2 + (size_t)brow0 * 384 + bchk0 * 8;
    const __nv_bfloat16* W2g1 = g_w2 + (size_t)brow1 * 384 + bchk1 * 8;
#pragma unroll
    for (int s = 0; s < 3; s++) {
        cp_async16(wsb0 + s * MWSZ, W2g0 + s * 16);
        if (bld1) cp_async16(wsb1 + s * MWSZ, W2g1 + s * 16);
        CP_COMMIT();
    }

#pragma unroll
    for (int i = 0; i < 2; i++)
#pragma unroll
        for (int j = 0; j < 6; j++)
#pragma unroll
            for (int l = 0; l < 4; l++) acc[i][j][l] = 0.0f;

    const uint32_t h_albase = sb + HID_OFF + (uint32_t)(wm + l15) * (HSTR * 2) + lhi * 16;

    for (int t = 0; t < 24; t++) {
        CP_WAIT(2);
        __syncthreads();
        const int tn = t + 3;
        if (tn < 24) {
            const int s = tn & 3;
            cp_async16(wsb0 + s * MWSZ, W2g0 + tn * 16);
            if (bld1) cp_async16(wsb1 + s * MWSZ, W2g1 + tn * 16);
        }
        CP_COMMIT();

        const int st = t & 3;
        uint32_t af[2][4];
        ldsm4(af[0], h_albase + t * 32);
        ldsm4(af[1], h_albase + 16 * (HSTR * 2) + t * 32);

        uint32_t bq[3][4];
#pragma unroll
        for (int pr = 0; pr < 3; pr++)
            ldsm4(bq[pr], wbbase + st * MWSZ + pr * 16 * (AROW * 2));

#pragma unroll
        for (int mt = 0; mt < 2; mt++)
#pragma unroll
            for (int pr = 0; pr < 3; pr++) {
                mma_bf16(acc[mt][2 * pr + 0], af[mt], &bq[pr][0]);
                mma_bf16(acc[mt][2 * pr + 1], af[mt], &bq[pr][2]);
            }
    }

    // epilogue: bias + thread-local fp32 residual, scattered store
#pragma unroll
    for (int mt = 0; mt < 2; mt++) {
        const int lr0 = wm + mt * 16 + g;
        const int d0 = src_index(row0 + lr0);
        const int d1 = src_index(row0 + lr0 + 8);
#pragma unroll
        for (int nt = 0; nt < 6; nt++) {
            const int col = wn + nt * 8 + 2 * tin;
            const float2 bv = *(const float2*)&b2v[col];
            float2 v0, v1;
            v0.x = acc[mt][nt][0] + bv.x + xf[mt][nt][0];
            v0.y = acc[mt][nt][1] + bv.y + xf[mt][nt][1];
            v1.x = acc[mt][nt][2] + bv.x + xf[mt][nt][2];
            v1.y = acc[mt][nt][3] + bv.y + xf[mt][nt][3];
            *(float2*)&out[(size_t)d0 * 192 + col] = v0;
            *(float2*)&out[(size_t)d1 * 192 + col] = v1;
        }
    }
}

// ---------------------------------------------------------------------------
// Launcher
// ---------------------------------------------------------------------------
extern "C" void kernel_launch(void* const* d_in, const int* in_sizes, int n_in,
                              void* d_out, int out_size) {
    const float* x     = (const float*)d_in[0];
    const float* ln1_g = (const float*)d_in[1];
    const float* ln1_b = (const float*)d_in[2];
    const float* ln2_g = (const float*)d_in[3];
    const float* ln2_b = (const float*)d_in[4];
    const float* w_qkv = (const float*)d_in[5];
    const float* b_qkv = (const float*)d_in[6];
    const float* w_out = (const float*)d_in[7];
    const float* b_out = (const float*)d_in[8];
    const float* w1    = (const float*)d_in[9];
    const float* b1    = (const float*)d_in[10];
    const float* w2    = (const float*)d_in[11];
    const float* b2    = (const float*)d_in[12];
    float* out = (float*)d_out;

    __nv_bfloat16 *a1, *aob;
    cudaGetSymbolAddress((void**)&a1,  g_a1);
    cudaGetSymbolAddress((void**)&aob, g_ao);

    cudaFuncSetAttribute(attn_fused, cudaFuncAttributeMaxDynamicSharedMemorySize, FUSED_SMEM);
    cudaFuncSetAttribute(mega, cudaFuncAttributeMaxDynamicSharedMemorySize, MEGA_SMEM);

    // 0) weight prep (wcvt + ln2 fold in one launch)
    prep_all<<<912, 256>>>(w_qkv, w_out, w2, w1, ln2_g, ln2_b);
    // 1) LN1 + shift + window partition -> a1 (bf16, window order)
    ln1_kernel<<<NTOK / 8, 256>>>(x, ln1_g, ln1_b, a1);
    // 2) fused QKV GEMM + attention -> ao
    attn_fused<<<dim3(1024, 6), 256, FUSED_SMEM>>>(a1, b_qkv, aob);
    // 3) mega: proj + residual + LN2 + fc1 + GELU + fc2 + residual -> out
    mega<<<NTOK / MBM, 256, MEGA_SMEM>>>(aob, x, b_out, b1, b2, out);
}